// round 2
// baseline (speedup 1.0000x reference)
#include <cuda_runtime.h>
#include <cuda_bf16.h>
#include <math.h>

// Problem constants (fixed by the reference)
#define HIDDEN  1024
#define NHEADS  16
#define HSIZE   64
#define BATCH   2
#define SEQ     2048
#define BS      (BATCH * SEQ)      // 4096 rows
#define QKVW    (3 * HIDDEN)       // 3072

// Scratch (allocation-free rule: __device__ globals)
__device__ float g_qkv [ (size_t)BS * QKVW ];   // [4096][3072]  q|k|v per row
__device__ float g_attn[ (size_t)BS * HIDDEN ]; // [4096][1024]

// ---------------------------------------------------------------------------
// GEMM: C[M,N] = A[M,K] * B[K,N] + bias[N]     (M,N mult of 128, K mult of 16)
// 128x128 block tile, 8x8 per thread, 256 threads.
// ---------------------------------------------------------------------------
__global__ __launch_bounds__(256) void gemm_bias_kernel(
    const float* __restrict__ A, const float* __restrict__ B,
    const float* __restrict__ bias, float* __restrict__ C,
    int M, int N, int K)
{
    __shared__ float As[16][132];   // A tile transposed [k][m], pad 4
    __shared__ float Bs[16][128];   // B tile [k][n]

    const int tid = threadIdx.x;
    const int tx  = tid & 15;       // n-dim
    const int ty  = tid >> 4;       // m-dim
    const int n0  = blockIdx.x * 128;
    const int m0  = blockIdx.y * 128;

    float acc[8][8];
    #pragma unroll
    for (int i = 0; i < 8; i++)
        #pragma unroll
        for (int j = 0; j < 8; j++) acc[i][j] = 0.f;

    for (int k0 = 0; k0 < K; k0 += 16) {
        // Load A tile: 128 rows x 16 cols = 512 float4
        #pragma unroll
        for (int it = 0; it < 2; it++) {
            int li = tid + it * 256;          // 0..511
            int r  = li >> 2;                 // 0..127
            int c4 = (li & 3) * 4;            // 0,4,8,12
            float4 v = *(const float4*)(A + (size_t)(m0 + r) * K + k0 + c4);
            As[c4 + 0][r] = v.x; As[c4 + 1][r] = v.y;
            As[c4 + 2][r] = v.z; As[c4 + 3][r] = v.w;
        }
        // Load B tile: 16 rows x 128 cols = 512 float4
        #pragma unroll
        for (int it = 0; it < 2; it++) {
            int li = tid + it * 256;
            int r  = li >> 5;                 // 0..15
            int c4 = (li & 31) * 4;           // 0..124
            *(float4*)&Bs[r][c4] = *(const float4*)(B + (size_t)(k0 + r) * N + n0 + c4);
        }
        __syncthreads();

        #pragma unroll
        for (int kk = 0; kk < 16; kk++) {
            float a[8], b[8];
            *(float4*)&a[0] = *(const float4*)&As[kk][ty * 8];
            *(float4*)&a[4] = *(const float4*)&As[kk][ty * 8 + 4];
            *(float4*)&b[0] = *(const float4*)&Bs[kk][tx * 8];
            *(float4*)&b[4] = *(const float4*)&Bs[kk][tx * 8 + 4];
            #pragma unroll
            for (int i = 0; i < 8; i++)
                #pragma unroll
                for (int j = 0; j < 8; j++)
                    acc[i][j] = fmaf(a[i], b[j], acc[i][j]);
        }
        __syncthreads();
    }

    #pragma unroll
    for (int i = 0; i < 8; i++) {
        size_t row = (size_t)(m0 + ty * 8 + i);
        #pragma unroll
        for (int j = 0; j < 8; j++) {
            int col = n0 + tx * 8 + j;
            C[row * N + col] = acc[i][j] + bias[col];
        }
    }
}

// ---------------------------------------------------------------------------
// Flash attention (fp32, online softmax).
// Grid: (SEQ/64, NHEADS, BATCH). Block: 256 threads.
// Per block: 64 q-rows x full head. KV tiles of 32 rows.
// Thread (tx = tid&15, ty = tid>>4): owns q-rows ty*4..+3.
//   QK^T: cols tx, tx+16   (S tile 64x32 -> s[4][2])
//   PV  : out cols tx+16*j (O tile 64x64 -> acc[4][4])
// ---------------------------------------------------------------------------
__global__ __launch_bounds__(256) void attn_kernel(
    const float* __restrict__ qkv, float* __restrict__ attn_out)
{
    __shared__ float Qs[64][68];   // pad 4 (float4-aligned, low-conflict reads)
    __shared__ float Ks[32][68];
    __shared__ float Vs[32][64];
    __shared__ float Ps[64][33];   // probs, pad 1

    const int tid = threadIdx.x;
    const int tx  = tid & 15;
    const int ty  = tid >> 4;
    const int q0  = blockIdx.x * 64;
    const int h   = blockIdx.y;
    const int b   = blockIdx.z;

    const float* base = qkv + (size_t)b * SEQ * QKVW;
    const int qcol = h * HSIZE;

    // Load Q tile: 64 rows x 64 cols = 1024 float4
    #pragma unroll
    for (int it = 0; it < 4; it++) {
        int li = tid + it * 256;
        int r  = li >> 4;            // 0..63
        int c4 = (li & 15) * 4;      // 0..60
        *(float4*)&Qs[r][c4] =
            *(const float4*)(base + (size_t)(q0 + r) * QKVW + qcol + c4);
    }

    float m[4], l[4], acc[4][4];
    #pragma unroll
    for (int i = 0; i < 4; i++) {
        m[i] = -1e30f; l[i] = 0.f;
        #pragma unroll
        for (int j = 0; j < 4; j++) acc[i][j] = 0.f;
    }

    const float scale = 0.125f;   // 1/sqrt(64)

    for (int kv0 = 0; kv0 < SEQ; kv0 += 32) {
        __syncthreads();   // prior PV reads of Vs/Ps done; Q load visible (iter 0)
        // Load K,V tiles: 32 rows x 64 cols each
        #pragma unroll
        for (int it = 0; it < 2; it++) {
            int li = tid + it * 256;
            int r  = li >> 4;          // 0..31
            int c4 = (li & 15) * 4;
            const float* rowp = base + (size_t)(kv0 + r) * QKVW + qcol;
            *(float4*)&Ks[r][c4] = *(const float4*)(rowp + HIDDEN  + c4);
            *(float4*)&Vs[r][c4] = *(const float4*)(rowp + 2*HIDDEN + c4);
        }
        __syncthreads();

        // S = Q K^T  (contract over d=64)
        float s[4][2] = {{0.f,0.f},{0.f,0.f},{0.f,0.f},{0.f,0.f}};
        #pragma unroll 8
        for (int kk = 0; kk < 64; kk++) {
            float a0 = Qs[ty*4+0][kk], a1 = Qs[ty*4+1][kk];
            float a2 = Qs[ty*4+2][kk], a3 = Qs[ty*4+3][kk];
            float b0 = Ks[tx][kk],     b1 = Ks[tx+16][kk];
            s[0][0] = fmaf(a0,b0,s[0][0]); s[0][1] = fmaf(a0,b1,s[0][1]);
            s[1][0] = fmaf(a1,b0,s[1][0]); s[1][1] = fmaf(a1,b1,s[1][1]);
            s[2][0] = fmaf(a2,b0,s[2][0]); s[2][1] = fmaf(a2,b1,s[2][1]);
            s[3][0] = fmaf(a3,b0,s[3][0]); s[3][1] = fmaf(a3,b1,s[3][1]);
        }

        // Online softmax update (row state replicated across the 16 tx threads)
        #pragma unroll
        for (int i = 0; i < 4; i++) {
            float s0 = s[i][0] * scale, s1 = s[i][1] * scale;
            float rm = fmaxf(s0, s1);
            #pragma unroll
            for (int off = 8; off; off >>= 1)
                rm = fmaxf(rm, __shfl_xor_sync(0xffffffffu, rm, off));
            float nm   = fmaxf(m[i], rm);
            float corr = __expf(m[i] - nm);
            float p0 = __expf(s0 - nm);
            float p1 = __expf(s1 - nm);
            float rs = p0 + p1;
            #pragma unroll
            for (int off = 8; off; off >>= 1)
                rs += __shfl_xor_sync(0xffffffffu, rs, off);
            l[i] = l[i] * corr + rs;
            m[i] = nm;
            #pragma unroll
            for (int j = 0; j < 4; j++) acc[i][j] *= corr;
            Ps[ty*4+i][tx]      = p0;
            Ps[ty*4+i][tx+16]   = p1;
        }
        __syncthreads();

        // O += P V   (contract over 32 kv rows)
        #pragma unroll 8
        for (int kk = 0; kk < 32; kk++) {
            float p0 = Ps[ty*4+0][kk], p1 = Ps[ty*4+1][kk];
            float p2 = Ps[ty*4+2][kk], p3 = Ps[ty*4+3][kk];
            float v0 = Vs[kk][tx],    v1 = Vs[kk][tx+16];
            float v2 = Vs[kk][tx+32], v3 = Vs[kk][tx+48];
            acc[0][0]=fmaf(p0,v0,acc[0][0]); acc[0][1]=fmaf(p0,v1,acc[0][1]);
            acc[0][2]=fmaf(p0,v2,acc[0][2]); acc[0][3]=fmaf(p0,v3,acc[0][3]);
            acc[1][0]=fmaf(p1,v0,acc[1][0]); acc[1][1]=fmaf(p1,v1,acc[1][1]);
            acc[1][2]=fmaf(p1,v2,acc[1][2]); acc[1][3]=fmaf(p1,v3,acc[1][3]);
            acc[2][0]=fmaf(p2,v0,acc[2][0]); acc[2][1]=fmaf(p2,v1,acc[2][1]);
            acc[2][2]=fmaf(p2,v2,acc[2][2]); acc[2][3]=fmaf(p2,v3,acc[2][3]);
            acc[3][0]=fmaf(p3,v0,acc[3][0]); acc[3][1]=fmaf(p3,v1,acc[3][1]);
            acc[3][2]=fmaf(p3,v2,acc[3][2]); acc[3][3]=fmaf(p3,v3,acc[3][3]);
        }
    }

    // Normalize and write O tile to attn buffer
    #pragma unroll
    for (int i = 0; i < 4; i++) {
        float inv = 1.0f / l[i];
        size_t row = (size_t)(b * SEQ + q0 + ty*4 + i);
        #pragma unroll
        for (int j = 0; j < 4; j++)
            attn_out[row * HIDDEN + qcol + tx + 16*j] = acc[i][j] * inv;
    }
}

// ---------------------------------------------------------------------------
// Launch: qkv = x@Wqkv + bqkv  ->  flash attention  ->  out = attn@Wo + bo
// ---------------------------------------------------------------------------
extern "C" void kernel_launch(void* const* d_in, const int* in_sizes, int n_in,
                              void* d_out, int out_size)
{
    const float* x    = (const float*)d_in[0];
    const float* Wqkv = (const float*)d_in[1];
    const float* bqkv = (const float*)d_in[2];
    const float* Wo   = (const float*)d_in[3];
    const float* bo   = (const float*)d_in[4];
    float* out = (float*)d_out;

    float *qkv_ptr = nullptr, *attn_ptr = nullptr;
    cudaGetSymbolAddress((void**)&qkv_ptr,  g_qkv);
    cudaGetSymbolAddress((void**)&attn_ptr, g_attn);

    // 1) QKV projection: [4096,1024] @ [1024,3072]
    gemm_bias_kernel<<<dim3(QKVW / 128, BS / 128), 256>>>(
        x, Wqkv, bqkv, qkv_ptr, BS, QKVW, HIDDEN);

    // 2) Attention: grid (q-tiles, heads, batch)
    attn_kernel<<<dim3(SEQ / 64, NHEADS, BATCH), 256>>>(qkv_ptr, attn_ptr);

    // 3) Output projection: [4096,1024] @ [1024,1024]
    gemm_bias_kernel<<<dim3(HIDDEN / 128, BS / 128), 256>>>(
        attn_ptr, Wo, bo, out, BS, HIDDEN, HIDDEN);
}

// round 6
// speedup vs baseline: 1.4377x; 1.4377x over previous
#include <cuda_runtime.h>
#include <cuda_bf16.h>
#include <cstdint>
#include <math.h>

// Problem constants
#define HIDDEN  1024
#define NHEADS  16
#define HSIZE   64
#define BATCH   2
#define SEQ     2048
#define BS      (BATCH * SEQ)      // 4096 rows
#define QKVW    (3 * HIDDEN)       // 3072
#define GK      1024               // GEMM K (both projections)

// Scratch (allocation-free rule: __device__ globals)
__device__ float g_qkv  [ (size_t)BS * QKVW ];       // [4096][3072]
__device__ float g_attn [ (size_t)BS * HIDDEN ];     // [4096][1024]
__device__ float g_wqkvT[ (size_t)QKVW * HIDDEN ];   // Wqkv^T [3072][1024]
__device__ float g_woT  [ (size_t)HIDDEN * HIDDEN ]; // Wo^T   [1024][1024]

__device__ __forceinline__ uint32_t f2tf32(float x) {
    uint32_t u;
    asm("cvt.rna.tf32.f32 %0, %1;" : "=r"(u) : "f"(x));
    return u;
}

// ---------------------------------------------------------------------------
// Transpose: out[C][R] = in[R][C]
// ---------------------------------------------------------------------------
__global__ __launch_bounds__(256) void transpose_kernel(
    const float* __restrict__ in, float* __restrict__ out, int R, int C)
{
    __shared__ float t[32][33];
    int x  = blockIdx.x * 32 + threadIdx.x;
    int y0 = blockIdx.y * 32;
    #pragma unroll
    for (int i = threadIdx.y; i < 32; i += 8)
        t[i][threadIdx.x] = in[(size_t)(y0 + i) * C + x];
    __syncthreads();
    int ox  = y0 + threadIdx.x;
    int oy0 = blockIdx.x * 32;
    #pragma unroll
    for (int i = threadIdx.y; i < 32; i += 8)
        out[(size_t)(oy0 + i) * R + ox] = t[threadIdx.x][i];
}

// ---------------------------------------------------------------------------
// tf32 mma.sync GEMM: C[M,N] = A[M,K] * BT[N,K]^T + bias[N]
// A: [M,1024] row-major.  BT: [N,1024] row-major (pre-transposed weights).
// CTA 128x128, 8 warps (4m x 2n), warp tile 32x64 (2x8 m16n8k8 tiles).
// K-chunk 16, double-buffered SMEM, LDG->compute->STS overlap.
// ---------------------------------------------------------------------------
#define BKC 16        // K per chunk
#define SPAD 20       // smem row stride (floats): conflict-free fragment reads

__global__ __launch_bounds__(256) void gemm_tf32_mma(
    const float* __restrict__ A, const float* __restrict__ BT,
    const float* __restrict__ bias, float* __restrict__ C, int N)
{
    __shared__ float As[2][128][SPAD];
    __shared__ float Bs[2][128][SPAD];

    const int tid  = threadIdx.x;
    const int lane = tid & 31;
    const int w    = tid >> 5;
    const int wm   = w & 3;        // 0..3 (m)
    const int wn   = w >> 2;       // 0..1 (n)
    const int n0   = blockIdx.x * 128;
    const int m0   = blockIdx.y * 128;
    const int g    = lane >> 2;    // 0..7
    const int t    = lane & 3;     // 0..3

    float c[2][8][4];
    #pragma unroll
    for (int mt = 0; mt < 2; mt++)
        #pragma unroll
        for (int nt = 0; nt < 8; nt++)
            #pragma unroll
            for (int i = 0; i < 4; i++) c[mt][nt][i] = 0.f;

    // Per-thread global-load coordinates (2 float4 for A, 2 for B)
    int lr[2], lc[2];
    #pragma unroll
    for (int it = 0; it < 2; it++) {
        int li = tid + it * 256;   // 0..511
        lr[it] = li >> 2;          // row 0..127
        lc[it] = (li & 3) * 4;     // col 0,4,8,12
    }

    float4 ra[2], rb[2];

    // Preload chunk 0
    #pragma unroll
    for (int it = 0; it < 2; it++) {
        ra[it] = *(const float4*)(A  + (size_t)(m0 + lr[it]) * GK + lc[it]);
        rb[it] = *(const float4*)(BT + (size_t)(n0 + lr[it]) * GK + lc[it]);
    }
    #pragma unroll
    for (int it = 0; it < 2; it++) {
        float* ap = &As[0][lr[it]][lc[it]];
        ap[0] = __uint_as_float(f2tf32(ra[it].x));
        ap[1] = __uint_as_float(f2tf32(ra[it].y));
        ap[2] = __uint_as_float(f2tf32(ra[it].z));
        ap[3] = __uint_as_float(f2tf32(ra[it].w));
        float* bp = &Bs[0][lr[it]][lc[it]];
        bp[0] = __uint_as_float(f2tf32(rb[it].x));
        bp[1] = __uint_as_float(f2tf32(rb[it].y));
        bp[2] = __uint_as_float(f2tf32(rb[it].z));
        bp[3] = __uint_as_float(f2tf32(rb[it].w));
    }
    __syncthreads();

    const int NCHUNK = GK / BKC;   // 64
    for (int chunk = 0; chunk < NCHUNK; chunk++) {
        const int buf = chunk & 1;

        // Prefetch next chunk (global -> regs)
        if (chunk + 1 < NCHUNK) {
            const int k0 = (chunk + 1) * BKC;
            #pragma unroll
            for (int it = 0; it < 2; it++) {
                ra[it] = *(const float4*)(A  + (size_t)(m0 + lr[it]) * GK + k0 + lc[it]);
                rb[it] = *(const float4*)(BT + (size_t)(n0 + lr[it]) * GK + k0 + lc[it]);
            }
        }

        // Compute: 2 k-steps of m16n8k8
        #pragma unroll
        for (int ks = 0; ks < 2; ks++) {
            const int kb = ks * 8;
            uint32_t af[2][4], bf[8][2];
            #pragma unroll
            for (int mt = 0; mt < 2; mt++) {
                const int rbase = wm * 32 + mt * 16;
                af[mt][0] = __float_as_uint(As[buf][rbase + g    ][kb + t    ]);
                af[mt][1] = __float_as_uint(As[buf][rbase + g + 8][kb + t    ]);
                af[mt][2] = __float_as_uint(As[buf][rbase + g    ][kb + t + 4]);
                af[mt][3] = __float_as_uint(As[buf][rbase + g + 8][kb + t + 4]);
            }
            #pragma unroll
            for (int nt = 0; nt < 8; nt++) {
                const int nbase = wn * 64 + nt * 8;
                bf[nt][0] = __float_as_uint(Bs[buf][nbase + g][kb + t    ]);
                bf[nt][1] = __float_as_uint(Bs[buf][nbase + g][kb + t + 4]);
            }
            #pragma unroll
            for (int mt = 0; mt < 2; mt++)
                #pragma unroll
                for (int nt = 0; nt < 8; nt++) {
                    asm volatile(
                        "mma.sync.aligned.m16n8k8.row.col.f32.tf32.tf32.f32 "
                        "{%0,%1,%2,%3}, {%4,%5,%6,%7}, {%8,%9}, {%0,%1,%2,%3};"
                        : "+f"(c[mt][nt][0]), "+f"(c[mt][nt][1]),
                          "+f"(c[mt][nt][2]), "+f"(c[mt][nt][3])
                        : "r"(af[mt][0]), "r"(af[mt][1]),
                          "r"(af[mt][2]), "r"(af[mt][3]),
                          "r"(bf[nt][0]), "r"(bf[nt][1]));
                }
        }

        // Store prefetched chunk into the other buffer
        if (chunk + 1 < NCHUNK) {
            const int nb = buf ^ 1;
            #pragma unroll
            for (int it = 0; it < 2; it++) {
                float* ap = &As[nb][lr[it]][lc[it]];
                ap[0] = __uint_as_float(f2tf32(ra[it].x));
                ap[1] = __uint_as_float(f2tf32(ra[it].y));
                ap[2] = __uint_as_float(f2tf32(ra[it].z));
                ap[3] = __uint_as_float(f2tf32(ra[it].w));
                float* bp = &Bs[nb][lr[it]][lc[it]];
                bp[0] = __uint_as_float(f2tf32(rb[it].x));
                bp[1] = __uint_as_float(f2tf32(rb[it].y));
                bp[2] = __uint_as_float(f2tf32(rb[it].z));
                bp[3] = __uint_as_float(f2tf32(rb[it].w));
            }
        }
        __syncthreads();
    }

    // Epilogue: write fragments + bias
    #pragma unroll
    for (int mt = 0; mt < 2; mt++) {
        const int row = m0 + wm * 32 + mt * 16 + g;
        #pragma unroll
        for (int nt = 0; nt < 8; nt++) {
            const int col = n0 + wn * 64 + nt * 8 + t * 2;
            float2 bv = *(const float2*)(bias + col);
            float2 o0 = { c[mt][nt][0] + bv.x, c[mt][nt][1] + bv.y };
            float2 o1 = { c[mt][nt][2] + bv.x, c[mt][nt][3] + bv.y };
            *(float2*)(C + (size_t)row * N + col)       = o0;
            *(float2*)(C + (size_t)(row + 8) * N + col) = o1;
        }
    }
}

// ---------------------------------------------------------------------------
// Flash attention (fp32, online softmax) — unchanged from R1 baseline.
// ---------------------------------------------------------------------------
__global__ __launch_bounds__(256) void attn_kernel(
    const float* __restrict__ qkv, float* __restrict__ attn_out)
{
    __shared__ float Qs[64][68];
    __shared__ float Ks[32][68];
    __shared__ float Vs[32][64];
    __shared__ float Ps[64][33];

    const int tid = threadIdx.x;
    const int tx  = tid & 15;
    const int ty  = tid >> 4;
    const int q0  = blockIdx.x * 64;
    const int h   = blockIdx.y;
    const int b   = blockIdx.z;

    const float* base = qkv + (size_t)b * SEQ * QKVW;
    const int qcol = h * HSIZE;

    #pragma unroll
    for (int it = 0; it < 4; it++) {
        int li = tid + it * 256;
        int r  = li >> 4;
        int c4 = (li & 15) * 4;
        *(float4*)&Qs[r][c4] =
            *(const float4*)(base + (size_t)(q0 + r) * QKVW + qcol + c4);
    }

    float m[4], l[4], acc[4][4];
    #pragma unroll
    for (int i = 0; i < 4; i++) {
        m[i] = -1e30f; l[i] = 0.f;
        #pragma unroll
        for (int j = 0; j < 4; j++) acc[i][j] = 0.f;
    }

    const float scale = 0.125f;

    for (int kv0 = 0; kv0 < SEQ; kv0 += 32) {
        __syncthreads();
        #pragma unroll
        for (int it = 0; it < 2; it++) {
            int li = tid + it * 256;
            int r  = li >> 4;
            int c4 = (li & 15) * 4;
            const float* rowp = base + (size_t)(kv0 + r) * QKVW + qcol;
            *(float4*)&Ks[r][c4] = *(const float4*)(rowp + HIDDEN  + c4);
            *(float4*)&Vs[r][c4] = *(const float4*)(rowp + 2*HIDDEN + c4);
        }
        __syncthreads();

        float s[4][2] = {{0.f,0.f},{0.f,0.f},{0.f,0.f},{0.f,0.f}};
        #pragma unroll 8
        for (int kk = 0; kk < 64; kk++) {
            float a0 = Qs[ty*4+0][kk], a1 = Qs[ty*4+1][kk];
            float a2 = Qs[ty*4+2][kk], a3 = Qs[ty*4+3][kk];
            float b0 = Ks[tx][kk],     b1 = Ks[tx+16][kk];
            s[0][0] = fmaf(a0,b0,s[0][0]); s[0][1] = fmaf(a0,b1,s[0][1]);
            s[1][0] = fmaf(a1,b0,s[1][0]); s[1][1] = fmaf(a1,b1,s[1][1]);
            s[2][0] = fmaf(a2,b0,s[2][0]); s[2][1] = fmaf(a2,b1,s[2][1]);
            s[3][0] = fmaf(a3,b0,s[3][0]); s[3][1] = fmaf(a3,b1,s[3][1]);
        }

        #pragma unroll
        for (int i = 0; i < 4; i++) {
            float s0 = s[i][0] * scale, s1 = s[i][1] * scale;
            float rm = fmaxf(s0, s1);
            #pragma unroll
            for (int off = 8; off; off >>= 1)
                rm = fmaxf(rm, __shfl_xor_sync(0xffffffffu, rm, off));
            float nm   = fmaxf(m[i], rm);
            float corr = __expf(m[i] - nm);
            float p0 = __expf(s0 - nm);
            float p1 = __expf(s1 - nm);
            float rs = p0 + p1;
            #pragma unroll
            for (int off = 8; off; off >>= 1)
                rs += __shfl_xor_sync(0xffffffffu, rs, off);
            l[i] = l[i] * corr + rs;
            m[i] = nm;
            #pragma unroll
            for (int j = 0; j < 4; j++) acc[i][j] *= corr;
            Ps[ty*4+i][tx]      = p0;
            Ps[ty*4+i][tx+16]   = p1;
        }
        __syncthreads();

        #pragma unroll 8
        for (int kk = 0; kk < 32; kk++) {
            float p0 = Ps[ty*4+0][kk], p1 = Ps[ty*4+1][kk];
            float p2 = Ps[ty*4+2][kk], p3 = Ps[ty*4+3][kk];
            float v0 = Vs[kk][tx],    v1 = Vs[kk][tx+16];
            float v2 = Vs[kk][tx+32], v3 = Vs[kk][tx+48];
            acc[0][0]=fmaf(p0,v0,acc[0][0]); acc[0][1]=fmaf(p0,v1,acc[0][1]);
            acc[0][2]=fmaf(p0,v2,acc[0][2]); acc[0][3]=fmaf(p0,v3,acc[0][3]);
            acc[1][0]=fmaf(p1,v0,acc[1][0]); acc[1][1]=fmaf(p1,v1,acc[1][1]);
            acc[1][2]=fmaf(p1,v2,acc[1][2]); acc[1][3]=fmaf(p1,v3,acc[1][3]);
            acc[2][0]=fmaf(p2,v0,acc[2][0]); acc[2][1]=fmaf(p2,v1,acc[2][1]);
            acc[2][2]=fmaf(p2,v2,acc[2][2]); acc[2][3]=fmaf(p2,v3,acc[2][3]);
            acc[3][0]=fmaf(p3,v0,acc[3][0]); acc[3][1]=fmaf(p3,v1,acc[3][1]);
            acc[3][2]=fmaf(p3,v2,acc[3][2]); acc[3][3]=fmaf(p3,v3,acc[3][3]);
        }
    }

    #pragma unroll
    for (int i = 0; i < 4; i++) {
        float inv = 1.0f / l[i];
        size_t row = (size_t)(b * SEQ + q0 + ty*4 + i);
        #pragma unroll
        for (int j = 0; j < 4; j++)
            attn_out[row * HIDDEN + qcol + tx + 16*j] = acc[i][j] * inv;
    }
}

// ---------------------------------------------------------------------------
// Launch
// ---------------------------------------------------------------------------
extern "C" void kernel_launch(void* const* d_in, const int* in_sizes, int n_in,
                              void* d_out, int out_size)
{
    const float* x    = (const float*)d_in[0];
    const float* Wqkv = (const float*)d_in[1];
    const float* bqkv = (const float*)d_in[2];
    const float* Wo   = (const float*)d_in[3];
    const float* bo   = (const float*)d_in[4];
    float* out = (float*)d_out;

    float *qkv_p = nullptr, *attn_p = nullptr, *wqkvT_p = nullptr, *woT_p = nullptr;
    cudaGetSymbolAddress((void**)&qkv_p,   g_qkv);
    cudaGetSymbolAddress((void**)&attn_p,  g_attn);
    cudaGetSymbolAddress((void**)&wqkvT_p, g_wqkvT);
    cudaGetSymbolAddress((void**)&woT_p,   g_woT);

    // 0) Transpose weights: Wqkv [1024,3072] -> [3072,1024]; Wo -> [1024,1024]
    transpose_kernel<<<dim3(QKVW / 32, HIDDEN / 32), dim3(32, 8)>>>(
        Wqkv, wqkvT_p, HIDDEN, QKVW);
    transpose_kernel<<<dim3(HIDDEN / 32, HIDDEN / 32), dim3(32, 8)>>>(
        Wo, woT_p, HIDDEN, HIDDEN);

    // 1) QKV projection (mma.sync tf32): [4096,1024] @ [1024,3072]
    gemm_tf32_mma<<<dim3(QKVW / 128, BS / 128), 256>>>(
        x, wqkvT_p, bqkv, qkv_p, QKVW);

    // 2) Attention
    attn_kernel<<<dim3(SEQ / 64, NHEADS, BATCH), 256>>>(qkv_p, attn_p);

    // 3) Output projection (mma.sync tf32): [4096,1024] @ [1024,1024]
    gemm_tf32_mma<<<dim3(HIDDEN / 128, BS / 128), 256>>>(
        attn_p, woT_p, bo, out, HIDDEN);
}

// round 7
// speedup vs baseline: 1.6957x; 1.1794x over previous
#include <cuda_runtime.h>
#include <cuda_bf16.h>
#include <cstdint>
#include <math.h>

// Problem constants
#define HIDDEN  1024
#define NHEADS  16
#define HSIZE   64
#define BATCH   2
#define SEQ     2048
#define BS      (BATCH * SEQ)      // 4096 rows
#define QKVW    (3 * HIDDEN)       // 3072
#define GK      1024               // GEMM K (both projections)

// Scratch (allocation-free rule: __device__ globals)
__device__ float g_qkv  [ (size_t)BS * QKVW ];       // [4096][3072]
__device__ float g_attn [ (size_t)BS * HIDDEN ];     // [4096][1024]
__device__ float g_wqkvT[ (size_t)QKVW * HIDDEN ];   // Wqkv^T [3072][1024]
__device__ float g_woT  [ (size_t)HIDDEN * HIDDEN ]; // Wo^T   [1024][1024]

__device__ __forceinline__ uint32_t f2tf32(float x) {
    uint32_t u;
    asm("cvt.rna.tf32.f32 %0, %1;" : "=r"(u) : "f"(x));
    return u;
}
// Split x into hi+lo tf32 pair (hi = tf32(x), lo = tf32(x - hi))
__device__ __forceinline__ void split_tf32(float x, uint32_t& hi, uint32_t& lo) {
    uint32_t h;
    asm("cvt.rna.tf32.f32 %0, %1;" : "=r"(h) : "f"(x));
    float hf = __uint_as_float(h);
    asm("cvt.rna.tf32.f32 %0, %1;" : "=r"(lo) : "f"(x - hf));
    hi = h;
}

#define MMA_TF32(c, a, b) \
    asm volatile("mma.sync.aligned.m16n8k8.row.col.f32.tf32.tf32.f32 " \
        "{%0,%1,%2,%3}, {%4,%5,%6,%7}, {%8,%9}, {%0,%1,%2,%3};" \
        : "+f"((c)[0]), "+f"((c)[1]), "+f"((c)[2]), "+f"((c)[3]) \
        : "r"((a)[0]), "r"((a)[1]), "r"((a)[2]), "r"((a)[3]), \
          "r"((b)[0]), "r"((b)[1]))

// ---------------------------------------------------------------------------
// Transpose: out[C][R] = in[R][C]
// ---------------------------------------------------------------------------
__global__ __launch_bounds__(256) void transpose_kernel(
    const float* __restrict__ in, float* __restrict__ out, int R, int C)
{
    __shared__ float t[32][33];
    int x  = blockIdx.x * 32 + threadIdx.x;
    int y0 = blockIdx.y * 32;
    #pragma unroll
    for (int i = threadIdx.y; i < 32; i += 8)
        t[i][threadIdx.x] = in[(size_t)(y0 + i) * C + x];
    __syncthreads();
    int ox  = y0 + threadIdx.x;
    int oy0 = blockIdx.x * 32;
    #pragma unroll
    for (int i = threadIdx.y; i < 32; i += 8)
        out[(size_t)(oy0 + i) * R + ox] = t[threadIdx.x][i];
}

// ---------------------------------------------------------------------------
// tf32 mma.sync GEMM (unchanged from R5): C = A * BT^T + bias
// ---------------------------------------------------------------------------
#define BKC 16
#define SPAD 20

__global__ __launch_bounds__(256) void gemm_tf32_mma(
    const float* __restrict__ A, const float* __restrict__ BT,
    const float* __restrict__ bias, float* __restrict__ C, int N)
{
    __shared__ float As[2][128][SPAD];
    __shared__ float Bs[2][128][SPAD];

    const int tid  = threadIdx.x;
    const int lane = tid & 31;
    const int w    = tid >> 5;
    const int wm   = w & 3;
    const int wn   = w >> 2;
    const int n0   = blockIdx.x * 128;
    const int m0   = blockIdx.y * 128;
    const int g    = lane >> 2;
    const int t    = lane & 3;

    float c[2][8][4];
    #pragma unroll
    for (int mt = 0; mt < 2; mt++)
        #pragma unroll
        for (int nt = 0; nt < 8; nt++)
            #pragma unroll
            for (int i = 0; i < 4; i++) c[mt][nt][i] = 0.f;

    int lr[2], lc[2];
    #pragma unroll
    for (int it = 0; it < 2; it++) {
        int li = tid + it * 256;
        lr[it] = li >> 2;
        lc[it] = (li & 3) * 4;
    }

    float4 ra[2], rb[2];
    #pragma unroll
    for (int it = 0; it < 2; it++) {
        ra[it] = *(const float4*)(A  + (size_t)(m0 + lr[it]) * GK + lc[it]);
        rb[it] = *(const float4*)(BT + (size_t)(n0 + lr[it]) * GK + lc[it]);
    }
    #pragma unroll
    for (int it = 0; it < 2; it++) {
        float* ap = &As[0][lr[it]][lc[it]];
        ap[0] = __uint_as_float(f2tf32(ra[it].x));
        ap[1] = __uint_as_float(f2tf32(ra[it].y));
        ap[2] = __uint_as_float(f2tf32(ra[it].z));
        ap[3] = __uint_as_float(f2tf32(ra[it].w));
        float* bp = &Bs[0][lr[it]][lc[it]];
        bp[0] = __uint_as_float(f2tf32(rb[it].x));
        bp[1] = __uint_as_float(f2tf32(rb[it].y));
        bp[2] = __uint_as_float(f2tf32(rb[it].z));
        bp[3] = __uint_as_float(f2tf32(rb[it].w));
    }
    __syncthreads();

    const int NCHUNK = GK / BKC;
    for (int chunk = 0; chunk < NCHUNK; chunk++) {
        const int buf = chunk & 1;
        if (chunk + 1 < NCHUNK) {
            const int k0 = (chunk + 1) * BKC;
            #pragma unroll
            for (int it = 0; it < 2; it++) {
                ra[it] = *(const float4*)(A  + (size_t)(m0 + lr[it]) * GK + k0 + lc[it]);
                rb[it] = *(const float4*)(BT + (size_t)(n0 + lr[it]) * GK + k0 + lc[it]);
            }
        }
        #pragma unroll
        for (int ks = 0; ks < 2; ks++) {
            const int kb = ks * 8;
            uint32_t af[2][4], bf[8][2];
            #pragma unroll
            for (int mt = 0; mt < 2; mt++) {
                const int rbase = wm * 32 + mt * 16;
                af[mt][0] = __float_as_uint(As[buf][rbase + g    ][kb + t    ]);
                af[mt][1] = __float_as_uint(As[buf][rbase + g + 8][kb + t    ]);
                af[mt][2] = __float_as_uint(As[buf][rbase + g    ][kb + t + 4]);
                af[mt][3] = __float_as_uint(As[buf][rbase + g + 8][kb + t + 4]);
            }
            #pragma unroll
            for (int nt = 0; nt < 8; nt++) {
                const int nbase = wn * 64 + nt * 8;
                bf[nt][0] = __float_as_uint(Bs[buf][nbase + g][kb + t    ]);
                bf[nt][1] = __float_as_uint(Bs[buf][nbase + g][kb + t + 4]);
            }
            #pragma unroll
            for (int mt = 0; mt < 2; mt++)
                #pragma unroll
                for (int nt = 0; nt < 8; nt++)
                    MMA_TF32(c[mt][nt], af[mt], bf[nt]);
        }
        if (chunk + 1 < NCHUNK) {
            const int nb = buf ^ 1;
            #pragma unroll
            for (int it = 0; it < 2; it++) {
                float* ap = &As[nb][lr[it]][lc[it]];
                ap[0] = __uint_as_float(f2tf32(ra[it].x));
                ap[1] = __uint_as_float(f2tf32(ra[it].y));
                ap[2] = __uint_as_float(f2tf32(ra[it].z));
                ap[3] = __uint_as_float(f2tf32(ra[it].w));
                float* bp = &Bs[nb][lr[it]][lc[it]];
                bp[0] = __uint_as_float(f2tf32(rb[it].x));
                bp[1] = __uint_as_float(f2tf32(rb[it].y));
                bp[2] = __uint_as_float(f2tf32(rb[it].z));
                bp[3] = __uint_as_float(f2tf32(rb[it].w));
            }
        }
        __syncthreads();
    }

    #pragma unroll
    for (int mt = 0; mt < 2; mt++) {
        const int row = m0 + wm * 32 + mt * 16 + g;
        #pragma unroll
        for (int nt = 0; nt < 8; nt++) {
            const int col = n0 + wn * 64 + nt * 8 + t * 2;
            float2 bv = *(const float2*)(bias + col);
            float2 o0 = { c[mt][nt][0] + bv.x, c[mt][nt][1] + bv.y };
            float2 o1 = { c[mt][nt][2] + bv.x, c[mt][nt][3] + bv.y };
            *(float2*)(C + (size_t)row * N + col)       = o0;
            *(float2*)(C + (size_t)(row + 8) * N + col) = o1;
        }
    }
}

// ---------------------------------------------------------------------------
// Flash attention on tensor cores (split-tf32 mma.sync, ~fp32 accuracy).
// Grid (SEQ/64, NHEADS, BATCH), 128 threads = 4 warps; warp w owns q-rows
// w*16..w*16+15. KV tiles of 64. All fragments via SMEM, stride 68
// (bank map 4g+t: conflict-free).
// ---------------------------------------------------------------------------
#define ASTR 68
#define ATTN_SMEM (4 * 64 * ASTR * 4)   // Qs,Ks,Vt,Ps = 69632 B

__global__ __launch_bounds__(128) void attn_mma_kernel(
    const float* __restrict__ qkv, float* __restrict__ attn_out)
{
    extern __shared__ float sm[];
    float* Qs = sm;                 // [64][68]  q * scale
    float* Ks = Qs + 64 * ASTR;     // [64][68]  K tile (kv-major)
    float* Vt = Ks + 64 * ASTR;     // [64][68]  V^T tile: Vt[d][kv]
    float* Ps = Vt + 64 * ASTR;     // [64][68]  probabilities

    const int tid  = threadIdx.x;
    const int lane = tid & 31;
    const int wm   = tid >> 5;         // warp 0..3
    const int g    = lane >> 2;        // 0..7
    const int t    = lane & 3;         // 0..3
    const int q0   = blockIdx.x * 64;
    const int h    = blockIdx.y;
    const int b    = blockIdx.z;

    const float* base = qkv + (size_t)b * SEQ * QKVW;
    const int col0 = h * HSIZE;
    const int prow = wm * 16;          // warp's q-row base within tile

    // Load Q tile, pre-scaled by 1/sqrt(d)
    #pragma unroll
    for (int it = 0; it < 8; it++) {
        int idx = tid + it * 128;
        int r = idx >> 4, c4 = (idx & 15) * 4;
        float4 v = *(const float4*)(base + (size_t)(q0 + r) * QKVW + col0 + c4);
        float* p = Qs + r * ASTR + c4;
        p[0] = v.x * 0.125f; p[1] = v.y * 0.125f;
        p[2] = v.z * 0.125f; p[3] = v.w * 0.125f;
    }

    float oc[8][4];
    #pragma unroll
    for (int nt = 0; nt < 8; nt++)
        #pragma unroll
        for (int i = 0; i < 4; i++) oc[nt][i] = 0.f;
    float mstat[2] = { -1e30f, -1e30f };
    float lstat[2] = { 0.f, 0.f };

    for (int kv0 = 0; kv0 < SEQ; kv0 += 64) {
        __syncthreads();   // all warps done reading Ks/Vt from prior tile
        // Load K tile [64 kv][64 d]
        {
            int r = tid >> 1, cb = (tid & 1) * 32;
            const float* src = base + (size_t)(kv0 + r) * QKVW + HIDDEN + col0 + cb;
            float* dst = Ks + r * ASTR + cb;
            #pragma unroll
            for (int j = 0; j < 8; j++)
                *(float4*)(dst + j * 4) = *(const float4*)(src + j * 4);
        }
        // Load V transposed: Vt[d][kv]
        #pragma unroll
        for (int it = 0; it < 8; it++) {
            int idx = tid + it * 128;
            int d = idx & 63, rg = idx >> 6;     // rg 0..15, 4 kv rows each
            const float* src = base + (size_t)(kv0 + rg * 4) * QKVW + 2 * HIDDEN + col0 + d;
            float4 v;
            v.x = src[0];
            v.y = src[QKVW];
            v.z = src[2 * QKVW];
            v.w = src[3 * QKVW];
            *(float4*)(Vt + d * ASTR + rg * 4) = v;
        }
        __syncthreads();

        // ---- S = (Q*scale) K^T : 16x64 per warp, split-tf32 (3 MMAs) ----
        float sc[8][4];
        #pragma unroll
        for (int nt = 0; nt < 8; nt++)
            #pragma unroll
            for (int i = 0; i < 4; i++) sc[nt][i] = 0.f;

        #pragma unroll
        for (int ks = 0; ks < 8; ks++) {
            const int kb = ks * 8;
            float a0 = Qs[(prow + g)     * ASTR + kb + t];
            float a1 = Qs[(prow + g + 8) * ASTR + kb + t];
            float a2 = Qs[(prow + g)     * ASTR + kb + t + 4];
            float a3 = Qs[(prow + g + 8) * ASTR + kb + t + 4];
            uint32_t ah[4], al[4];
            split_tf32(a0, ah[0], al[0]); split_tf32(a1, ah[1], al[1]);
            split_tf32(a2, ah[2], al[2]); split_tf32(a3, ah[3], al[3]);
            #pragma unroll
            for (int nt = 0; nt < 8; nt++) {
                float b0 = Ks[(nt * 8 + g) * ASTR + kb + t];
                float b1 = Ks[(nt * 8 + g) * ASTR + kb + t + 4];
                uint32_t bh[2], bl[2];
                split_tf32(b0, bh[0], bl[0]); split_tf32(b1, bh[1], bl[1]);
                MMA_TF32(sc[nt], ah, bh);
                MMA_TF32(sc[nt], al, bh);
                MMA_TF32(sc[nt], ah, bl);
            }
        }

        // ---- online softmax on fragments (rows g and g+8) ----
        #pragma unroll
        for (int hf = 0; hf < 2; hf++) {
            const int i0 = hf * 2;
            float rm = -1e30f;
            #pragma unroll
            for (int nt = 0; nt < 8; nt++)
                rm = fmaxf(rm, fmaxf(sc[nt][i0], sc[nt][i0 + 1]));
            rm = fmaxf(rm, __shfl_xor_sync(0xffffffffu, rm, 1));
            rm = fmaxf(rm, __shfl_xor_sync(0xffffffffu, rm, 2));
            float nm   = fmaxf(mstat[hf], rm);
            float corr = __expf(mstat[hf] - nm);
            float rs = 0.f;
            #pragma unroll
            for (int nt = 0; nt < 8; nt++) {
                float p0 = __expf(sc[nt][i0]     - nm);
                float p1 = __expf(sc[nt][i0 + 1] - nm);
                sc[nt][i0] = p0; sc[nt][i0 + 1] = p1;
                rs += p0 + p1;
            }
            rs += __shfl_xor_sync(0xffffffffu, rs, 1);
            rs += __shfl_xor_sync(0xffffffffu, rs, 2);
            lstat[hf] = lstat[hf] * corr + rs;
            mstat[hf] = nm;
            #pragma unroll
            for (int nt = 0; nt < 8; nt++) {
                oc[nt][i0]     *= corr;
                oc[nt][i0 + 1] *= corr;
            }
        }

        // Write P fragments to smem (own warp's rows only)
        #pragma unroll
        for (int nt = 0; nt < 8; nt++) {
            float2 p0 = { sc[nt][0], sc[nt][1] };
            float2 p1 = { sc[nt][2], sc[nt][3] };
            *(float2*)(Ps + (prow + g)     * ASTR + nt * 8 + 2 * t) = p0;
            *(float2*)(Ps + (prow + g + 8) * ASTR + nt * 8 + 2 * t) = p1;
        }
        __syncwarp();

        // ---- O += P V : split-tf32 (3 MMAs) ----
        #pragma unroll
        for (int ks = 0; ks < 8; ks++) {
            const int kb = ks * 8;
            float a0 = Ps[(prow + g)     * ASTR + kb + t];
            float a1 = Ps[(prow + g + 8) * ASTR + kb + t];
            float a2 = Ps[(prow + g)     * ASTR + kb + t + 4];
            float a3 = Ps[(prow + g + 8) * ASTR + kb + t + 4];
            uint32_t ah[4], al[4];
            split_tf32(a0, ah[0], al[0]); split_tf32(a1, ah[1], al[1]);
            split_tf32(a2, ah[2], al[2]); split_tf32(a3, ah[3], al[3]);
            #pragma unroll
            for (int nt = 0; nt < 8; nt++) {
                float b0 = Vt[(nt * 8 + g) * ASTR + kb + t];
                float b1 = Vt[(nt * 8 + g) * ASTR + kb + t + 4];
                uint32_t bh[2], bl[2];
                split_tf32(b0, bh[0], bl[0]); split_tf32(b1, bh[1], bl[1]);
                MMA_TF32(oc[nt], ah, bh);
                MMA_TF32(oc[nt], al, bh);
                MMA_TF32(oc[nt], ah, bl);
            }
        }
    }

    // Epilogue: normalize + store
    const float inv0 = 1.0f / lstat[0];
    const float inv1 = 1.0f / lstat[1];
    const size_t r0 = (size_t)(b * SEQ + q0 + prow + g);
    #pragma unroll
    for (int nt = 0; nt < 8; nt++) {
        const int colw = col0 + nt * 8 + 2 * t;
        float2 o0 = { oc[nt][0] * inv0, oc[nt][1] * inv0 };
        float2 o1 = { oc[nt][2] * inv1, oc[nt][3] * inv1 };
        *(float2*)(attn_out + r0 * HIDDEN + colw)       = o0;
        *(float2*)(attn_out + (r0 + 8) * HIDDEN + colw) = o1;
    }
}

// ---------------------------------------------------------------------------
// Launch
// ---------------------------------------------------------------------------
extern "C" void kernel_launch(void* const* d_in, const int* in_sizes, int n_in,
                              void* d_out, int out_size)
{
    const float* x    = (const float*)d_in[0];
    const float* Wqkv = (const float*)d_in[1];
    const float* bqkv = (const float*)d_in[2];
    const float* Wo   = (const float*)d_in[3];
    const float* bo   = (const float*)d_in[4];
    float* out = (float*)d_out;

    float *qkv_p = nullptr, *attn_p = nullptr, *wqkvT_p = nullptr, *woT_p = nullptr;
    cudaGetSymbolAddress((void**)&qkv_p,   g_qkv);
    cudaGetSymbolAddress((void**)&attn_p,  g_attn);
    cudaGetSymbolAddress((void**)&wqkvT_p, g_wqkvT);
    cudaGetSymbolAddress((void**)&woT_p,   g_woT);

    cudaFuncSetAttribute(attn_mma_kernel,
                         cudaFuncAttributeMaxDynamicSharedMemorySize, ATTN_SMEM);

    // 0) Transpose weights
    transpose_kernel<<<dim3(QKVW / 32, HIDDEN / 32), dim3(32, 8)>>>(
        Wqkv, wqkvT_p, HIDDEN, QKVW);
    transpose_kernel<<<dim3(HIDDEN / 32, HIDDEN / 32), dim3(32, 8)>>>(
        Wo, woT_p, HIDDEN, HIDDEN);

    // 1) QKV projection
    gemm_tf32_mma<<<dim3(QKVW / 128, BS / 128), 256>>>(
        x, wqkvT_p, bqkv, qkv_p, QKVW);

    // 2) Attention (tensor-core flash attention)
    attn_mma_kernel<<<dim3(SEQ / 64, NHEADS, BATCH), 128, ATTN_SMEM>>>(
        qkv_p, attn_p);

    // 3) Output projection
    gemm_tf32_mma<<<dim3(HIDDEN / 128, BS / 128), 256>>>(
        attn_p, woT_p, bo, out, HIDDEN);
}

// round 9
// speedup vs baseline: 2.4918x; 1.4695x over previous
#include <cuda_runtime.h>
#include <cuda_bf16.h>
#include <cstdint>
#include <math.h>

// Problem constants
#define HIDDEN  1024
#define NHEADS  16
#define HSIZE   64
#define BATCH   2
#define SEQ     2048
#define BS      (BATCH * SEQ)      // 4096 rows
#define QKVW    (3 * HIDDEN)       // 3072
#define GK      1024               // GEMM K (both projections)

// Scratch (allocation-free rule: __device__ globals)
__device__ float g_qkv  [ (size_t)BS * QKVW ];       // [4096][3072]
__device__ float g_attn [ (size_t)BS * HIDDEN ];     // [4096][1024]
__device__ float g_wqkvT[ (size_t)QKVW * HIDDEN ];   // Wqkv^T [3072][1024]
__device__ float g_woT  [ (size_t)HIDDEN * HIDDEN ]; // Wo^T   [1024][1024]

__device__ __forceinline__ uint32_t f2tf32(float x) {
    uint32_t u;
    asm("cvt.rna.tf32.f32 %0, %1;" : "=r"(u) : "f"(x));
    return u;
}

#define MMA_TF32(c, a, b) \
    asm volatile("mma.sync.aligned.m16n8k8.row.col.f32.tf32.tf32.f32 " \
        "{%0,%1,%2,%3}, {%4,%5,%6,%7}, {%8,%9}, {%0,%1,%2,%3};" \
        : "+f"((c)[0]), "+f"((c)[1]), "+f"((c)[2]), "+f"((c)[3]) \
        : "r"((a)[0]), "r"((a)[1]), "r"((a)[2]), "r"((a)[3]), \
          "r"((b)[0]), "r"((b)[1]))

#define MMA_BF16(c, a, b) \
    asm volatile("mma.sync.aligned.m16n8k16.row.col.f32.bf16.bf16.f32 " \
        "{%0,%1,%2,%3}, {%4,%5,%6,%7}, {%8,%9}, {%0,%1,%2,%3};" \
        : "+f"((c)[0]), "+f"((c)[1]), "+f"((c)[2]), "+f"((c)[3]) \
        : "r"((a)[0]), "r"((a)[1]), "r"((a)[2]), "r"((a)[3]), \
          "r"((b)[0]), "r"((b)[1]))

// Split two floats (even-k x0, odd-k x1) into {hi bf16x2, lo bf16x2}
__device__ __forceinline__ uint2 split2(float x0, float x1) {
    __nv_bfloat162 h = __floats2bfloat162_rn(x0, x1);   // .x=x0(low), .y=x1(high)
    float h0 = __bfloat162float(h.x);
    float h1 = __bfloat162float(h.y);
    __nv_bfloat162 l = __floats2bfloat162_rn(x0 - h0, x1 - h1);
    uint2 r;
    r.x = *reinterpret_cast<uint32_t*>(&h);
    r.y = *reinterpret_cast<uint32_t*>(&l);
    return r;
}

// ---------------------------------------------------------------------------
// Transpose: out[C][R] = in[R][C]
// ---------------------------------------------------------------------------
__global__ __launch_bounds__(256) void transpose_kernel(
    const float* __restrict__ in, float* __restrict__ out, int R, int C)
{
    __shared__ float t[32][33];
    int x  = blockIdx.x * 32 + threadIdx.x;
    int y0 = blockIdx.y * 32;
    #pragma unroll
    for (int i = threadIdx.y; i < 32; i += 8)
        t[i][threadIdx.x] = in[(size_t)(y0 + i) * C + x];
    __syncthreads();
    int ox  = y0 + threadIdx.x;
    int oy0 = blockIdx.x * 32;
    #pragma unroll
    for (int i = threadIdx.y; i < 32; i += 8)
        out[(size_t)(oy0 + i) * R + ox] = t[threadIdx.x][i];
}

// ---------------------------------------------------------------------------
// tf32 mma.sync GEMM (unchanged): C = A * BT^T + bias
// ---------------------------------------------------------------------------
#define BKC 16
#define SPAD 20

__global__ __launch_bounds__(256) void gemm_tf32_mma(
    const float* __restrict__ A, const float* __restrict__ BT,
    const float* __restrict__ bias, float* __restrict__ C, int N)
{
    __shared__ float As[2][128][SPAD];
    __shared__ float Bs[2][128][SPAD];

    const int tid  = threadIdx.x;
    const int lane = tid & 31;
    const int w    = tid >> 5;
    const int wm   = w & 3;
    const int wn   = w >> 2;
    const int n0   = blockIdx.x * 128;
    const int m0   = blockIdx.y * 128;
    const int g    = lane >> 2;
    const int t    = lane & 3;

    float c[2][8][4];
    #pragma unroll
    for (int mt = 0; mt < 2; mt++)
        #pragma unroll
        for (int nt = 0; nt < 8; nt++)
            #pragma unroll
            for (int i = 0; i < 4; i++) c[mt][nt][i] = 0.f;

    int lr[2], lc[2];
    #pragma unroll
    for (int it = 0; it < 2; it++) {
        int li = tid + it * 256;
        lr[it] = li >> 2;
        lc[it] = (li & 3) * 4;
    }

    float4 ra[2], rb[2];
    #pragma unroll
    for (int it = 0; it < 2; it++) {
        ra[it] = *(const float4*)(A  + (size_t)(m0 + lr[it]) * GK + lc[it]);
        rb[it] = *(const float4*)(BT + (size_t)(n0 + lr[it]) * GK + lc[it]);
    }
    #pragma unroll
    for (int it = 0; it < 2; it++) {
        float* ap = &As[0][lr[it]][lc[it]];
        ap[0] = __uint_as_float(f2tf32(ra[it].x));
        ap[1] = __uint_as_float(f2tf32(ra[it].y));
        ap[2] = __uint_as_float(f2tf32(ra[it].z));
        ap[3] = __uint_as_float(f2tf32(ra[it].w));
        float* bp = &Bs[0][lr[it]][lc[it]];
        bp[0] = __uint_as_float(f2tf32(rb[it].x));
        bp[1] = __uint_as_float(f2tf32(rb[it].y));
        bp[2] = __uint_as_float(f2tf32(rb[it].z));
        bp[3] = __uint_as_float(f2tf32(rb[it].w));
    }
    __syncthreads();

    const int NCHUNK = GK / BKC;
    for (int chunk = 0; chunk < NCHUNK; chunk++) {
        const int buf = chunk & 1;
        if (chunk + 1 < NCHUNK) {
            const int k0 = (chunk + 1) * BKC;
            #pragma unroll
            for (int it = 0; it < 2; it++) {
                ra[it] = *(const float4*)(A  + (size_t)(m0 + lr[it]) * GK + k0 + lc[it]);
                rb[it] = *(const float4*)(BT + (size_t)(n0 + lr[it]) * GK + k0 + lc[it]);
            }
        }
        #pragma unroll
        for (int ks = 0; ks < 2; ks++) {
            const int kb = ks * 8;
            uint32_t af[2][4], bf[8][2];
            #pragma unroll
            for (int mt = 0; mt < 2; mt++) {
                const int rbase = wm * 32 + mt * 16;
                af[mt][0] = __float_as_uint(As[buf][rbase + g    ][kb + t    ]);
                af[mt][1] = __float_as_uint(As[buf][rbase + g + 8][kb + t    ]);
                af[mt][2] = __float_as_uint(As[buf][rbase + g    ][kb + t + 4]);
                af[mt][3] = __float_as_uint(As[buf][rbase + g + 8][kb + t + 4]);
            }
            #pragma unroll
            for (int nt = 0; nt < 8; nt++) {
                const int nbase = wn * 64 + nt * 8;
                bf[nt][0] = __float_as_uint(Bs[buf][nbase + g][kb + t    ]);
                bf[nt][1] = __float_as_uint(Bs[buf][nbase + g][kb + t + 4]);
            }
            #pragma unroll
            for (int mt = 0; mt < 2; mt++)
                #pragma unroll
                for (int nt = 0; nt < 8; nt++)
                    MMA_TF32(c[mt][nt], af[mt], bf[nt]);
        }
        if (chunk + 1 < NCHUNK) {
            const int nb = buf ^ 1;
            #pragma unroll
            for (int it = 0; it < 2; it++) {
                float* ap = &As[nb][lr[it]][lc[it]];
                ap[0] = __uint_as_float(f2tf32(ra[it].x));
                ap[1] = __uint_as_float(f2tf32(ra[it].y));
                ap[2] = __uint_as_float(f2tf32(ra[it].z));
                ap[3] = __uint_as_float(f2tf32(ra[it].w));
                float* bp = &Bs[nb][lr[it]][lc[it]];
                bp[0] = __uint_as_float(f2tf32(rb[it].x));
                bp[1] = __uint_as_float(f2tf32(rb[it].y));
                bp[2] = __uint_as_float(f2tf32(rb[it].z));
                bp[3] = __uint_as_float(f2tf32(rb[it].w));
            }
        }
        __syncthreads();
    }

    #pragma unroll
    for (int mt = 0; mt < 2; mt++) {
        const int row = m0 + wm * 32 + mt * 16 + g;
        #pragma unroll
        for (int nt = 0; nt < 8; nt++) {
            const int col = n0 + wn * 64 + nt * 8 + t * 2;
            float2 bv = *(const float2*)(bias + col);
            float2 o0 = { c[mt][nt][0] + bv.x, c[mt][nt][1] + bv.y };
            float2 o1 = { c[mt][nt][2] + bv.x, c[mt][nt][3] + bv.y };
            *(float2*)(C + (size_t)row * N + col)       = o0;
            *(float2*)(C + (size_t)(row + 8) * N + col) = o1;
        }
    }
}

// ---------------------------------------------------------------------------
// Flash attention on tensor cores — bf16x3 (m16n8k16), pre-split SMEM planes.
// Grid (SEQ/64, NHEADS, BATCH), 128 threads = 4 warps; warp wm owns q-rows
// wm*16..+15. KV tiles of 64.
// Each plane: [64 rows][32 k-pairs] of uint2 {hi bf16x2, lo bf16x2},
// row stride 36 uint2 -> fragment reads hit banks (4g+t): conflict-free.
// Inner loops: LDS.64 + HMMA only (all cvt hoisted to load time).
// ---------------------------------------------------------------------------
#define PLSTR 36
#define PLANE (64 * PLSTR)              // uint2 elements per plane
#define ATTN_SMEM (4 * PLANE * 8)       // Qp,Kp,Vp,Pp = 73728 B

__global__ __launch_bounds__(128) void attn_mma_kernel(
    const float* __restrict__ qkv, float* __restrict__ attn_out)
{
    extern __shared__ uint2 smp[];
    uint2* Qp = smp;                // Q * scale, split
    uint2* Kp = Qp + PLANE;         // K tile, split
    uint2* Vp = Kp + PLANE;         // V^T tile (Vt[d][kv]), split
    uint2* Pp = Vp + PLANE;         // probabilities, split

    const int tid  = threadIdx.x;
    const int lane = tid & 31;
    const int wm   = tid >> 5;         // warp 0..3
    const int g    = lane >> 2;        // 0..7
    const int t    = lane & 3;         // 0..3
    const int q0   = blockIdx.x * 64;
    const int h    = blockIdx.y;
    const int b    = blockIdx.z;

    const float* base = qkv + (size_t)b * SEQ * QKVW;
    const int col0 = h * HSIZE;
    const int prow = wm * 16;          // warp's q-row base within tile

    // Load Q tile, pre-scaled, split into bf16 hi/lo pairs
    #pragma unroll
    for (int it = 0; it < 8; it++) {
        int idx = tid + it * 128;
        int r = idx >> 4, c4 = (idx & 15) * 4;
        float4 v = *(const float4*)(base + (size_t)(q0 + r) * QKVW + col0 + c4);
        v.x *= 0.125f; v.y *= 0.125f; v.z *= 0.125f; v.w *= 0.125f;
        Qp[r * PLSTR + (c4 >> 1)    ] = split2(v.x, v.y);
        Qp[r * PLSTR + (c4 >> 1) + 1] = split2(v.z, v.w);
    }

    float oc[8][4];
    #pragma unroll
    for (int nt = 0; nt < 8; nt++)
        #pragma unroll
        for (int i = 0; i < 4; i++) oc[nt][i] = 0.f;
    float mstat[2] = { -1e30f, -1e30f };
    float lstat[2] = { 0.f, 0.f };

    for (int kv0 = 0; kv0 < SEQ; kv0 += 64) {
        __syncthreads();   // prior tile's K/V reads done (also covers Q init)
        // Load K tile [64 kv][64 d], split
        #pragma unroll
        for (int it = 0; it < 8; it++) {
            int idx = tid + it * 128;
            int r = idx >> 4, c4 = (idx & 15) * 4;
            float4 v = *(const float4*)(base + (size_t)(kv0 + r) * QKVW
                                        + HIDDEN + col0 + c4);
            Kp[r * PLSTR + (c4 >> 1)    ] = split2(v.x, v.y);
            Kp[r * PLSTR + (c4 >> 1) + 1] = split2(v.z, v.w);
        }
        // Load V transposed (Vt[d][kv]), split; pairs along kv
        #pragma unroll
        for (int it = 0; it < 8; it++) {
            int idx = tid + it * 128;
            int d = idx & 63, pg = idx >> 6;     // pg 0..15, 4 kv rows each
            const float* src = base + (size_t)(kv0 + pg * 4) * QKVW
                               + 2 * HIDDEN + col0 + d;
            float v0 = src[0];
            float v1 = src[QKVW];
            float v2 = src[2 * QKVW];
            float v3 = src[3 * QKVW];
            Vp[d * PLSTR + pg * 2    ] = split2(v0, v1);
            Vp[d * PLSTR + pg * 2 + 1] = split2(v2, v3);
        }
        __syncthreads();

        // ---- S = (Q*scale) K^T : 16x64 per warp, bf16x3 ----
        float sc[8][4];
        #pragma unroll
        for (int nt = 0; nt < 8; nt++)
            #pragma unroll
            for (int i = 0; i < 4; i++) sc[nt][i] = 0.f;

        #pragma unroll
        for (int ks = 0; ks < 4; ks++) {       // k16 steps over d=64
            const int ab = (prow + g) * PLSTR + ks * 8;
            uint2 qa0 = Qp[ab + t];
            uint2 qa1 = Qp[ab + 8 * PLSTR + t];
            uint2 qa2 = Qp[ab + t + 4];
            uint2 qa3 = Qp[ab + 8 * PLSTR + t + 4];
            uint32_t ah[4] = { qa0.x, qa1.x, qa2.x, qa3.x };
            uint32_t al[4] = { qa0.y, qa1.y, qa2.y, qa3.y };
            #pragma unroll
            for (int nt = 0; nt < 8; nt++) {
                const int bb = (nt * 8 + g) * PLSTR + ks * 8;
                uint2 kb0 = Kp[bb + t];
                uint2 kb1 = Kp[bb + t + 4];
                uint32_t bh[2] = { kb0.x, kb1.x };
                uint32_t bl[2] = { kb0.y, kb1.y };
                MMA_BF16(sc[nt], ah, bh);
                MMA_BF16(sc[nt], al, bh);
                MMA_BF16(sc[nt], ah, bl);
            }
        }

        // ---- online softmax on fragments (rows g and g+8) ----
        #pragma unroll
        for (int hf = 0; hf < 2; hf++) {
            const int i0 = hf * 2;
            float rm = -1e30f;
            #pragma unroll
            for (int nt = 0; nt < 8; nt++)
                rm = fmaxf(rm, fmaxf(sc[nt][i0], sc[nt][i0 + 1]));
            rm = fmaxf(rm, __shfl_xor_sync(0xffffffffu, rm, 1));
            rm = fmaxf(rm, __shfl_xor_sync(0xffffffffu, rm, 2));
            float nm   = fmaxf(mstat[hf], rm);
            float corr = __expf(mstat[hf] - nm);
            float rs = 0.f;
            #pragma unroll
            for (int nt = 0; nt < 8; nt++) {
                float p0 = __expf(sc[nt][i0]     - nm);
                float p1 = __expf(sc[nt][i0 + 1] - nm);
                sc[nt][i0] = p0; sc[nt][i0 + 1] = p1;
                rs += p0 + p1;
            }
            rs += __shfl_xor_sync(0xffffffffu, rs, 1);
            rs += __shfl_xor_sync(0xffffffffu, rs, 2);
            lstat[hf] = lstat[hf] * corr + rs;
            mstat[hf] = nm;
            #pragma unroll
            for (int nt = 0; nt < 8; nt++) {
                oc[nt][i0]     *= corr;
                oc[nt][i0 + 1] *= corr;
            }
        }

        // Write P fragments split to smem (own warp's rows; c0/c1 are
        // adjacent kv columns -> direct pair packing)
        #pragma unroll
        for (int nt = 0; nt < 8; nt++) {
            Pp[(prow + g)     * PLSTR + nt * 4 + t] = split2(sc[nt][0], sc[nt][1]);
            Pp[(prow + g + 8) * PLSTR + nt * 4 + t] = split2(sc[nt][2], sc[nt][3]);
        }
        __syncwarp();

        // ---- O += P V : bf16x3, contract over kv=64 ----
        #pragma unroll
        for (int ks = 0; ks < 4; ks++) {
            const int ab = (prow + g) * PLSTR + ks * 8;
            uint2 pa0 = Pp[ab + t];
            uint2 pa1 = Pp[ab + 8 * PLSTR + t];
            uint2 pa2 = Pp[ab + t + 4];
            uint2 pa3 = Pp[ab + 8 * PLSTR + t + 4];
            uint32_t ah[4] = { pa0.x, pa1.x, pa2.x, pa3.x };
            uint32_t al[4] = { pa0.y, pa1.y, pa2.y, pa3.y };
            #pragma unroll
            for (int nt = 0; nt < 8; nt++) {
                const int bb = (nt * 8 + g) * PLSTR + ks * 8;
                uint2 vb0 = Vp[bb + t];
                uint2 vb1 = Vp[bb + t + 4];
                uint32_t bh[2] = { vb0.x, vb1.x };
                uint32_t bl[2] = { vb0.y, vb1.y };
                MMA_BF16(oc[nt], ah, bh);
                MMA_BF16(oc[nt], al, bh);
                MMA_BF16(oc[nt], ah, bl);
            }
        }
    }

    // Epilogue: normalize + store
    const float inv0 = 1.0f / lstat[0];
    const float inv1 = 1.0f / lstat[1];
    const size_t r0 = (size_t)(b * SEQ + q0 + prow + g);
    #pragma unroll
    for (int nt = 0; nt < 8; nt++) {
        const int colw = col0 + nt * 8 + 2 * t;
        float2 o0 = { oc[nt][0] * inv0, oc[nt][1] * inv0 };
        float2 o1 = { oc[nt][2] * inv1, oc[nt][3] * inv1 };
        *(float2*)(attn_out + r0 * HIDDEN + colw)       = o0;
        *(float2*)(attn_out + (r0 + 8) * HIDDEN + colw) = o1;
    }
}

// ---------------------------------------------------------------------------
// Launch
// ---------------------------------------------------------------------------
extern "C" void kernel_launch(void* const* d_in, const int* in_sizes, int n_in,
                              void* d_out, int out_size)
{
    const float* x    = (const float*)d_in[0];
    const float* Wqkv = (const float*)d_in[1];
    const float* bqkv = (const float*)d_in[2];
    const float* Wo   = (const float*)d_in[3];
    const float* bo   = (const float*)d_in[4];
    float* out = (float*)d_out;

    float *qkv_p = nullptr, *attn_p = nullptr, *wqkvT_p = nullptr, *woT_p = nullptr;
    cudaGetSymbolAddress((void**)&qkv_p,   g_qkv);
    cudaGetSymbolAddress((void**)&attn_p,  g_attn);
    cudaGetSymbolAddress((void**)&wqkvT_p, g_wqkvT);
    cudaGetSymbolAddress((void**)&woT_p,   g_woT);

    cudaFuncSetAttribute(attn_mma_kernel,
                         cudaFuncAttributeMaxDynamicSharedMemorySize, ATTN_SMEM);

    // 0) Transpose weights
    transpose_kernel<<<dim3(QKVW / 32, HIDDEN / 32), dim3(32, 8)>>>(
        Wqkv, wqkvT_p, HIDDEN, QKVW);
    transpose_kernel<<<dim3(HIDDEN / 32, HIDDEN / 32), dim3(32, 8)>>>(
        Wo, woT_p, HIDDEN, HIDDEN);

    // 1) QKV projection
    gemm_tf32_mma<<<dim3(QKVW / 128, BS / 128), 256>>>(
        x, wqkvT_p, bqkv, qkv_p, QKVW);

    // 2) Attention (bf16x3 tensor-core flash attention)
    attn_mma_kernel<<<dim3(SEQ / 64, NHEADS, BATCH), 128, ATTN_SMEM>>>(
        qkv_p, attn_p);

    // 3) Output projection
    gemm_tf32_mma<<<dim3(HIDDEN / 128, BS / 128), 256>>>(
        attn_p, woT_p, bo, out, HIDDEN);
}

// round 10
// speedup vs baseline: 2.9876x; 1.1989x over previous
#include <cuda_runtime.h>
#include <cuda_bf16.h>
#include <cstdint>
#include <math.h>

// Problem constants
#define HIDDEN  1024
#define NHEADS  16
#define HSIZE   64
#define BATCH   2
#define SEQ     2048
#define BS      (BATCH * SEQ)      // 4096 rows
#define QKVW    (3 * HIDDEN)       // 3072
#define GK      1024               // GEMM K (both projections)

// Scratch (allocation-free rule: __device__ globals)
__device__ float g_qkv  [ (size_t)BS * QKVW ];       // [4096][3072]
__device__ float g_attn [ (size_t)BS * HIDDEN ];     // [4096][1024]
__device__ float g_wqkvT[ (size_t)QKVW * HIDDEN ];   // Wqkv^T [3072][1024]
__device__ float g_woT  [ (size_t)HIDDEN * HIDDEN ]; // Wo^T   [1024][1024]

__device__ __forceinline__ uint32_t f2tf32(float x) {
    uint32_t u;
    asm("cvt.rna.tf32.f32 %0, %1;" : "=r"(u) : "f"(x));
    return u;
}

#define MMA_TF32(c, a, b) \
    asm volatile("mma.sync.aligned.m16n8k8.row.col.f32.tf32.tf32.f32 " \
        "{%0,%1,%2,%3}, {%4,%5,%6,%7}, {%8,%9}, {%0,%1,%2,%3};" \
        : "+f"((c)[0]), "+f"((c)[1]), "+f"((c)[2]), "+f"((c)[3]) \
        : "r"((a)[0]), "r"((a)[1]), "r"((a)[2]), "r"((a)[3]), \
          "r"((b)[0]), "r"((b)[1]))

#define MMA_BF16(c, a, b) \
    asm volatile("mma.sync.aligned.m16n8k16.row.col.f32.bf16.bf16.f32 " \
        "{%0,%1,%2,%3}, {%4,%5,%6,%7}, {%8,%9}, {%0,%1,%2,%3};" \
        : "+f"((c)[0]), "+f"((c)[1]), "+f"((c)[2]), "+f"((c)[3]) \
        : "r"((a)[0]), "r"((a)[1]), "r"((a)[2]), "r"((a)[3]), \
          "r"((b)[0]), "r"((b)[1]))

#define LDMX4(r, a) \
    asm volatile("ldmatrix.sync.aligned.m8n8.x4.shared.b16 {%0,%1,%2,%3}, [%4];" \
        : "=r"((r)[0]), "=r"((r)[1]), "=r"((r)[2]), "=r"((r)[3]) : "r"(a))

#define LDMX4T(r, a) \
    asm volatile("ldmatrix.sync.aligned.m8n8.x4.trans.shared.b16 {%0,%1,%2,%3}, [%4];" \
        : "=r"((r)[0]), "=r"((r)[1]), "=r"((r)[2]), "=r"((r)[3]) : "r"(a))

// Split two floats into {hi bf16x2, lo bf16x2}
__device__ __forceinline__ uint2 split2(float x0, float x1) {
    __nv_bfloat162 h = __floats2bfloat162_rn(x0, x1);
    float h0 = __bfloat162float(h.x);
    float h1 = __bfloat162float(h.y);
    __nv_bfloat162 l = __floats2bfloat162_rn(x0 - h0, x1 - h1);
    uint2 r;
    r.x = *reinterpret_cast<uint32_t*>(&h);
    r.y = *reinterpret_cast<uint32_t*>(&l);
    return r;
}

// ---------------------------------------------------------------------------
// Transpose: out[C][R] = in[R][C]
// ---------------------------------------------------------------------------
__global__ __launch_bounds__(256) void transpose_kernel(
    const float* __restrict__ in, float* __restrict__ out, int R, int C)
{
    __shared__ float t[32][33];
    int x  = blockIdx.x * 32 + threadIdx.x;
    int y0 = blockIdx.y * 32;
    #pragma unroll
    for (int i = threadIdx.y; i < 32; i += 8)
        t[i][threadIdx.x] = in[(size_t)(y0 + i) * C + x];
    __syncthreads();
    int ox  = y0 + threadIdx.x;
    int oy0 = blockIdx.x * 32;
    #pragma unroll
    for (int i = threadIdx.y; i < 32; i += 8)
        out[(size_t)(oy0 + i) * R + ox] = t[threadIdx.x][i];
}

// ---------------------------------------------------------------------------
// tf32 mma.sync GEMM (unchanged): C = A * BT^T + bias
// ---------------------------------------------------------------------------
#define BKC 16
#define SPAD 20

__global__ __launch_bounds__(256) void gemm_tf32_mma(
    const float* __restrict__ A, const float* __restrict__ BT,
    const float* __restrict__ bias, float* __restrict__ C, int N)
{
    __shared__ float As[2][128][SPAD];
    __shared__ float Bs[2][128][SPAD];

    const int tid  = threadIdx.x;
    const int lane = tid & 31;
    const int w    = tid >> 5;
    const int wm   = w & 3;
    const int wn   = w >> 2;
    const int n0   = blockIdx.x * 128;
    const int m0   = blockIdx.y * 128;
    const int g    = lane >> 2;
    const int t    = lane & 3;

    float c[2][8][4];
    #pragma unroll
    for (int mt = 0; mt < 2; mt++)
        #pragma unroll
        for (int nt = 0; nt < 8; nt++)
            #pragma unroll
            for (int i = 0; i < 4; i++) c[mt][nt][i] = 0.f;

    int lr[2], lc[2];
    #pragma unroll
    for (int it = 0; it < 2; it++) {
        int li = tid + it * 256;
        lr[it] = li >> 2;
        lc[it] = (li & 3) * 4;
    }

    float4 ra[2], rb[2];
    #pragma unroll
    for (int it = 0; it < 2; it++) {
        ra[it] = *(const float4*)(A  + (size_t)(m0 + lr[it]) * GK + lc[it]);
        rb[it] = *(const float4*)(BT + (size_t)(n0 + lr[it]) * GK + lc[it]);
    }
    #pragma unroll
    for (int it = 0; it < 2; it++) {
        float* ap = &As[0][lr[it]][lc[it]];
        ap[0] = __uint_as_float(f2tf32(ra[it].x));
        ap[1] = __uint_as_float(f2tf32(ra[it].y));
        ap[2] = __uint_as_float(f2tf32(ra[it].z));
        ap[3] = __uint_as_float(f2tf32(ra[it].w));
        float* bp = &Bs[0][lr[it]][lc[it]];
        bp[0] = __uint_as_float(f2tf32(rb[it].x));
        bp[1] = __uint_as_float(f2tf32(rb[it].y));
        bp[2] = __uint_as_float(f2tf32(rb[it].z));
        bp[3] = __uint_as_float(f2tf32(rb[it].w));
    }
    __syncthreads();

    const int NCHUNK = GK / BKC;
    for (int chunk = 0; chunk < NCHUNK; chunk++) {
        const int buf = chunk & 1;
        if (chunk + 1 < NCHUNK) {
            const int k0 = (chunk + 1) * BKC;
            #pragma unroll
            for (int it = 0; it < 2; it++) {
                ra[it] = *(const float4*)(A  + (size_t)(m0 + lr[it]) * GK + k0 + lc[it]);
                rb[it] = *(const float4*)(BT + (size_t)(n0 + lr[it]) * GK + k0 + lc[it]);
            }
        }
        #pragma unroll
        for (int ks = 0; ks < 2; ks++) {
            const int kb = ks * 8;
            uint32_t af[2][4], bf[8][2];
            #pragma unroll
            for (int mt = 0; mt < 2; mt++) {
                const int rbase = wm * 32 + mt * 16;
                af[mt][0] = __float_as_uint(As[buf][rbase + g    ][kb + t    ]);
                af[mt][1] = __float_as_uint(As[buf][rbase + g + 8][kb + t    ]);
                af[mt][2] = __float_as_uint(As[buf][rbase + g    ][kb + t + 4]);
                af[mt][3] = __float_as_uint(As[buf][rbase + g + 8][kb + t + 4]);
            }
            #pragma unroll
            for (int nt = 0; nt < 8; nt++) {
                const int nbase = wn * 64 + nt * 8;
                bf[nt][0] = __float_as_uint(Bs[buf][nbase + g][kb + t    ]);
                bf[nt][1] = __float_as_uint(Bs[buf][nbase + g][kb + t + 4]);
            }
            #pragma unroll
            for (int mt = 0; mt < 2; mt++)
                #pragma unroll
                for (int nt = 0; nt < 8; nt++)
                    MMA_TF32(c[mt][nt], af[mt], bf[nt]);
        }
        if (chunk + 1 < NCHUNK) {
            const int nb = buf ^ 1;
            #pragma unroll
            for (int it = 0; it < 2; it++) {
                float* ap = &As[nb][lr[it]][lc[it]];
                ap[0] = __uint_as_float(f2tf32(ra[it].x));
                ap[1] = __uint_as_float(f2tf32(ra[it].y));
                ap[2] = __uint_as_float(f2tf32(ra[it].z));
                ap[3] = __uint_as_float(f2tf32(ra[it].w));
                float* bp = &Bs[nb][lr[it]][lc[it]];
                bp[0] = __uint_as_float(f2tf32(rb[it].x));
                bp[1] = __uint_as_float(f2tf32(rb[it].y));
                bp[2] = __uint_as_float(f2tf32(rb[it].z));
                bp[3] = __uint_as_float(f2tf32(rb[it].w));
            }
        }
        __syncthreads();
    }

    #pragma unroll
    for (int mt = 0; mt < 2; mt++) {
        const int row = m0 + wm * 32 + mt * 16 + g;
        #pragma unroll
        for (int nt = 0; nt < 8; nt++) {
            const int col = n0 + wn * 64 + nt * 8 + t * 2;
            float2 bv = *(const float2*)(bias + col);
            float2 o0 = { c[mt][nt][0] + bv.x, c[mt][nt][1] + bv.y };
            float2 o1 = { c[mt][nt][2] + bv.x, c[mt][nt][3] + bv.y };
            *(float2*)(C + (size_t)row * N + col)       = o0;
            *(float2*)(C + (size_t)(row + 8) * N + col) = o1;
        }
    }
}

// ---------------------------------------------------------------------------
// Flash attention — bf16x3 m16n8k16, ldmatrix fragments, BQ=128, 8 warps.
// Grid (SEQ/128, NHEADS, BATCH), 256 threads; warp wm owns q-rows wm*16..+15.
// SMEM planes (bf16, row stride 144B = 72 bf16, 64 data cols):
//   QH[128] QL[128] KH[64] KL[64] VH[64] VL[64] PH[128] PL[128]
// K stored [kv][d] (native .col B for QK); V stored [kv][d] and read with
// ldmatrix.trans for PV. All cvt hoisted to load/P-write time.
// ---------------------------------------------------------------------------
#define RSTR 144                       // bytes per plane row
#define OQH 0
#define OQL (OQH + 128 * RSTR)         // 18432
#define OKH (OQL + 128 * RSTR)         // 36864
#define OKL (OKH + 64 * RSTR)          // 46080
#define OVH (OKL + 64 * RSTR)          // 55296
#define OVL (OVH + 64 * RSTR)          // 64512
#define OPH (OVL + 64 * RSTR)          // 73728
#define OPL (OPH + 128 * RSTR)         // 92160
#define ATTN_SMEM (OPL + 128 * RSTR)   // 110592 B

__global__ __launch_bounds__(256, 2) void attn_mma_kernel(
    const float* __restrict__ qkv, float* __restrict__ attn_out)
{
    extern __shared__ char sm[];
    const uint32_t smb = (uint32_t)__cvta_generic_to_shared(sm);

    const int tid  = threadIdx.x;
    const int lane = tid & 31;
    const int wm   = tid >> 5;         // warp 0..7
    const int g    = lane >> 2;        // 0..7
    const int t    = lane & 3;         // 0..3
    const int q0   = blockIdx.x * 128;
    const int h    = blockIdx.y;
    const int b    = blockIdx.z;

    const float* base = qkv + (size_t)b * SEQ * QKVW;
    const int col0 = h * HSIZE;
    const int prow = wm * 16;

    // ldmatrix base addresses (per-lane, precomputed)
    const uint32_t aRow = (uint32_t)(prow + (lane & 15)) * RSTR + (lane >> 4) * 16;
    const uint32_t qA = smb + OQH + aRow;              // +ks*32 ; lo at +18432
    const uint32_t pA = smb + OPH + aRow;              // +ks*32 ; lo at +18432
    const uint32_t kB = smb + OKH
        + (uint32_t)((((lane >> 4) & 1) * 8) + (lane & 7)) * RSTR
        + ((lane >> 3) & 1) * 16;                      // +p*2304 + ks*32 ; lo +9216
    const uint32_t vB = smb + OVH
        + (uint32_t)((((lane >> 3) & 1) * 8) + (lane & 7)) * RSTR
        + ((lane >> 4) & 1) * 16;                      // +ks*2304 + p*32 ; lo +9216

    // Load Q tile (128 x 64), scaled, split into hi/lo planes
    #pragma unroll
    for (int it = 0; it < 8; it++) {
        int idx = tid + it * 256;
        int r = idx >> 4, c4 = (idx & 15) * 4;
        float4 v = *(const float4*)(base + (size_t)(q0 + r) * QKVW + col0 + c4);
        v.x *= 0.125f; v.y *= 0.125f; v.z *= 0.125f; v.w *= 0.125f;
        uint2 s0 = split2(v.x, v.y), s1 = split2(v.z, v.w);
        int off = r * RSTR + c4 * 2;
        *(uint2*)(sm + OQH + off) = make_uint2(s0.x, s1.x);
        *(uint2*)(sm + OQL + off) = make_uint2(s0.y, s1.y);
    }

    float oc[8][4];
    #pragma unroll
    for (int nt = 0; nt < 8; nt++)
        #pragma unroll
        for (int i = 0; i < 4; i++) oc[nt][i] = 0.f;
    float mstat[2] = { -1e30f, -1e30f };
    float lstat[2] = { 0.f, 0.f };

    for (int kv0 = 0; kv0 < SEQ; kv0 += 64) {
        __syncthreads();   // prior tile's K/V fragment reads complete
        // Load K and V tiles (64 x 64 each), split into planes
        #pragma unroll
        for (int it = 0; it < 4; it++) {
            int idx = tid + it * 256;
            int r = idx >> 4, c4 = (idx & 15) * 4;
            int off = r * RSTR + c4 * 2;
            const float* rowp = base + (size_t)(kv0 + r) * QKVW + col0 + c4;
            float4 kv_ = *(const float4*)(rowp + HIDDEN);
            uint2 k0 = split2(kv_.x, kv_.y), k1 = split2(kv_.z, kv_.w);
            *(uint2*)(sm + OKH + off) = make_uint2(k0.x, k1.x);
            *(uint2*)(sm + OKL + off) = make_uint2(k0.y, k1.y);
            float4 vv = *(const float4*)(rowp + 2 * HIDDEN);
            uint2 v0 = split2(vv.x, vv.y), v1 = split2(vv.z, vv.w);
            *(uint2*)(sm + OVH + off) = make_uint2(v0.x, v1.x);
            *(uint2*)(sm + OVL + off) = make_uint2(v0.y, v1.y);
        }
        __syncthreads();

        // ---- S = (Q*scale) K^T : 16x64 per warp, bf16x3 ----
        float sc[8][4];
        #pragma unroll
        for (int nt = 0; nt < 8; nt++)
            #pragma unroll
            for (int i = 0; i < 4; i++) sc[nt][i] = 0.f;

        #pragma unroll
        for (int ks = 0; ks < 4; ks++) {
            uint32_t ah[4], al[4];
            LDMX4(ah, qA + ks * 32);
            LDMX4(al, qA + 18432 + ks * 32);
            #pragma unroll
            for (int p = 0; p < 4; p++) {
                uint32_t bh[4], bl[4];
                LDMX4(bh, kB + p * 2304 + ks * 32);
                LDMX4(bl, kB + 9216 + p * 2304 + ks * 32);
                MMA_BF16(sc[2*p],   ah, bh);
                MMA_BF16(sc[2*p],   al, bh);
                MMA_BF16(sc[2*p],   ah, bl);
                MMA_BF16(sc[2*p+1], ah, bh + 2);
                MMA_BF16(sc[2*p+1], al, bh + 2);
                MMA_BF16(sc[2*p+1], ah, bl + 2);
            }
        }

        // ---- online softmax on fragments (rows g and g+8) ----
        #pragma unroll
        for (int hf = 0; hf < 2; hf++) {
            const int i0 = hf * 2;
            float rm = -1e30f;
            #pragma unroll
            for (int nt = 0; nt < 8; nt++)
                rm = fmaxf(rm, fmaxf(sc[nt][i0], sc[nt][i0 + 1]));
            rm = fmaxf(rm, __shfl_xor_sync(0xffffffffu, rm, 1));
            rm = fmaxf(rm, __shfl_xor_sync(0xffffffffu, rm, 2));
            float nm   = fmaxf(mstat[hf], rm);
            float corr = __expf(mstat[hf] - nm);
            float rs = 0.f;
            #pragma unroll
            for (int nt = 0; nt < 8; nt++) {
                float p0 = __expf(sc[nt][i0]     - nm);
                float p1 = __expf(sc[nt][i0 + 1] - nm);
                sc[nt][i0] = p0; sc[nt][i0 + 1] = p1;
                rs += p0 + p1;
            }
            rs += __shfl_xor_sync(0xffffffffu, rs, 1);
            rs += __shfl_xor_sync(0xffffffffu, rs, 2);
            lstat[hf] = lstat[hf] * corr + rs;
            mstat[hf] = nm;
            #pragma unroll
            for (int nt = 0; nt < 8; nt++) {
                oc[nt][i0]     *= corr;
                oc[nt][i0 + 1] *= corr;
            }
        }

        // Write P fragments split to planes (own warp's rows)
        #pragma unroll
        for (int nt = 0; nt < 8; nt++) {
            uint2 s0 = split2(sc[nt][0], sc[nt][1]);
            uint2 s1 = split2(sc[nt][2], sc[nt][3]);
            int off0 = (prow + g)     * RSTR + nt * 16 + 4 * t;
            int off1 = (prow + g + 8) * RSTR + nt * 16 + 4 * t;
            *(uint32_t*)(sm + OPH + off0) = s0.x;
            *(uint32_t*)(sm + OPL + off0) = s0.y;
            *(uint32_t*)(sm + OPH + off1) = s1.x;
            *(uint32_t*)(sm + OPL + off1) = s1.y;
        }
        __syncwarp();

        // ---- O += P V : bf16x3, V read transposed via ldmatrix.trans ----
        #pragma unroll
        for (int ks = 0; ks < 4; ks++) {
            uint32_t ah[4], al[4];
            LDMX4(ah, pA + ks * 32);
            LDMX4(al, pA + 18432 + ks * 32);
            #pragma unroll
            for (int p = 0; p < 4; p++) {
                uint32_t bh[4], bl[4];
                LDMX4T(bh, vB + ks * 2304 + p * 32);
                LDMX4T(bl, vB + 9216 + ks * 2304 + p * 32);
                MMA_BF16(oc[2*p],   ah, bh);
                MMA_BF16(oc[2*p],   al, bh);
                MMA_BF16(oc[2*p],   ah, bl);
                MMA_BF16(oc[2*p+1], ah, bh + 2);
                MMA_BF16(oc[2*p+1], al, bh + 2);
                MMA_BF16(oc[2*p+1], ah, bl + 2);
            }
        }
    }

    // Epilogue: normalize + store
    const float inv0 = 1.0f / lstat[0];
    const float inv1 = 1.0f / lstat[1];
    const size_t r0 = (size_t)(b * SEQ + q0 + prow + g);
    #pragma unroll
    for (int nt = 0; nt < 8; nt++) {
        const int colw = col0 + nt * 8 + 2 * t;
        float2 o0 = { oc[nt][0] * inv0, oc[nt][1] * inv0 };
        float2 o1 = { oc[nt][2] * inv1, oc[nt][3] * inv1 };
        *(float2*)(attn_out + r0 * HIDDEN + colw)       = o0;
        *(float2*)(attn_out + (r0 + 8) * HIDDEN + colw) = o1;
    }
}

// ---------------------------------------------------------------------------
// Launch
// ---------------------------------------------------------------------------
extern "C" void kernel_launch(void* const* d_in, const int* in_sizes, int n_in,
                              void* d_out, int out_size)
{
    const float* x    = (const float*)d_in[0];
    const float* Wqkv = (const float*)d_in[1];
    const float* bqkv = (const float*)d_in[2];
    const float* Wo   = (const float*)d_in[3];
    const float* bo   = (const float*)d_in[4];
    float* out = (float*)d_out;

    float *qkv_p = nullptr, *attn_p = nullptr, *wqkvT_p = nullptr, *woT_p = nullptr;
    cudaGetSymbolAddress((void**)&qkv_p,   g_qkv);
    cudaGetSymbolAddress((void**)&attn_p,  g_attn);
    cudaGetSymbolAddress((void**)&wqkvT_p, g_wqkvT);
    cudaGetSymbolAddress((void**)&woT_p,   g_woT);

    cudaFuncSetAttribute(attn_mma_kernel,
                         cudaFuncAttributeMaxDynamicSharedMemorySize, ATTN_SMEM);

    // 0) Transpose weights
    transpose_kernel<<<dim3(QKVW / 32, HIDDEN / 32), dim3(32, 8)>>>(
        Wqkv, wqkvT_p, HIDDEN, QKVW);
    transpose_kernel<<<dim3(HIDDEN / 32, HIDDEN / 32), dim3(32, 8)>>>(
        Wo, woT_p, HIDDEN, HIDDEN);

    // 1) QKV projection
    gemm_tf32_mma<<<dim3(QKVW / 128, BS / 128), 256>>>(
        x, wqkvT_p, bqkv, qkv_p, QKVW);

    // 2) Attention (bf16x3 + ldmatrix flash attention, BQ=128)
    attn_mma_kernel<<<dim3(SEQ / 128, NHEADS, BATCH), 256, ATTN_SMEM>>>(
        qkv_p, attn_p);

    // 3) Output projection
    gemm_tf32_mma<<<dim3(HIDDEN / 128, BS / 128), 256>>>(
        attn_p, woT_p, bo, out, HIDDEN);
}

// round 11
// speedup vs baseline: 3.1207x; 1.0446x over previous
#include <cuda_runtime.h>
#include <cuda_bf16.h>
#include <cstdint>
#include <math.h>

// Problem constants
#define HIDDEN  1024
#define NHEADS  16
#define HSIZE   64
#define BATCH   2
#define SEQ     2048
#define BS      (BATCH * SEQ)      // 4096 rows
#define QKVW    (3 * HIDDEN)       // 3072
#define GK      1024               // GEMM K (both projections)

// Scratch (allocation-free rule: __device__ globals)
__device__ float g_qkv  [ (size_t)BS * QKVW ];       // [4096][3072]
__device__ float g_attn [ (size_t)BS * HIDDEN ];     // [4096][1024]
__device__ float g_wqkvT[ (size_t)QKVW * HIDDEN ];   // Wqkv^T
__device__ float g_woT  [ (size_t)HIDDEN * HIDDEN ]; // Wo^T
// Pre-split bf16 planes, per-head layout: ((b*16+h)*SEQ+s)*64+d
__device__ __nv_bfloat16 g_Qh[(size_t)BS * HIDDEN];
__device__ __nv_bfloat16 g_Ql[(size_t)BS * HIDDEN];
__device__ __nv_bfloat16 g_Kh[(size_t)BS * HIDDEN];
__device__ __nv_bfloat16 g_Kl[(size_t)BS * HIDDEN];
__device__ __nv_bfloat16 g_Vh[(size_t)BS * HIDDEN];
__device__ __nv_bfloat16 g_Vl[(size_t)BS * HIDDEN];

__device__ __forceinline__ uint32_t f2tf32(float x) {
    uint32_t u;
    asm("cvt.rna.tf32.f32 %0, %1;" : "=r"(u) : "f"(x));
    return u;
}

#define MMA_TF32(c, a, b) \
    asm volatile("mma.sync.aligned.m16n8k8.row.col.f32.tf32.tf32.f32 " \
        "{%0,%1,%2,%3}, {%4,%5,%6,%7}, {%8,%9}, {%0,%1,%2,%3};" \
        : "+f"((c)[0]), "+f"((c)[1]), "+f"((c)[2]), "+f"((c)[3]) \
        : "r"((a)[0]), "r"((a)[1]), "r"((a)[2]), "r"((a)[3]), \
          "r"((b)[0]), "r"((b)[1]))

#define MMA_BF16(c, a, b) \
    asm volatile("mma.sync.aligned.m16n8k16.row.col.f32.bf16.bf16.f32 " \
        "{%0,%1,%2,%3}, {%4,%5,%6,%7}, {%8,%9}, {%0,%1,%2,%3};" \
        : "+f"((c)[0]), "+f"((c)[1]), "+f"((c)[2]), "+f"((c)[3]) \
        : "r"((a)[0]), "r"((a)[1]), "r"((a)[2]), "r"((a)[3]), \
          "r"((b)[0]), "r"((b)[1]))

#define LDMX4(r, a) \
    asm volatile("ldmatrix.sync.aligned.m8n8.x4.shared.b16 {%0,%1,%2,%3}, [%4];" \
        : "=r"((r)[0]), "=r"((r)[1]), "=r"((r)[2]), "=r"((r)[3]) : "r"(a))

#define LDMX4T(r, a) \
    asm volatile("ldmatrix.sync.aligned.m8n8.x4.trans.shared.b16 {%0,%1,%2,%3}, [%4];" \
        : "=r"((r)[0]), "=r"((r)[1]), "=r"((r)[2]), "=r"((r)[3]) : "r"(a))

#define CP16(dst, src) \
    asm volatile("cp.async.cg.shared.global [%0], [%1], 16;" \
        :: "r"(dst), "l"(src))
#define CP_COMMIT() asm volatile("cp.async.commit_group;")
#define CP_WAIT1()  asm volatile("cp.async.wait_group 1;")
#define CP_WAIT0()  asm volatile("cp.async.wait_group 0;")

// Split two floats into {hi bf16x2, lo bf16x2}
__device__ __forceinline__ uint2 split2(float x0, float x1) {
    __nv_bfloat162 h = __floats2bfloat162_rn(x0, x1);
    float h0 = __bfloat162float(h.x);
    float h1 = __bfloat162float(h.y);
    __nv_bfloat162 l = __floats2bfloat162_rn(x0 - h0, x1 - h1);
    uint2 r;
    r.x = *reinterpret_cast<uint32_t*>(&h);
    r.y = *reinterpret_cast<uint32_t*>(&l);
    return r;
}

// ---------------------------------------------------------------------------
// Transpose: out[C][R] = in[R][C]
// ---------------------------------------------------------------------------
__global__ __launch_bounds__(256) void transpose_kernel(
    const float* __restrict__ in, float* __restrict__ out, int R, int C)
{
    __shared__ float t[32][33];
    int x  = blockIdx.x * 32 + threadIdx.x;
    int y0 = blockIdx.y * 32;
    #pragma unroll
    for (int i = threadIdx.y; i < 32; i += 8)
        t[i][threadIdx.x] = in[(size_t)(y0 + i) * C + x];
    __syncthreads();
    int ox  = y0 + threadIdx.x;
    int oy0 = blockIdx.x * 32;
    #pragma unroll
    for (int i = threadIdx.y; i < 32; i += 8)
        out[(size_t)(oy0 + i) * R + ox] = t[threadIdx.x][i];
}

// ---------------------------------------------------------------------------
// tf32 mma.sync GEMM (unchanged): C = A * BT^T + bias
// ---------------------------------------------------------------------------
#define BKC 16
#define SPAD 20

__global__ __launch_bounds__(256) void gemm_tf32_mma(
    const float* __restrict__ A, const float* __restrict__ BT,
    const float* __restrict__ bias, float* __restrict__ C, int N)
{
    __shared__ float As[2][128][SPAD];
    __shared__ float Bs[2][128][SPAD];

    const int tid  = threadIdx.x;
    const int lane = tid & 31;
    const int w    = tid >> 5;
    const int wm   = w & 3;
    const int wn   = w >> 2;
    const int n0   = blockIdx.x * 128;
    const int m0   = blockIdx.y * 128;
    const int g    = lane >> 2;
    const int t    = lane & 3;

    float c[2][8][4];
    #pragma unroll
    for (int mt = 0; mt < 2; mt++)
        #pragma unroll
        for (int nt = 0; nt < 8; nt++)
            #pragma unroll
            for (int i = 0; i < 4; i++) c[mt][nt][i] = 0.f;

    int lr[2], lc[2];
    #pragma unroll
    for (int it = 0; it < 2; it++) {
        int li = tid + it * 256;
        lr[it] = li >> 2;
        lc[it] = (li & 3) * 4;
    }

    float4 ra[2], rb[2];
    #pragma unroll
    for (int it = 0; it < 2; it++) {
        ra[it] = *(const float4*)(A  + (size_t)(m0 + lr[it]) * GK + lc[it]);
        rb[it] = *(const float4*)(BT + (size_t)(n0 + lr[it]) * GK + lc[it]);
    }
    #pragma unroll
    for (int it = 0; it < 2; it++) {
        float* ap = &As[0][lr[it]][lc[it]];
        ap[0] = __uint_as_float(f2tf32(ra[it].x));
        ap[1] = __uint_as_float(f2tf32(ra[it].y));
        ap[2] = __uint_as_float(f2tf32(ra[it].z));
        ap[3] = __uint_as_float(f2tf32(ra[it].w));
        float* bp = &Bs[0][lr[it]][lc[it]];
        bp[0] = __uint_as_float(f2tf32(rb[it].x));
        bp[1] = __uint_as_float(f2tf32(rb[it].y));
        bp[2] = __uint_as_float(f2tf32(rb[it].z));
        bp[3] = __uint_as_float(f2tf32(rb[it].w));
    }
    __syncthreads();

    const int NCHUNK = GK / BKC;
    for (int chunk = 0; chunk < NCHUNK; chunk++) {
        const int buf = chunk & 1;
        if (chunk + 1 < NCHUNK) {
            const int k0 = (chunk + 1) * BKC;
            #pragma unroll
            for (int it = 0; it < 2; it++) {
                ra[it] = *(const float4*)(A  + (size_t)(m0 + lr[it]) * GK + k0 + lc[it]);
                rb[it] = *(const float4*)(BT + (size_t)(n0 + lr[it]) * GK + k0 + lc[it]);
            }
        }
        #pragma unroll
        for (int ks = 0; ks < 2; ks++) {
            const int kb = ks * 8;
            uint32_t af[2][4], bf[8][2];
            #pragma unroll
            for (int mt = 0; mt < 2; mt++) {
                const int rbase = wm * 32 + mt * 16;
                af[mt][0] = __float_as_uint(As[buf][rbase + g    ][kb + t    ]);
                af[mt][1] = __float_as_uint(As[buf][rbase + g + 8][kb + t    ]);
                af[mt][2] = __float_as_uint(As[buf][rbase + g    ][kb + t + 4]);
                af[mt][3] = __float_as_uint(As[buf][rbase + g + 8][kb + t + 4]);
            }
            #pragma unroll
            for (int nt = 0; nt < 8; nt++) {
                const int nbase = wn * 64 + nt * 8;
                bf[nt][0] = __float_as_uint(Bs[buf][nbase + g][kb + t    ]);
                bf[nt][1] = __float_as_uint(Bs[buf][nbase + g][kb + t + 4]);
            }
            #pragma unroll
            for (int mt = 0; mt < 2; mt++)
                #pragma unroll
                for (int nt = 0; nt < 8; nt++)
                    MMA_TF32(c[mt][nt], af[mt], bf[nt]);
        }
        if (chunk + 1 < NCHUNK) {
            const int nb = buf ^ 1;
            #pragma unroll
            for (int it = 0; it < 2; it++) {
                float* ap = &As[nb][lr[it]][lc[it]];
                ap[0] = __uint_as_float(f2tf32(ra[it].x));
                ap[1] = __uint_as_float(f2tf32(ra[it].y));
                ap[2] = __uint_as_float(f2tf32(ra[it].z));
                ap[3] = __uint_as_float(f2tf32(ra[it].w));
                float* bp = &Bs[nb][lr[it]][lc[it]];
                bp[0] = __uint_as_float(f2tf32(rb[it].x));
                bp[1] = __uint_as_float(f2tf32(rb[it].y));
                bp[2] = __uint_as_float(f2tf32(rb[it].z));
                bp[3] = __uint_as_float(f2tf32(rb[it].w));
            }
        }
        __syncthreads();
    }

    #pragma unroll
    for (int mt = 0; mt < 2; mt++) {
        const int row = m0 + wm * 32 + mt * 16 + g;
        #pragma unroll
        for (int nt = 0; nt < 8; nt++) {
            const int col = n0 + wn * 64 + nt * 8 + t * 2;
            float2 bv = *(const float2*)(bias + col);
            float2 o0 = { c[mt][nt][0] + bv.x, c[mt][nt][1] + bv.y };
            float2 o1 = { c[mt][nt][2] + bv.x, c[mt][nt][3] + bv.y };
            *(float2*)(C + (size_t)row * N + col)       = o0;
            *(float2*)(C + (size_t)(row + 8) * N + col) = o1;
        }
    }
}

// ---------------------------------------------------------------------------
// Convert: qkv f32 -> per-head bf16 hi/lo planes (Q pre-scaled by 0.125)
// ---------------------------------------------------------------------------
__global__ __launch_bounds__(256) void convert_kernel(const float* __restrict__ qkv)
{
    const int idx = blockIdx.x * 256 + threadIdx.x;   // over BS*QKVW/4 float4s
    const int row = idx / (QKVW / 4);                 // 0..4095
    const int cc  = (idx - row * (QKVW / 4)) * 4;     // col 0..3068
    const int sec = cc >> 10;                         // 0=q 1=k 2=v
    const int hh  = (cc & 1023) >> 6;
    const int d   = cc & 63;
    const int b   = row >> 11;
    const int s   = row & 2047;

    float4 v = *(const float4*)(qkv + (size_t)row * QKVW + cc);
    if (sec == 0) { v.x *= 0.125f; v.y *= 0.125f; v.z *= 0.125f; v.w *= 0.125f; }
    uint2 s0 = split2(v.x, v.y);
    uint2 s1 = split2(v.z, v.w);

    const size_t dst = ((size_t)(b * NHEADS + hh) * SEQ + s) * HSIZE + d;
    __nv_bfloat16 *ph, *pl;
    if (sec == 0)      { ph = g_Qh; pl = g_Ql; }
    else if (sec == 1) { ph = g_Kh; pl = g_Kl; }
    else               { ph = g_Vh; pl = g_Vl; }
    *(uint2*)(ph + dst) = make_uint2(s0.x, s1.x);
    *(uint2*)(pl + dst) = make_uint2(s0.y, s1.y);
}

// ---------------------------------------------------------------------------
// Flash attention — bf16x3 m16n8k16, pre-split GMEM planes, cp.async double
// buffering, register-direct P fragments. BQ=128, 8 warps.
// SMEM: QH,QL [128][144B]; 2 x (KH,KL,VH,VL)[64][144B] = 110592 B.
// ---------------------------------------------------------------------------
#define RSTR 144
#define OQH 0
#define OQL 18432
#define OKV0 36864
#define KVBUF 36864            // one buffer: KH(9216) KL VH VL
#define ATTN_SMEM 110592

__global__ __launch_bounds__(256, 2) void attn_mma_kernel(
    float* __restrict__ attn_out)
{
    extern __shared__ char sm[];
    const uint32_t smb = (uint32_t)__cvta_generic_to_shared(sm);

    const int tid  = threadIdx.x;
    const int lane = tid & 31;
    const int wm   = tid >> 5;
    const int g    = lane >> 2;
    const int t    = lane & 3;
    const int q0   = blockIdx.x * 128;
    const int h    = blockIdx.y;
    const int b    = blockIdx.z;

    const size_t hb = (size_t)(b * NHEADS + h) * SEQ;   // row base in planes
    const int prow = wm * 16;

    // ldmatrix per-lane addresses
    const uint32_t aRow = (uint32_t)(prow + (lane & 15)) * RSTR + (lane >> 4) * 16;
    const uint32_t qA = smb + OQH + aRow;
    const uint32_t kLane = (uint32_t)((((lane >> 4) & 1) * 8) + (lane & 7)) * RSTR
                         + ((lane >> 3) & 1) * 16;
    const uint32_t vLane = (uint32_t)((((lane >> 3) & 1) * 8) + (lane & 7)) * RSTR
                         + ((lane >> 4) & 1) * 16;

    // cp.async per-thread coordinates: chunk = (row, 16B-slot)
    const int cr = tid >> 3;        // K/V: rows 0..31 (+32 for it=1)
    const int ccol = (tid & 7) * 16;           // byte col in row
    const int csrc = (tid & 7) * 8;            // bf16 col in src row

    // ---- Prologue: Q planes (group 0 with tile 0) ----
    #pragma unroll
    for (int it = 0; it < 4; it++) {
        int r = cr + it * 32;
        CP16(smb + OQH + r * RSTR + ccol, g_Qh + (hb + q0 + r) * HSIZE + csrc);
        CP16(smb + OQL + r * RSTR + ccol, g_Ql + (hb + q0 + r) * HSIZE + csrc);
    }
    // tile 0 K/V
    {
        const uint32_t kvb = smb + OKV0;
        #pragma unroll
        for (int it = 0; it < 2; it++) {
            int r = cr + it * 32;
            size_t src = (hb + r) * HSIZE + csrc;
            uint32_t doff = r * RSTR + ccol;
            CP16(kvb + doff,          g_Kh + src);
            CP16(kvb + 9216 + doff,   g_Kl + src);
            CP16(kvb + 18432 + doff,  g_Vh + src);
            CP16(kvb + 27648 + doff,  g_Vl + src);
        }
    }
    CP_COMMIT();

    float oc[8][4];
    #pragma unroll
    for (int nt = 0; nt < 8; nt++)
        #pragma unroll
        for (int i = 0; i < 4; i++) oc[nt][i] = 0.f;
    float mstat[2] = { -1e30f, -1e30f };
    float lstat[2] = { 0.f, 0.f };

    const int NT = SEQ / 64;   // 32
    for (int tile = 0; tile < NT; tile++) {
        const int buf = tile & 1;
        // Issue next tile into other buffer
        if (tile + 1 < NT) {
            const uint32_t kvb = smb + OKV0 + (buf ^ 1) * KVBUF;
            const int kv1 = (tile + 1) * 64;
            #pragma unroll
            for (int it = 0; it < 2; it++) {
                int r = cr + it * 32;
                size_t src = (hb + kv1 + r) * HSIZE + csrc;
                uint32_t doff = r * RSTR + ccol;
                CP16(kvb + doff,          g_Kh + src);
                CP16(kvb + 9216 + doff,   g_Kl + src);
                CP16(kvb + 18432 + doff,  g_Vh + src);
                CP16(kvb + 27648 + doff,  g_Vl + src);
            }
            CP_COMMIT();
            CP_WAIT1();
        } else {
            CP_WAIT0();
        }
        __syncthreads();

        const uint32_t kvb = smb + OKV0 + buf * KVBUF;
        const uint32_t kA = kvb + kLane;            // KH ; KL at +9216
        const uint32_t vA = kvb + 18432 + vLane;    // VH ; VL at +9216

        // ---- S = (Q*scale) K^T ----
        float sc[8][4];
        #pragma unroll
        for (int nt = 0; nt < 8; nt++)
            #pragma unroll
            for (int i = 0; i < 4; i++) sc[nt][i] = 0.f;

        #pragma unroll
        for (int ks = 0; ks < 4; ks++) {
            uint32_t ah[4], al[4];
            LDMX4(ah, qA + ks * 32);
            LDMX4(al, qA + OQL + ks * 32);
            #pragma unroll
            for (int p = 0; p < 4; p++) {
                uint32_t bh[4], bl[4];
                LDMX4(bh, kA + p * 2304 + ks * 32);
                LDMX4(bl, kA + 9216 + p * 2304 + ks * 32);
                MMA_BF16(sc[2*p],   ah, bh);
                MMA_BF16(sc[2*p],   al, bh);
                MMA_BF16(sc[2*p],   ah, bl);
                MMA_BF16(sc[2*p+1], ah, bh + 2);
                MMA_BF16(sc[2*p+1], al, bh + 2);
                MMA_BF16(sc[2*p+1], ah, bl + 2);
            }
        }

        // ---- online softmax ----
        #pragma unroll
        for (int hf = 0; hf < 2; hf++) {
            const int i0 = hf * 2;
            float rm = -1e30f;
            #pragma unroll
            for (int nt = 0; nt < 8; nt++)
                rm = fmaxf(rm, fmaxf(sc[nt][i0], sc[nt][i0 + 1]));
            rm = fmaxf(rm, __shfl_xor_sync(0xffffffffu, rm, 1));
            rm = fmaxf(rm, __shfl_xor_sync(0xffffffffu, rm, 2));
            float nm   = fmaxf(mstat[hf], rm);
            float corr = __expf(mstat[hf] - nm);
            float rs = 0.f;
            #pragma unroll
            for (int nt = 0; nt < 8; nt++) {
                float p0 = __expf(sc[nt][i0]     - nm);
                float p1 = __expf(sc[nt][i0 + 1] - nm);
                sc[nt][i0] = p0; sc[nt][i0 + 1] = p1;
                rs += p0 + p1;
            }
            rs += __shfl_xor_sync(0xffffffffu, rs, 1);
            rs += __shfl_xor_sync(0xffffffffu, rs, 2);
            lstat[hf] = lstat[hf] * corr + rs;
            mstat[hf] = nm;
            #pragma unroll
            for (int nt = 0; nt < 8; nt++) {
                oc[nt][i0]     *= corr;
                oc[nt][i0 + 1] *= corr;
            }
        }

        // ---- O += P V : P fragments packed directly from accumulators ----
        #pragma unroll
        for (int ks = 0; ks < 4; ks++) {
            uint2 u0 = split2(sc[2*ks][0],   sc[2*ks][1]);
            uint2 u1 = split2(sc[2*ks][2],   sc[2*ks][3]);
            uint2 u2 = split2(sc[2*ks+1][0], sc[2*ks+1][1]);
            uint2 u3 = split2(sc[2*ks+1][2], sc[2*ks+1][3]);
            uint32_t ah[4] = { u0.x, u1.x, u2.x, u3.x };
            uint32_t al[4] = { u0.y, u1.y, u2.y, u3.y };
            #pragma unroll
            for (int p = 0; p < 4; p++) {
                uint32_t bh[4], bl[4];
                LDMX4T(bh, vA + ks * 2304 + p * 32);
                LDMX4T(bl, vA + 9216 + ks * 2304 + p * 32);
                MMA_BF16(oc[2*p],   ah, bh);
                MMA_BF16(oc[2*p],   al, bh);
                MMA_BF16(oc[2*p],   ah, bl);
                MMA_BF16(oc[2*p+1], ah, bh + 2);
                MMA_BF16(oc[2*p+1], al, bh + 2);
                MMA_BF16(oc[2*p+1], ah, bl + 2);
            }
        }
        __syncthreads();   // all warps done with this buffer before overwrite
    }

    // Epilogue: normalize + store
    const float inv0 = 1.0f / lstat[0];
    const float inv1 = 1.0f / lstat[1];
    const size_t r0 = (size_t)(b * SEQ + q0 + prow + g);
    const int col0 = h * HSIZE;
    #pragma unroll
    for (int nt = 0; nt < 8; nt++) {
        const int colw = col0 + nt * 8 + 2 * t;
        float2 o0 = { oc[nt][0] * inv0, oc[nt][1] * inv0 };
        float2 o1 = { oc[nt][2] * inv1, oc[nt][3] * inv1 };
        *(float2*)(attn_out + r0 * HIDDEN + colw)       = o0;
        *(float2*)(attn_out + (r0 + 8) * HIDDEN + colw) = o1;
    }
}

// ---------------------------------------------------------------------------
// Launch
// ---------------------------------------------------------------------------
extern "C" void kernel_launch(void* const* d_in, const int* in_sizes, int n_in,
                              void* d_out, int out_size)
{
    const float* x    = (const float*)d_in[0];
    const float* Wqkv = (const float*)d_in[1];
    const float* bqkv = (const float*)d_in[2];
    const float* Wo   = (const float*)d_in[3];
    const float* bo   = (const float*)d_in[4];
    float* out = (float*)d_out;

    float *qkv_p = nullptr, *attn_p = nullptr, *wqkvT_p = nullptr, *woT_p = nullptr;
    cudaGetSymbolAddress((void**)&qkv_p,   g_qkv);
    cudaGetSymbolAddress((void**)&attn_p,  g_attn);
    cudaGetSymbolAddress((void**)&wqkvT_p, g_wqkvT);
    cudaGetSymbolAddress((void**)&woT_p,   g_woT);

    cudaFuncSetAttribute(attn_mma_kernel,
                         cudaFuncAttributeMaxDynamicSharedMemorySize, ATTN_SMEM);

    // 0) Transpose weights
    transpose_kernel<<<dim3(QKVW / 32, HIDDEN / 32), dim3(32, 8)>>>(
        Wqkv, wqkvT_p, HIDDEN, QKVW);
    transpose_kernel<<<dim3(HIDDEN / 32, HIDDEN / 32), dim3(32, 8)>>>(
        Wo, woT_p, HIDDEN, HIDDEN);

    // 1) QKV projection
    gemm_tf32_mma<<<dim3(QKVW / 128, BS / 128), 256>>>(
        x, wqkvT_p, bqkv, qkv_p, QKVW);

    // 1.5) Split qkv into bf16 hi/lo per-head planes
    convert_kernel<<<(BS * QKVW / 4) / 256, 256>>>(qkv_p);

    // 2) Attention
    attn_mma_kernel<<<dim3(SEQ / 128, NHEADS, BATCH), 256, ATTN_SMEM>>>(attn_p);

    // 3) Output projection
    gemm_tf32_mma<<<dim3(HIDDEN / 128, BS / 128), 256>>>(
        attn_p, woT_p, bo, out, HIDDEN);
}

// round 12
// speedup vs baseline: 3.3895x; 1.0861x over previous
#include <cuda_runtime.h>
#include <cuda_bf16.h>
#include <cstdint>
#include <math.h>

// Problem constants
#define HIDDEN  1024
#define NHEADS  16
#define HSIZE   64
#define BATCH   2
#define SEQ     2048
#define BS      (BATCH * SEQ)      // 4096 rows
#define QKVW    (3 * HIDDEN)       // 3072
#define GK      1024               // GEMM K (both projections)

// Scratch (allocation-free rule: __device__ globals)
__device__ float g_qkv  [ (size_t)BS * QKVW ];       // [4096][3072]
__device__ float g_attn [ (size_t)BS * HIDDEN ];     // [4096][1024] (tf32-rounded)
__device__ float g_xr   [ (size_t)BS * HIDDEN ];     // x, tf32-rounded
__device__ float g_wqkvT[ (size_t)QKVW * HIDDEN ];   // Wqkv^T (tf32-rounded)
__device__ float g_woT  [ (size_t)HIDDEN * HIDDEN ]; // Wo^T   (tf32-rounded)
// Pre-split bf16 planes, per-head layout: ((b*16+h)*SEQ+s)*64+d
__device__ __nv_bfloat16 g_Qh[(size_t)BS * HIDDEN];
__device__ __nv_bfloat16 g_Ql[(size_t)BS * HIDDEN];
__device__ __nv_bfloat16 g_Kh[(size_t)BS * HIDDEN];
__device__ __nv_bfloat16 g_Kl[(size_t)BS * HIDDEN];
__device__ __nv_bfloat16 g_Vh[(size_t)BS * HIDDEN];
__device__ __nv_bfloat16 g_Vl[(size_t)BS * HIDDEN];

__device__ __forceinline__ uint32_t f2tf32(float x) {
    uint32_t u;
    asm("cvt.rna.tf32.f32 %0, %1;" : "=r"(u) : "f"(x));
    return u;
}

#define MMA_TF32(c, a, b) \
    asm volatile("mma.sync.aligned.m16n8k8.row.col.f32.tf32.tf32.f32 " \
        "{%0,%1,%2,%3}, {%4,%5,%6,%7}, {%8,%9}, {%0,%1,%2,%3};" \
        : "+f"((c)[0]), "+f"((c)[1]), "+f"((c)[2]), "+f"((c)[3]) \
        : "r"((a)[0]), "r"((a)[1]), "r"((a)[2]), "r"((a)[3]), \
          "r"((b)[0]), "r"((b)[1]))

#define MMA_BF16(c, a, b) \
    asm volatile("mma.sync.aligned.m16n8k16.row.col.f32.bf16.bf16.f32 " \
        "{%0,%1,%2,%3}, {%4,%5,%6,%7}, {%8,%9}, {%0,%1,%2,%3};" \
        : "+f"((c)[0]), "+f"((c)[1]), "+f"((c)[2]), "+f"((c)[3]) \
        : "r"((a)[0]), "r"((a)[1]), "r"((a)[2]), "r"((a)[3]), \
          "r"((b)[0]), "r"((b)[1]))

#define LDMX4(r, a) \
    asm volatile("ldmatrix.sync.aligned.m8n8.x4.shared.b16 {%0,%1,%2,%3}, [%4];" \
        : "=r"((r)[0]), "=r"((r)[1]), "=r"((r)[2]), "=r"((r)[3]) : "r"(a))

#define LDMX4T(r, a) \
    asm volatile("ldmatrix.sync.aligned.m8n8.x4.trans.shared.b16 {%0,%1,%2,%3}, [%4];" \
        : "=r"((r)[0]), "=r"((r)[1]), "=r"((r)[2]), "=r"((r)[3]) : "r"(a))

#define CP16(dst, src) \
    asm volatile("cp.async.cg.shared.global [%0], [%1], 16;" \
        :: "r"(dst), "l"(src))
#define CP_COMMIT() asm volatile("cp.async.commit_group;")
#define CP_WAIT1()  asm volatile("cp.async.wait_group 1;")
#define CP_WAIT0()  asm volatile("cp.async.wait_group 0;")

// Split two floats into {hi bf16x2, lo bf16x2}
__device__ __forceinline__ uint2 split2(float x0, float x1) {
    __nv_bfloat162 h = __floats2bfloat162_rn(x0, x1);
    float h0 = __bfloat162float(h.x);
    float h1 = __bfloat162float(h.y);
    __nv_bfloat162 l = __floats2bfloat162_rn(x0 - h0, x1 - h1);
    uint2 r;
    r.x = *reinterpret_cast<uint32_t*>(&h);
    r.y = *reinterpret_cast<uint32_t*>(&l);
    return r;
}

// ---------------------------------------------------------------------------
// Round: out = tf32(in)    (element-wise, float4)
// ---------------------------------------------------------------------------
__global__ __launch_bounds__(256) void round_kernel(
    const float* __restrict__ in, float* __restrict__ out)
{
    int i = (blockIdx.x * 256 + threadIdx.x) * 4;
    float4 v = *(const float4*)(in + i);
    float4 o;
    o.x = __uint_as_float(f2tf32(v.x));
    o.y = __uint_as_float(f2tf32(v.y));
    o.z = __uint_as_float(f2tf32(v.z));
    o.w = __uint_as_float(f2tf32(v.w));
    *(float4*)(out + i) = o;
}

// ---------------------------------------------------------------------------
// Transpose + tf32 round: out[C][R] = tf32(in[R][C])
// ---------------------------------------------------------------------------
__global__ __launch_bounds__(256) void transpose_kernel(
    const float* __restrict__ in, float* __restrict__ out, int R, int C)
{
    __shared__ float t[32][33];
    int x  = blockIdx.x * 32 + threadIdx.x;
    int y0 = blockIdx.y * 32;
    #pragma unroll
    for (int i = threadIdx.y; i < 32; i += 8)
        t[i][threadIdx.x] = in[(size_t)(y0 + i) * C + x];
    __syncthreads();
    int ox  = y0 + threadIdx.x;
    int oy0 = blockIdx.x * 32;
    #pragma unroll
    for (int i = threadIdx.y; i < 32; i += 8)
        out[(size_t)(oy0 + i) * R + ox] =
            __uint_as_float(f2tf32(t[threadIdx.x][i]));
}

// ---------------------------------------------------------------------------
// tf32 GEMM v2: C[M,N] = A[M,K] * BT[N,K]^T + bias[N]
// Inputs pre-rounded to tf32. ldmatrix fragments, cp.async double buffering.
// CTA 128x128, 8 warps (4m x 2n), warp tile 32x64. K-chunk 16.
// SMEM rows: 20 floats (80 B) -> ldmatrix banks (20r)%32 conflict-free.
// ---------------------------------------------------------------------------
#define GSTR 20                       // floats per smem row
#define GROW 80                       // bytes per smem row
#define ABUF 10240                    // one A (or B) buffer: 128*80
#define OB   20480                    // B base (A[2] first)

__global__ __launch_bounds__(256) void gemm_tf32_mma(
    const float* __restrict__ A, const float* __restrict__ BT,
    const float* __restrict__ bias, float* __restrict__ C, int N)
{
    __shared__ float smem_f[2 * 128 * GSTR * 2];   // A[2] then B[2]
    const uint32_t smb = (uint32_t)__cvta_generic_to_shared(smem_f);

    const int tid  = threadIdx.x;
    const int lane = tid & 31;
    const int w    = tid >> 5;
    const int wm   = w & 3;
    const int wn   = w >> 2;
    const int n0   = blockIdx.x * 128;
    const int m0   = blockIdx.y * 128;
    const int g    = lane >> 2;
    const int t    = lane & 3;

    float c[2][8][4];
    #pragma unroll
    for (int mt = 0; mt < 2; mt++)
        #pragma unroll
        for (int nt = 0; nt < 8; nt++)
            #pragma unroll
            for (int i = 0; i < 4; i++) c[mt][nt][i] = 0.f;

    // cp.async coords: 512 16B-chunks per tile, 2 per thread
    const int cra = tid >> 2;          // row 0..63 (+64)
    const int cca = (tid & 3) * 16;    // byte col

    // ldmatrix per-lane addresses
    // A: lanes 0-15 -> rows rbase+0..15 @ +0B; lanes 16-31 -> same rows @ +16B
    const uint32_t aA = smb + (uint32_t)(wm * 32 + (lane & 15)) * GROW
                      + (lane >> 4) * 16;
    // B: pair p covers n-rows p*16..+15: lanes0-7 r0-7@0,8-15 r0-7@16,
    //    16-23 r8-15@0, 24-31 r8-15@16
    const uint32_t bB = smb + OB
                      + (uint32_t)(wn * 64 + ((lane >> 4) & 1) * 8 + (lane & 7)) * GROW
                      + ((lane >> 3) & 1) * 16;

    // Prologue: chunk 0 into buf 0
    #pragma unroll
    for (int it = 0; it < 2; it++) {
        int r = cra + it * 64;
        CP16(smb + r * GROW + cca,      A  + (size_t)(m0 + r) * GK + (cca >> 2));
        CP16(smb + OB + r * GROW + cca, BT + (size_t)(n0 + r) * GK + (cca >> 2));
    }
    CP_COMMIT();

    const int NCHUNK = GK / 16;   // 64
    for (int chunk = 0; chunk < NCHUNK; chunk++) {
        const int buf = chunk & 1;
        if (chunk + 1 < NCHUNK) {
            const int k0 = (chunk + 1) * 16;
            const uint32_t db = (buf ^ 1) * ABUF;
            #pragma unroll
            for (int it = 0; it < 2; it++) {
                int r = cra + it * 64;
                CP16(smb + db + r * GROW + cca,
                     A  + (size_t)(m0 + r) * GK + k0 + (cca >> 2));
                CP16(smb + OB + db + r * GROW + cca,
                     BT + (size_t)(n0 + r) * GK + k0 + (cca >> 2));
            }
            CP_COMMIT();
            CP_WAIT1();
        } else {
            CP_WAIT0();
        }
        __syncthreads();

        const uint32_t ab = buf * ABUF;
        #pragma unroll
        for (int ks = 0; ks < 2; ks++) {
            uint32_t af[2][4], bf[8][4];
            #pragma unroll
            for (int mt = 0; mt < 2; mt++)
                LDMX4(af[mt], aA + ab + mt * 16 * GROW + ks * 32);
            #pragma unroll
            for (int p = 0; p < 4; p++)
                LDMX4(bf[2 * p], bB + ab + p * 16 * GROW + ks * 32);
            // bf[2p] = {B[2p][0], B[2p][1], B[2p+1][0], B[2p+1][1]}
            #pragma unroll
            for (int mt = 0; mt < 2; mt++)
                #pragma unroll
                for (int p = 0; p < 4; p++) {
                    MMA_TF32(c[mt][2 * p],     af[mt], &bf[2 * p][0]);
                    MMA_TF32(c[mt][2 * p + 1], af[mt], &bf[2 * p][2]);
                }
        }
        __syncthreads();
    }

    #pragma unroll
    for (int mt = 0; mt < 2; mt++) {
        const int row = m0 + wm * 32 + mt * 16 + g;
        #pragma unroll
        for (int nt = 0; nt < 8; nt++) {
            const int col = n0 + wn * 64 + nt * 8 + t * 2;
            float2 bv = *(const float2*)(bias + col);
            float2 o0 = { c[mt][nt][0] + bv.x, c[mt][nt][1] + bv.y };
            float2 o1 = { c[mt][nt][2] + bv.x, c[mt][nt][3] + bv.y };
            *(float2*)(C + (size_t)row * N + col)       = o0;
            *(float2*)(C + (size_t)(row + 8) * N + col) = o1;
        }
    }
}

// ---------------------------------------------------------------------------
// Convert: qkv f32 -> per-head bf16 hi/lo planes (Q pre-scaled by 0.125)
// ---------------------------------------------------------------------------
__global__ __launch_bounds__(256) void convert_kernel(const float* __restrict__ qkv)
{
    const int idx = blockIdx.x * 256 + threadIdx.x;
    const int row = idx / (QKVW / 4);
    const int cc  = (idx - row * (QKVW / 4)) * 4;
    const int sec = cc >> 10;
    const int hh  = (cc & 1023) >> 6;
    const int d   = cc & 63;
    const int b   = row >> 11;
    const int s   = row & 2047;

    float4 v = *(const float4*)(qkv + (size_t)row * QKVW + cc);
    if (sec == 0) { v.x *= 0.125f; v.y *= 0.125f; v.z *= 0.125f; v.w *= 0.125f; }
    uint2 s0 = split2(v.x, v.y);
    uint2 s1 = split2(v.z, v.w);

    const size_t dst = ((size_t)(b * NHEADS + hh) * SEQ + s) * HSIZE + d;
    __nv_bfloat16 *ph, *pl;
    if (sec == 0)      { ph = g_Qh; pl = g_Ql; }
    else if (sec == 1) { ph = g_Kh; pl = g_Kl; }
    else               { ph = g_Vh; pl = g_Vl; }
    *(uint2*)(ph + dst) = make_uint2(s0.x, s1.x);
    *(uint2*)(pl + dst) = make_uint2(s0.y, s1.y);
}

// ---------------------------------------------------------------------------
// Flash attention — bf16x3 m16n8k16, pre-split GMEM planes, cp.async double
// buffering, register-direct P fragments. BQ=128, 8 warps.
// ---------------------------------------------------------------------------
#define RSTR 144
#define OQH 0
#define OQL 18432
#define OKV0 36864
#define KVBUF 36864
#define ATTN_SMEM 110592

__global__ __launch_bounds__(256, 2) void attn_mma_kernel(
    float* __restrict__ attn_out)
{
    extern __shared__ char sm[];
    const uint32_t smb = (uint32_t)__cvta_generic_to_shared(sm);

    const int tid  = threadIdx.x;
    const int lane = tid & 31;
    const int wm   = tid >> 5;
    const int g    = lane >> 2;
    const int t    = lane & 3;
    const int q0   = blockIdx.x * 128;
    const int h    = blockIdx.y;
    const int b    = blockIdx.z;

    const size_t hb = (size_t)(b * NHEADS + h) * SEQ;
    const int prow = wm * 16;

    const uint32_t aRow = (uint32_t)(prow + (lane & 15)) * RSTR + (lane >> 4) * 16;
    const uint32_t qA = smb + OQH + aRow;
    const uint32_t kLane = (uint32_t)((((lane >> 4) & 1) * 8) + (lane & 7)) * RSTR
                         + ((lane >> 3) & 1) * 16;
    const uint32_t vLane = (uint32_t)((((lane >> 3) & 1) * 8) + (lane & 7)) * RSTR
                         + ((lane >> 4) & 1) * 16;

    const int cr = tid >> 3;
    const int ccol = (tid & 7) * 16;
    const int csrc = (tid & 7) * 8;

    #pragma unroll
    for (int it = 0; it < 4; it++) {
        int r = cr + it * 32;
        CP16(smb + OQH + r * RSTR + ccol, g_Qh + (hb + q0 + r) * HSIZE + csrc);
        CP16(smb + OQL + r * RSTR + ccol, g_Ql + (hb + q0 + r) * HSIZE + csrc);
    }
    {
        const uint32_t kvb = smb + OKV0;
        #pragma unroll
        for (int it = 0; it < 2; it++) {
            int r = cr + it * 32;
            size_t src = (hb + r) * HSIZE + csrc;
            uint32_t doff = r * RSTR + ccol;
            CP16(kvb + doff,          g_Kh + src);
            CP16(kvb + 9216 + doff,   g_Kl + src);
            CP16(kvb + 18432 + doff,  g_Vh + src);
            CP16(kvb + 27648 + doff,  g_Vl + src);
        }
    }
    CP_COMMIT();

    float oc[8][4];
    #pragma unroll
    for (int nt = 0; nt < 8; nt++)
        #pragma unroll
        for (int i = 0; i < 4; i++) oc[nt][i] = 0.f;
    float mstat[2] = { -1e30f, -1e30f };
    float lstat[2] = { 0.f, 0.f };

    const int NT = SEQ / 64;
    for (int tile = 0; tile < NT; tile++) {
        const int buf = tile & 1;
        if (tile + 1 < NT) {
            const uint32_t kvb = smb + OKV0 + (buf ^ 1) * KVBUF;
            const int kv1 = (tile + 1) * 64;
            #pragma unroll
            for (int it = 0; it < 2; it++) {
                int r = cr + it * 32;
                size_t src = (hb + kv1 + r) * HSIZE + csrc;
                uint32_t doff = r * RSTR + ccol;
                CP16(kvb + doff,          g_Kh + src);
                CP16(kvb + 9216 + doff,   g_Kl + src);
                CP16(kvb + 18432 + doff,  g_Vh + src);
                CP16(kvb + 27648 + doff,  g_Vl + src);
            }
            CP_COMMIT();
            CP_WAIT1();
        } else {
            CP_WAIT0();
        }
        __syncthreads();

        const uint32_t kvb = smb + OKV0 + buf * KVBUF;
        const uint32_t kA = kvb + kLane;
        const uint32_t vA = kvb + 18432 + vLane;

        float sc[8][4];
        #pragma unroll
        for (int nt = 0; nt < 8; nt++)
            #pragma unroll
            for (int i = 0; i < 4; i++) sc[nt][i] = 0.f;

        #pragma unroll
        for (int ks = 0; ks < 4; ks++) {
            uint32_t ah[4], al[4];
            LDMX4(ah, qA + ks * 32);
            LDMX4(al, qA + OQL + ks * 32);
            #pragma unroll
            for (int p = 0; p < 4; p++) {
                uint32_t bh[4], bl[4];
                LDMX4(bh, kA + p * 2304 + ks * 32);
                LDMX4(bl, kA + 9216 + p * 2304 + ks * 32);
                MMA_BF16(sc[2*p],   ah, bh);
                MMA_BF16(sc[2*p],   al, bh);
                MMA_BF16(sc[2*p],   ah, bl);
                MMA_BF16(sc[2*p+1], ah, bh + 2);
                MMA_BF16(sc[2*p+1], al, bh + 2);
                MMA_BF16(sc[2*p+1], ah, bl + 2);
            }
        }

        #pragma unroll
        for (int hf = 0; hf < 2; hf++) {
            const int i0 = hf * 2;
            float rm = -1e30f;
            #pragma unroll
            for (int nt = 0; nt < 8; nt++)
                rm = fmaxf(rm, fmaxf(sc[nt][i0], sc[nt][i0 + 1]));
            rm = fmaxf(rm, __shfl_xor_sync(0xffffffffu, rm, 1));
            rm = fmaxf(rm, __shfl_xor_sync(0xffffffffu, rm, 2));
            float nm   = fmaxf(mstat[hf], rm);
            float corr = __expf(mstat[hf] - nm);
            float rs = 0.f;
            #pragma unroll
            for (int nt = 0; nt < 8; nt++) {
                float p0 = __expf(sc[nt][i0]     - nm);
                float p1 = __expf(sc[nt][i0 + 1] - nm);
                sc[nt][i0] = p0; sc[nt][i0 + 1] = p1;
                rs += p0 + p1;
            }
            rs += __shfl_xor_sync(0xffffffffu, rs, 1);
            rs += __shfl_xor_sync(0xffffffffu, rs, 2);
            lstat[hf] = lstat[hf] * corr + rs;
            mstat[hf] = nm;
            #pragma unroll
            for (int nt = 0; nt < 8; nt++) {
                oc[nt][i0]     *= corr;
                oc[nt][i0 + 1] *= corr;
            }
        }

        #pragma unroll
        for (int ks = 0; ks < 4; ks++) {
            uint2 u0 = split2(sc[2*ks][0],   sc[2*ks][1]);
            uint2 u1 = split2(sc[2*ks][2],   sc[2*ks][3]);
            uint2 u2 = split2(sc[2*ks+1][0], sc[2*ks+1][1]);
            uint2 u3 = split2(sc[2*ks+1][2], sc[2*ks+1][3]);
            uint32_t ah[4] = { u0.x, u1.x, u2.x, u3.x };
            uint32_t al[4] = { u0.y, u1.y, u2.y, u3.y };
            #pragma unroll
            for (int p = 0; p < 4; p++) {
                uint32_t bh[4], bl[4];
                LDMX4T(bh, vA + ks * 2304 + p * 32);
                LDMX4T(bl, vA + 9216 + ks * 2304 + p * 32);
                MMA_BF16(oc[2*p],   ah, bh);
                MMA_BF16(oc[2*p],   al, bh);
                MMA_BF16(oc[2*p],   ah, bl);
                MMA_BF16(oc[2*p+1], ah, bh + 2);
                MMA_BF16(oc[2*p+1], al, bh + 2);
                MMA_BF16(oc[2*p+1], ah, bl + 2);
            }
        }
        __syncthreads();
    }

    // Epilogue: normalize + store, tf32-rounded (O-proj consumes it raw)
    const float inv0 = 1.0f / lstat[0];
    const float inv1 = 1.0f / lstat[1];
    const size_t r0 = (size_t)(b * SEQ + q0 + prow + g);
    const int col0 = h * HSIZE;
    #pragma unroll
    for (int nt = 0; nt < 8; nt++) {
        const int colw = col0 + nt * 8 + 2 * t;
        float2 o0 = { __uint_as_float(f2tf32(oc[nt][0] * inv0)),
                      __uint_as_float(f2tf32(oc[nt][1] * inv0)) };
        float2 o1 = { __uint_as_float(f2tf32(oc[nt][2] * inv1)),
                      __uint_as_float(f2tf32(oc[nt][3] * inv1)) };
        *(float2*)(attn_out + r0 * HIDDEN + colw)       = o0;
        *(float2*)(attn_out + (r0 + 8) * HIDDEN + colw) = o1;
    }
}

// ---------------------------------------------------------------------------
// Launch
// ---------------------------------------------------------------------------
extern "C" void kernel_launch(void* const* d_in, const int* in_sizes, int n_in,
                              void* d_out, int out_size)
{
    const float* x    = (const float*)d_in[0];
    const float* Wqkv = (const float*)d_in[1];
    const float* bqkv = (const float*)d_in[2];
    const float* Wo   = (const float*)d_in[3];
    const float* bo   = (const float*)d_in[4];
    float* out = (float*)d_out;

    float *qkv_p = nullptr, *attn_p = nullptr, *xr_p = nullptr,
          *wqkvT_p = nullptr, *woT_p = nullptr;
    cudaGetSymbolAddress((void**)&qkv_p,   g_qkv);
    cudaGetSymbolAddress((void**)&attn_p,  g_attn);
    cudaGetSymbolAddress((void**)&xr_p,    g_xr);
    cudaGetSymbolAddress((void**)&wqkvT_p, g_wqkvT);
    cudaGetSymbolAddress((void**)&woT_p,   g_woT);

    cudaFuncSetAttribute(attn_mma_kernel,
                         cudaFuncAttributeMaxDynamicSharedMemorySize, ATTN_SMEM);

    // 0) Pre-round x; transpose+round weights
    round_kernel<<<(BS * HIDDEN / 4) / 256, 256>>>(x, xr_p);
    transpose_kernel<<<dim3(QKVW / 32, HIDDEN / 32), dim3(32, 8)>>>(
        Wqkv, wqkvT_p, HIDDEN, QKVW);
    transpose_kernel<<<dim3(HIDDEN / 32, HIDDEN / 32), dim3(32, 8)>>>(
        Wo, woT_p, HIDDEN, HIDDEN);

    // 1) QKV projection
    gemm_tf32_mma<<<dim3(QKVW / 128, BS / 128), 256>>>(
        xr_p, wqkvT_p, bqkv, qkv_p, QKVW);

    // 1.5) Split qkv into bf16 hi/lo per-head planes
    convert_kernel<<<(BS * QKVW / 4) / 256, 256>>>(qkv_p);

    // 2) Attention
    attn_mma_kernel<<<dim3(SEQ / 128, NHEADS, BATCH), 256, ATTN_SMEM>>>(attn_p);

    // 3) Output projection (g_attn already tf32-rounded)
    gemm_tf32_mma<<<dim3(HIDDEN / 128, BS / 128), 256>>>(
        attn_p, woT_p, bo, out, HIDDEN);
}

// round 13
// speedup vs baseline: 3.4212x; 1.0094x over previous
#include <cuda_runtime.h>
#include <cuda_bf16.h>
#include <cstdint>
#include <math.h>

// Problem constants
#define HIDDEN  1024
#define NHEADS  16
#define HSIZE   64
#define BATCH   2
#define SEQ     2048
#define BS      (BATCH * SEQ)      // 4096 rows
#define QKVW    (3 * HIDDEN)       // 3072
#define GK      1024               // GEMM K (both projections)

// Scratch (allocation-free rule: __device__ globals)
__device__ float g_qkv  [ (size_t)BS * QKVW ];       // [4096][3072]
__device__ float g_attn [ (size_t)BS * HIDDEN ];     // [4096][1024] (tf32-rounded)
__device__ float g_xr   [ (size_t)BS * HIDDEN ];     // x, tf32-rounded
__device__ float g_wqkvT[ (size_t)QKVW * HIDDEN ];   // Wqkv^T (tf32-rounded)
__device__ float g_woT  [ (size_t)HIDDEN * HIDDEN ]; // Wo^T   (tf32-rounded)
// Pre-split bf16 planes, per-head layout: ((b*16+h)*SEQ+s)*64+d
__device__ __nv_bfloat16 g_Qh[(size_t)BS * HIDDEN];
__device__ __nv_bfloat16 g_Ql[(size_t)BS * HIDDEN];
__device__ __nv_bfloat16 g_Kh[(size_t)BS * HIDDEN];
__device__ __nv_bfloat16 g_Kl[(size_t)BS * HIDDEN];
__device__ __nv_bfloat16 g_Vh[(size_t)BS * HIDDEN];
__device__ __nv_bfloat16 g_Vl[(size_t)BS * HIDDEN];

__device__ __forceinline__ uint32_t f2tf32(float x) {
    uint32_t u;
    asm("cvt.rna.tf32.f32 %0, %1;" : "=r"(u) : "f"(x));
    return u;
}

#define MMA_TF32(c, a, b) \
    asm volatile("mma.sync.aligned.m16n8k8.row.col.f32.tf32.tf32.f32 " \
        "{%0,%1,%2,%3}, {%4,%5,%6,%7}, {%8,%9}, {%0,%1,%2,%3};" \
        : "+f"((c)[0]), "+f"((c)[1]), "+f"((c)[2]), "+f"((c)[3]) \
        : "r"((a)[0]), "r"((a)[1]), "r"((a)[2]), "r"((a)[3]), \
          "r"((b)[0]), "r"((b)[1]))

#define MMA_BF16(c, a, b) \
    asm volatile("mma.sync.aligned.m16n8k16.row.col.f32.bf16.bf16.f32 " \
        "{%0,%1,%2,%3}, {%4,%5,%6,%7}, {%8,%9}, {%0,%1,%2,%3};" \
        : "+f"((c)[0]), "+f"((c)[1]), "+f"((c)[2]), "+f"((c)[3]) \
        : "r"((a)[0]), "r"((a)[1]), "r"((a)[2]), "r"((a)[3]), \
          "r"((b)[0]), "r"((b)[1]))

#define LDMX4(r, a) \
    asm volatile("ldmatrix.sync.aligned.m8n8.x4.shared.b16 {%0,%1,%2,%3}, [%4];" \
        : "=r"((r)[0]), "=r"((r)[1]), "=r"((r)[2]), "=r"((r)[3]) : "r"(a))

#define LDMX4T(r, a) \
    asm volatile("ldmatrix.sync.aligned.m8n8.x4.trans.shared.b16 {%0,%1,%2,%3}, [%4];" \
        : "=r"((r)[0]), "=r"((r)[1]), "=r"((r)[2]), "=r"((r)[3]) : "r"(a))

#define CP16(dst, src) \
    asm volatile("cp.async.cg.shared.global [%0], [%1], 16;" \
        :: "r"(dst), "l"(src))
#define CP_COMMIT() asm volatile("cp.async.commit_group;")
#define CP_WAIT2()  asm volatile("cp.async.wait_group 2;")
#define CP_WAIT1()  asm volatile("cp.async.wait_group 1;")
#define CP_WAIT0()  asm volatile("cp.async.wait_group 0;")

// Split two floats into {hi bf16x2, lo bf16x2}
__device__ __forceinline__ uint2 split2(float x0, float x1) {
    __nv_bfloat162 h = __floats2bfloat162_rn(x0, x1);
    float h0 = __bfloat162float(h.x);
    float h1 = __bfloat162float(h.y);
    __nv_bfloat162 l = __floats2bfloat162_rn(x0 - h0, x1 - h1);
    uint2 r;
    r.x = *reinterpret_cast<uint32_t*>(&h);
    r.y = *reinterpret_cast<uint32_t*>(&l);
    return r;
}

// ---------------------------------------------------------------------------
// Round: out = tf32(in)
// ---------------------------------------------------------------------------
__global__ __launch_bounds__(256) void round_kernel(
    const float* __restrict__ in, float* __restrict__ out)
{
    int i = (blockIdx.x * 256 + threadIdx.x) * 4;
    float4 v = *(const float4*)(in + i);
    float4 o;
    o.x = __uint_as_float(f2tf32(v.x));
    o.y = __uint_as_float(f2tf32(v.y));
    o.z = __uint_as_float(f2tf32(v.z));
    o.w = __uint_as_float(f2tf32(v.w));
    *(float4*)(out + i) = o;
}

// ---------------------------------------------------------------------------
// Transpose + tf32 round: out[C][R] = tf32(in[R][C])
// ---------------------------------------------------------------------------
__global__ __launch_bounds__(256) void transpose_kernel(
    const float* __restrict__ in, float* __restrict__ out, int R, int C)
{
    __shared__ float t[32][33];
    int x  = blockIdx.x * 32 + threadIdx.x;
    int y0 = blockIdx.y * 32;
    #pragma unroll
    for (int i = threadIdx.y; i < 32; i += 8)
        t[i][threadIdx.x] = in[(size_t)(y0 + i) * C + x];
    __syncthreads();
    int ox  = y0 + threadIdx.x;
    int oy0 = blockIdx.x * 32;
    #pragma unroll
    for (int i = threadIdx.y; i < 32; i += 8)
        out[(size_t)(oy0 + i) * R + ox] =
            __uint_as_float(f2tf32(t[threadIdx.x][i]));
}

// ---------------------------------------------------------------------------
// tf32 GEMM v3: 4-stage cp.async pipeline. C = A * BT^T + bias.
// CTA 128x128, 8 warps (4m x 2n), warp tile 32x64. K-chunk 16.
// SMEM rows: 20 floats (80 B); A stages then B stages; 81920 B total.
// ---------------------------------------------------------------------------
#define GSTR 20
#define GROW 80
#define ABUF 10240                    // one stage of one operand: 128*80
#define OB   40960                    // B base (A[4] first)
#define GEMM_SMEM 81920

__global__ __launch_bounds__(256) void gemm_tf32_mma(
    const float* __restrict__ A, const float* __restrict__ BT,
    const float* __restrict__ bias, float* __restrict__ C, int N)
{
    extern __shared__ float smem_f[];
    const uint32_t smb = (uint32_t)__cvta_generic_to_shared(smem_f);

    const int tid  = threadIdx.x;
    const int lane = tid & 31;
    const int w    = tid >> 5;
    const int wm   = w & 3;
    const int wn   = w >> 2;
    const int n0   = blockIdx.x * 128;
    const int m0   = blockIdx.y * 128;
    const int g    = lane >> 2;
    const int t    = lane & 3;

    float c[2][8][4];
    #pragma unroll
    for (int mt = 0; mt < 2; mt++)
        #pragma unroll
        for (int nt = 0; nt < 8; nt++)
            #pragma unroll
            for (int i = 0; i < 4; i++) c[mt][nt][i] = 0.f;

    // cp.async coords: 2 x 16B per thread per operand per chunk
    const int cra = tid >> 2;          // row 0..63 (+64)
    const int cca = (tid & 3) * 16;    // byte col (k offset)

    // ldmatrix per-lane addresses
    const uint32_t aA = smb + (uint32_t)(wm * 32 + (lane & 15)) * GROW
                      + (lane >> 4) * 16;
    const uint32_t bB = smb + OB
                      + (uint32_t)(wn * 64 + ((lane >> 4) & 1) * 8 + (lane & 7)) * GROW
                      + ((lane >> 3) & 1) * 16;

    const int NCHUNK = GK / 16;   // 64

    // Prologue: issue chunks 0..2 into stages 0..2
    #pragma unroll
    for (int s = 0; s < 3; s++) {
        const uint32_t db = s * ABUF;
        const int k0 = s * 16;
        #pragma unroll
        for (int it = 0; it < 2; it++) {
            int r = cra + it * 64;
            CP16(smb + db + r * GROW + cca,
                 A  + (size_t)(m0 + r) * GK + k0 + (cca >> 2));
            CP16(smb + OB + db + r * GROW + cca,
                 BT + (size_t)(n0 + r) * GK + k0 + (cca >> 2));
        }
        CP_COMMIT();
    }

    for (int chunk = 0; chunk < NCHUNK; chunk++) {
        const uint32_t ab = (chunk & 3) * ABUF;

        // Wait until this chunk's stage has landed (tail-aware)
        if (chunk + 2 < NCHUNK)      { CP_WAIT2(); }
        else if (chunk + 2 == NCHUNK){ CP_WAIT1(); }
        else                         { CP_WAIT0(); }
        __syncthreads();   // also retires last iteration's reads of stage (chunk+3)&3

        // Issue chunk+3 into its stage (the one just retired)
        if (chunk + 3 < NCHUNK) {
            const int k0 = (chunk + 3) * 16;
            const uint32_t db = ((chunk + 3) & 3) * ABUF;
            #pragma unroll
            for (int it = 0; it < 2; it++) {
                int r = cra + it * 64;
                CP16(smb + db + r * GROW + cca,
                     A  + (size_t)(m0 + r) * GK + k0 + (cca >> 2));
                CP16(smb + OB + db + r * GROW + cca,
                     BT + (size_t)(n0 + r) * GK + k0 + (cca >> 2));
            }
            CP_COMMIT();
        }

        #pragma unroll
        for (int ks = 0; ks < 2; ks++) {
            uint32_t af[2][4], bf[8][4];
            #pragma unroll
            for (int mt = 0; mt < 2; mt++)
                LDMX4(af[mt], aA + ab + mt * 16 * GROW + ks * 32);
            #pragma unroll
            for (int p = 0; p < 4; p++)
                LDMX4(bf[2 * p], bB + ab + p * 16 * GROW + ks * 32);
            #pragma unroll
            for (int mt = 0; mt < 2; mt++)
                #pragma unroll
                for (int p = 0; p < 4; p++) {
                    MMA_TF32(c[mt][2 * p],     af[mt], &bf[2 * p][0]);
                    MMA_TF32(c[mt][2 * p + 1], af[mt], &bf[2 * p][2]);
                }
        }
    }

    #pragma unroll
    for (int mt = 0; mt < 2; mt++) {
        const int row = m0 + wm * 32 + mt * 16 + g;
        #pragma unroll
        for (int nt = 0; nt < 8; nt++) {
            const int col = n0 + wn * 64 + nt * 8 + t * 2;
            float2 bv = *(const float2*)(bias + col);
            float2 o0 = { c[mt][nt][0] + bv.x, c[mt][nt][1] + bv.y };
            float2 o1 = { c[mt][nt][2] + bv.x, c[mt][nt][3] + bv.y };
            *(float2*)(C + (size_t)row * N + col)       = o0;
            *(float2*)(C + (size_t)(row + 8) * N + col) = o1;
        }
    }
}

// ---------------------------------------------------------------------------
// Convert: qkv f32 -> per-head bf16 hi/lo planes (Q pre-scaled by 0.125)
// ---------------------------------------------------------------------------
__global__ __launch_bounds__(256) void convert_kernel(const float* __restrict__ qkv)
{
    const int idx = blockIdx.x * 256 + threadIdx.x;
    const int row = idx / (QKVW / 4);
    const int cc  = (idx - row * (QKVW / 4)) * 4;
    const int sec = cc >> 10;
    const int hh  = (cc & 1023) >> 6;
    const int d   = cc & 63;
    const int b   = row >> 11;
    const int s   = row & 2047;

    float4 v = *(const float4*)(qkv + (size_t)row * QKVW + cc);
    if (sec == 0) { v.x *= 0.125f; v.y *= 0.125f; v.z *= 0.125f; v.w *= 0.125f; }
    uint2 s0 = split2(v.x, v.y);
    uint2 s1 = split2(v.z, v.w);

    const size_t dst = ((size_t)(b * NHEADS + hh) * SEQ + s) * HSIZE + d;
    __nv_bfloat16 *ph, *pl;
    if (sec == 0)      { ph = g_Qh; pl = g_Ql; }
    else if (sec == 1) { ph = g_Kh; pl = g_Kl; }
    else               { ph = g_Vh; pl = g_Vl; }
    *(uint2*)(ph + dst) = make_uint2(s0.x, s1.x);
    *(uint2*)(pl + dst) = make_uint2(s0.y, s1.y);
}

// ---------------------------------------------------------------------------
// Flash attention — bf16x3 m16n8k16, pre-split GMEM planes, cp.async double
// buffering, register-direct P fragments. BQ=128, 8 warps. (unchanged)
// ---------------------------------------------------------------------------
#define RSTR 144
#define OQH 0
#define OQL 18432
#define OKV0 36864
#define KVBUF 36864
#define ATTN_SMEM 110592

__global__ __launch_bounds__(256, 2) void attn_mma_kernel(
    float* __restrict__ attn_out)
{
    extern __shared__ char sm[];
    const uint32_t smb = (uint32_t)__cvta_generic_to_shared(sm);

    const int tid  = threadIdx.x;
    const int lane = tid & 31;
    const int wm   = tid >> 5;
    const int g    = lane >> 2;
    const int t    = lane & 3;
    const int q0   = blockIdx.x * 128;
    const int h    = blockIdx.y;
    const int b    = blockIdx.z;

    const size_t hb = (size_t)(b * NHEADS + h) * SEQ;
    const int prow = wm * 16;

    const uint32_t aRow = (uint32_t)(prow + (lane & 15)) * RSTR + (lane >> 4) * 16;
    const uint32_t qA = smb + OQH + aRow;
    const uint32_t kLane = (uint32_t)((((lane >> 4) & 1) * 8) + (lane & 7)) * RSTR
                         + ((lane >> 3) & 1) * 16;
    const uint32_t vLane = (uint32_t)((((lane >> 3) & 1) * 8) + (lane & 7)) * RSTR
                         + ((lane >> 4) & 1) * 16;

    const int cr = tid >> 3;
    const int ccol = (tid & 7) * 16;
    const int csrc = (tid & 7) * 8;

    #pragma unroll
    for (int it = 0; it < 4; it++) {
        int r = cr + it * 32;
        CP16(smb + OQH + r * RSTR + ccol, g_Qh + (hb + q0 + r) * HSIZE + csrc);
        CP16(smb + OQL + r * RSTR + ccol, g_Ql + (hb + q0 + r) * HSIZE + csrc);
    }
    {
        const uint32_t kvb = smb + OKV0;
        #pragma unroll
        for (int it = 0; it < 2; it++) {
            int r = cr + it * 32;
            size_t src = (hb + r) * HSIZE + csrc;
            uint32_t doff = r * RSTR + ccol;
            CP16(kvb + doff,          g_Kh + src);
            CP16(kvb + 9216 + doff,   g_Kl + src);
            CP16(kvb + 18432 + doff,  g_Vh + src);
            CP16(kvb + 27648 + doff,  g_Vl + src);
        }
    }
    CP_COMMIT();

    float oc[8][4];
    #pragma unroll
    for (int nt = 0; nt < 8; nt++)
        #pragma unroll
        for (int i = 0; i < 4; i++) oc[nt][i] = 0.f;
    float mstat[2] = { -1e30f, -1e30f };
    float lstat[2] = { 0.f, 0.f };

    const int NT = SEQ / 64;
    for (int tile = 0; tile < NT; tile++) {
        const int buf = tile & 1;
        if (tile + 1 < NT) {
            const uint32_t kvb = smb + OKV0 + (buf ^ 1) * KVBUF;
            const int kv1 = (tile + 1) * 64;
            #pragma unroll
            for (int it = 0; it < 2; it++) {
                int r = cr + it * 32;
                size_t src = (hb + kv1 + r) * HSIZE + csrc;
                uint32_t doff = r * RSTR + ccol;
                CP16(kvb + doff,          g_Kh + src);
                CP16(kvb + 9216 + doff,   g_Kl + src);
                CP16(kvb + 18432 + doff,  g_Vh + src);
                CP16(kvb + 27648 + doff,  g_Vl + src);
            }
            CP_COMMIT();
            CP_WAIT1();
        } else {
            CP_WAIT0();
        }
        __syncthreads();

        const uint32_t kvb = smb + OKV0 + buf * KVBUF;
        const uint32_t kA = kvb + kLane;
        const uint32_t vA = kvb + 18432 + vLane;

        float sc[8][4];
        #pragma unroll
        for (int nt = 0; nt < 8; nt++)
            #pragma unroll
            for (int i = 0; i < 4; i++) sc[nt][i] = 0.f;

        #pragma unroll
        for (int ks = 0; ks < 4; ks++) {
            uint32_t ah[4], al[4];
            LDMX4(ah, qA + ks * 32);
            LDMX4(al, qA + OQL + ks * 32);
            #pragma unroll
            for (int p = 0; p < 4; p++) {
                uint32_t bh[4], bl[4];
                LDMX4(bh, kA + p * 2304 + ks * 32);
                LDMX4(bl, kA + 9216 + p * 2304 + ks * 32);
                MMA_BF16(sc[2*p],   ah, bh);
                MMA_BF16(sc[2*p],   al, bh);
                MMA_BF16(sc[2*p],   ah, bl);
                MMA_BF16(sc[2*p+1], ah, bh + 2);
                MMA_BF16(sc[2*p+1], al, bh + 2);
                MMA_BF16(sc[2*p+1], ah, bl + 2);
            }
        }

        #pragma unroll
        for (int hf = 0; hf < 2; hf++) {
            const int i0 = hf * 2;
            float rm = -1e30f;
            #pragma unroll
            for (int nt = 0; nt < 8; nt++)
                rm = fmaxf(rm, fmaxf(sc[nt][i0], sc[nt][i0 + 1]));
            rm = fmaxf(rm, __shfl_xor_sync(0xffffffffu, rm, 1));
            rm = fmaxf(rm, __shfl_xor_sync(0xffffffffu, rm, 2));
            float nm   = fmaxf(mstat[hf], rm);
            float corr = __expf(mstat[hf] - nm);
            float rs = 0.f;
            #pragma unroll
            for (int nt = 0; nt < 8; nt++) {
                float p0 = __expf(sc[nt][i0]     - nm);
                float p1 = __expf(sc[nt][i0 + 1] - nm);
                sc[nt][i0] = p0; sc[nt][i0 + 1] = p1;
                rs += p0 + p1;
            }
            rs += __shfl_xor_sync(0xffffffffu, rs, 1);
            rs += __shfl_xor_sync(0xffffffffu, rs, 2);
            lstat[hf] = lstat[hf] * corr + rs;
            mstat[hf] = nm;
            #pragma unroll
            for (int nt = 0; nt < 8; nt++) {
                oc[nt][i0]     *= corr;
                oc[nt][i0 + 1] *= corr;
            }
        }

        #pragma unroll
        for (int ks = 0; ks < 4; ks++) {
            uint2 u0 = split2(sc[2*ks][0],   sc[2*ks][1]);
            uint2 u1 = split2(sc[2*ks][2],   sc[2*ks][3]);
            uint2 u2 = split2(sc[2*ks+1][0], sc[2*ks+1][1]);
            uint2 u3 = split2(sc[2*ks+1][2], sc[2*ks+1][3]);
            uint32_t ah[4] = { u0.x, u1.x, u2.x, u3.x };
            uint32_t al[4] = { u0.y, u1.y, u2.y, u3.y };
            #pragma unroll
            for (int p = 0; p < 4; p++) {
                uint32_t bh[4], bl[4];
                LDMX4T(bh, vA + ks * 2304 + p * 32);
                LDMX4T(bl, vA + 9216 + ks * 2304 + p * 32);
                MMA_BF16(oc[2*p],   ah, bh);
                MMA_BF16(oc[2*p],   al, bh);
                MMA_BF16(oc[2*p],   ah, bl);
                MMA_BF16(oc[2*p+1], ah, bh + 2);
                MMA_BF16(oc[2*p+1], al, bh + 2);
                MMA_BF16(oc[2*p+1], ah, bl + 2);
            }
        }
        __syncthreads();
    }

    const float inv0 = 1.0f / lstat[0];
    const float inv1 = 1.0f / lstat[1];
    const size_t r0 = (size_t)(b * SEQ + q0 + prow + g);
    const int col0 = h * HSIZE;
    #pragma unroll
    for (int nt = 0; nt < 8; nt++) {
        const int colw = col0 + nt * 8 + 2 * t;
        float2 o0 = { __uint_as_float(f2tf32(oc[nt][0] * inv0)),
                      __uint_as_float(f2tf32(oc[nt][1] * inv0)) };
        float2 o1 = { __uint_as_float(f2tf32(oc[nt][2] * inv1)),
                      __uint_as_float(f2tf32(oc[nt][3] * inv1)) };
        *(float2*)(attn_out + r0 * HIDDEN + colw)       = o0;
        *(float2*)(attn_out + (r0 + 8) * HIDDEN + colw) = o1;
    }
}

// ---------------------------------------------------------------------------
// Launch
// ---------------------------------------------------------------------------
extern "C" void kernel_launch(void* const* d_in, const int* in_sizes, int n_in,
                              void* d_out, int out_size)
{
    const float* x    = (const float*)d_in[0];
    const float* Wqkv = (const float*)d_in[1];
    const float* bqkv = (const float*)d_in[2];
    const float* Wo   = (const float*)d_in[3];
    const float* bo   = (const float*)d_in[4];
    float* out = (float*)d_out;

    float *qkv_p = nullptr, *attn_p = nullptr, *xr_p = nullptr,
          *wqkvT_p = nullptr, *woT_p = nullptr;
    cudaGetSymbolAddress((void**)&qkv_p,   g_qkv);
    cudaGetSymbolAddress((void**)&attn_p,  g_attn);
    cudaGetSymbolAddress((void**)&xr_p,    g_xr);
    cudaGetSymbolAddress((void**)&wqkvT_p, g_wqkvT);
    cudaGetSymbolAddress((void**)&woT_p,   g_woT);

    cudaFuncSetAttribute(attn_mma_kernel,
                         cudaFuncAttributeMaxDynamicSharedMemorySize, ATTN_SMEM);
    cudaFuncSetAttribute(gemm_tf32_mma,
                         cudaFuncAttributeMaxDynamicSharedMemorySize, GEMM_SMEM);

    // 0) Pre-round x; transpose+round weights
    round_kernel<<<(BS * HIDDEN / 4) / 256, 256>>>(x, xr_p);
    transpose_kernel<<<dim3(QKVW / 32, HIDDEN / 32), dim3(32, 8)>>>(
        Wqkv, wqkvT_p, HIDDEN, QKVW);
    transpose_kernel<<<dim3(HIDDEN / 32, HIDDEN / 32), dim3(32, 8)>>>(
        Wo, woT_p, HIDDEN, HIDDEN);

    // 1) QKV projection
    gemm_tf32_mma<<<dim3(QKVW / 128, BS / 128), 256, GEMM_SMEM>>>(
        xr_p, wqkvT_p, bqkv, qkv_p, QKVW);

    // 1.5) Split qkv into bf16 hi/lo per-head planes
    convert_kernel<<<(BS * QKVW / 4) / 256, 256>>>(qkv_p);

    // 2) Attention
    attn_mma_kernel<<<dim3(SEQ / 128, NHEADS, BATCH), 256, ATTN_SMEM>>>(attn_p);

    // 3) Output projection
    gemm_tf32_mma<<<dim3(HIDDEN / 128, BS / 128), 256, GEMM_SMEM>>>(
        attn_p, woT_p, bo, out, HIDDEN);
}

// round 14
// speedup vs baseline: 3.4930x; 1.0210x over previous
#include <cuda_runtime.h>
#include <cuda_bf16.h>
#include <cstdint>
#include <math.h>

// Problem constants
#define HIDDEN  1024
#define NHEADS  16
#define HSIZE   64
#define BATCH   2
#define SEQ     2048
#define BS      (BATCH * SEQ)      // 4096 rows
#define QKVW    (3 * HIDDEN)       // 3072
#define GK      1024               // GEMM K (both projections)

// Scratch (allocation-free rule: __device__ globals)
__device__ float g_attn [ (size_t)BS * HIDDEN ];     // [4096][1024] (tf32-rounded)
__device__ float g_xr   [ (size_t)BS * HIDDEN ];     // x, tf32-rounded
__device__ float g_wqkvT[ (size_t)QKVW * HIDDEN ];   // Wqkv^T (tf32-rounded)
__device__ float g_woT  [ (size_t)HIDDEN * HIDDEN ]; // Wo^T   (tf32-rounded)
// Pre-split bf16 planes, per-head layout: ((b*16+h)*SEQ+s)*64+d
__device__ __nv_bfloat16 g_Qh[(size_t)BS * HIDDEN];
__device__ __nv_bfloat16 g_Ql[(size_t)BS * HIDDEN];
__device__ __nv_bfloat16 g_Kh[(size_t)BS * HIDDEN];
__device__ __nv_bfloat16 g_Kl[(size_t)BS * HIDDEN];
__device__ __nv_bfloat16 g_Vh[(size_t)BS * HIDDEN];
__device__ __nv_bfloat16 g_Vl[(size_t)BS * HIDDEN];

__device__ __forceinline__ uint32_t f2tf32(float x) {
    uint32_t u;
    asm("cvt.rna.tf32.f32 %0, %1;" : "=r"(u) : "f"(x));
    return u;
}

#define MMA_TF32(c, a, b) \
    asm volatile("mma.sync.aligned.m16n8k8.row.col.f32.tf32.tf32.f32 " \
        "{%0,%1,%2,%3}, {%4,%5,%6,%7}, {%8,%9}, {%0,%1,%2,%3};" \
        : "+f"((c)[0]), "+f"((c)[1]), "+f"((c)[2]), "+f"((c)[3]) \
        : "r"((a)[0]), "r"((a)[1]), "r"((a)[2]), "r"((a)[3]), \
          "r"((b)[0]), "r"((b)[1]))

#define MMA_BF16(c, a, b) \
    asm volatile("mma.sync.aligned.m16n8k16.row.col.f32.bf16.bf16.f32 " \
        "{%0,%1,%2,%3}, {%4,%5,%6,%7}, {%8,%9}, {%0,%1,%2,%3};" \
        : "+f"((c)[0]), "+f"((c)[1]), "+f"((c)[2]), "+f"((c)[3]) \
        : "r"((a)[0]), "r"((a)[1]), "r"((a)[2]), "r"((a)[3]), \
          "r"((b)[0]), "r"((b)[1]))

#define LDMX4(r, a) \
    asm volatile("ldmatrix.sync.aligned.m8n8.x4.shared.b16 {%0,%1,%2,%3}, [%4];" \
        : "=r"((r)[0]), "=r"((r)[1]), "=r"((r)[2]), "=r"((r)[3]) : "r"(a))

#define LDMX4T(r, a) \
    asm volatile("ldmatrix.sync.aligned.m8n8.x4.trans.shared.b16 {%0,%1,%2,%3}, [%4];" \
        : "=r"((r)[0]), "=r"((r)[1]), "=r"((r)[2]), "=r"((r)[3]) : "r"(a))

#define CP16(dst, src) \
    asm volatile("cp.async.cg.shared.global [%0], [%1], 16;" \
        :: "r"(dst), "l"(src))
#define CP_COMMIT() asm volatile("cp.async.commit_group;")
#define CP_WAIT3()  asm volatile("cp.async.wait_group 3;")
#define CP_WAIT2()  asm volatile("cp.async.wait_group 2;")
#define CP_WAIT1()  asm volatile("cp.async.wait_group 1;")
#define CP_WAIT0()  asm volatile("cp.async.wait_group 0;")

// Split two floats into {hi bf16x2, lo bf16x2}
__device__ __forceinline__ uint2 split2(float x0, float x1) {
    __nv_bfloat162 h = __floats2bfloat162_rn(x0, x1);
    float h0 = __bfloat162float(h.x);
    float h1 = __bfloat162float(h.y);
    __nv_bfloat162 l = __floats2bfloat162_rn(x0 - h0, x1 - h1);
    uint2 r;
    r.x = *reinterpret_cast<uint32_t*>(&h);
    r.y = *reinterpret_cast<uint32_t*>(&l);
    return r;
}

// ---------------------------------------------------------------------------
// Round: out = tf32(in)
// ---------------------------------------------------------------------------
__global__ __launch_bounds__(256) void round_kernel(
    const float* __restrict__ in, float* __restrict__ out)
{
    int i = (blockIdx.x * 256 + threadIdx.x) * 4;
    float4 v = *(const float4*)(in + i);
    float4 o;
    o.x = __uint_as_float(f2tf32(v.x));
    o.y = __uint_as_float(f2tf32(v.y));
    o.z = __uint_as_float(f2tf32(v.z));
    o.w = __uint_as_float(f2tf32(v.w));
    *(float4*)(out + i) = o;
}

// ---------------------------------------------------------------------------
// Transpose + tf32 round: out[C][R] = tf32(in[R][C])
// ---------------------------------------------------------------------------
__global__ __launch_bounds__(256) void transpose_kernel(
    const float* __restrict__ in, float* __restrict__ out, int R, int C)
{
    __shared__ float t[32][33];
    int x  = blockIdx.x * 32 + threadIdx.x;
    int y0 = blockIdx.y * 32;
    #pragma unroll
    for (int i = threadIdx.y; i < 32; i += 8)
        t[i][threadIdx.x] = in[(size_t)(y0 + i) * C + x];
    __syncthreads();
    int ox  = y0 + threadIdx.x;
    int oy0 = blockIdx.x * 32;
    #pragma unroll
    for (int i = threadIdx.y; i < 32; i += 8)
        out[(size_t)(oy0 + i) * R + ox] =
            __uint_as_float(f2tf32(t[threadIdx.x][i]));
}

// ---------------------------------------------------------------------------
// tf32 GEMM v4: 5-stage cp.async pipeline. C = A * BT^T + bias.
// mode 0: write f32 C+bias.  mode 1: QKV epilogue — bias, Q-scale, bf16
// hi/lo split, write per-head planes directly (no separate convert pass).
// CTA 128x128, 8 warps (4m x 2n), warp tile 32x64. K-chunk 16.
// ---------------------------------------------------------------------------
#define GSTR 20
#define GROW 80
#define ABUF 10240                    // one stage of one operand: 128*80
#define OB   51200                    // B base (A[5] first)
#define GEMM_SMEM 102400

__global__ __launch_bounds__(256, 2) void gemm_tf32_mma(
    const float* __restrict__ A, const float* __restrict__ BT,
    const float* __restrict__ bias, float* __restrict__ C, int N, int mode)
{
    extern __shared__ float smem_f[];
    const uint32_t smb = (uint32_t)__cvta_generic_to_shared(smem_f);

    const int tid  = threadIdx.x;
    const int lane = tid & 31;
    const int w    = tid >> 5;
    const int wm   = w & 3;
    const int wn   = w >> 2;
    const int n0   = blockIdx.x * 128;
    const int m0   = blockIdx.y * 128;
    const int g    = lane >> 2;
    const int t    = lane & 3;

    float c[2][8][4];
    #pragma unroll
    for (int mt = 0; mt < 2; mt++)
        #pragma unroll
        for (int nt = 0; nt < 8; nt++)
            #pragma unroll
            for (int i = 0; i < 4; i++) c[mt][nt][i] = 0.f;

    const int cra = tid >> 2;
    const int cca = (tid & 3) * 16;

    const uint32_t aA = smb + (uint32_t)(wm * 32 + (lane & 15)) * GROW
                      + (lane >> 4) * 16;
    const uint32_t bB = smb + OB
                      + (uint32_t)(wn * 64 + ((lane >> 4) & 1) * 8 + (lane & 7)) * GROW
                      + ((lane >> 3) & 1) * 16;

    const int NCHUNK = GK / 16;   // 64

    // Prologue: issue chunks 0..3 into stages 0..3
    #pragma unroll
    for (int s = 0; s < 4; s++) {
        const uint32_t db = s * ABUF;
        const int k0 = s * 16;
        #pragma unroll
        for (int it = 0; it < 2; it++) {
            int r = cra + it * 64;
            CP16(smb + db + r * GROW + cca,
                 A  + (size_t)(m0 + r) * GK + k0 + (cca >> 2));
            CP16(smb + OB + db + r * GROW + cca,
                 BT + (size_t)(n0 + r) * GK + k0 + (cca >> 2));
        }
        CP_COMMIT();
    }

    int st = 0, ist = 4;   // compute stage, issue stage = (chunk+4)%5
    for (int chunk = 0; chunk < NCHUNK; chunk++) {
        const uint32_t ab = st * ABUF;

        // Wait until this chunk's stage has landed (tail-aware)
        if (chunk + 3 < NCHUNK)       { CP_WAIT3(); }
        else if (chunk + 3 == NCHUNK) { CP_WAIT2(); }
        else if (chunk + 2 == NCHUNK) { CP_WAIT1(); }
        else                          { CP_WAIT0(); }
        __syncthreads();   // retires reads of stage ist from chunk-1

        if (chunk + 4 < NCHUNK) {
            const int k0 = (chunk + 4) * 16;
            const uint32_t db = ist * ABUF;
            #pragma unroll
            for (int it = 0; it < 2; it++) {
                int r = cra + it * 64;
                CP16(smb + db + r * GROW + cca,
                     A  + (size_t)(m0 + r) * GK + k0 + (cca >> 2));
                CP16(smb + OB + db + r * GROW + cca,
                     BT + (size_t)(n0 + r) * GK + k0 + (cca >> 2));
            }
            CP_COMMIT();
        }

        #pragma unroll
        for (int ks = 0; ks < 2; ks++) {
            uint32_t af[2][4], bf[8][4];
            #pragma unroll
            for (int mt = 0; mt < 2; mt++)
                LDMX4(af[mt], aA + ab + mt * 16 * GROW + ks * 32);
            #pragma unroll
            for (int p = 0; p < 4; p++)
                LDMX4(bf[2 * p], bB + ab + p * 16 * GROW + ks * 32);
            #pragma unroll
            for (int mt = 0; mt < 2; mt++)
                #pragma unroll
                for (int p = 0; p < 4; p++) {
                    MMA_TF32(c[mt][2 * p],     af[mt], &bf[2 * p][0]);
                    MMA_TF32(c[mt][2 * p + 1], af[mt], &bf[2 * p][2]);
                }
        }
        st  = (st  == 4) ? 0 : st  + 1;
        ist = (ist == 4) ? 0 : ist + 1;
    }

    if (mode == 1) {
        // QKV epilogue: bias + Q-scale + bf16 hi/lo split -> head planes
        const int sec = n0 >> 10;          // 0=q, 1=k, 2=v (uniform per CTA)
        __nv_bfloat16* ph = (sec == 0) ? g_Qh : (sec == 1) ? g_Kh : g_Vh;
        __nv_bfloat16* pl = (sec == 0) ? g_Ql : (sec == 1) ? g_Kl : g_Vl;
        const float qs = (sec == 0) ? 0.125f : 1.0f;
        #pragma unroll
        for (int mt = 0; mt < 2; mt++) {
            const int row = m0 + wm * 32 + mt * 16 + g;
            const int bb = row >> 11, ss = row & 2047;
            #pragma unroll
            for (int nt = 0; nt < 8; nt++) {
                const int colg = n0 + wn * 64 + nt * 8 + 2 * t;
                float2 bv = *(const float2*)(bias + colg);
                const int gc = colg & 1023;
                const int hh = gc >> 6, d = gc & 63;
                const size_t dst0 =
                    ((size_t)(bb * NHEADS + hh) * SEQ + ss) * HSIZE + d;
                const size_t dst1 = dst0 + 8 * HSIZE;   // row + 8
                uint2 s0 = split2((c[mt][nt][0] + bv.x) * qs,
                                  (c[mt][nt][1] + bv.y) * qs);
                uint2 s1 = split2((c[mt][nt][2] + bv.x) * qs,
                                  (c[mt][nt][3] + bv.y) * qs);
                *(uint32_t*)(ph + dst0) = s0.x;
                *(uint32_t*)(pl + dst0) = s0.y;
                *(uint32_t*)(ph + dst1) = s1.x;
                *(uint32_t*)(pl + dst1) = s1.y;
            }
        }
    } else {
        #pragma unroll
        for (int mt = 0; mt < 2; mt++) {
            const int row = m0 + wm * 32 + mt * 16 + g;
            #pragma unroll
            for (int nt = 0; nt < 8; nt++) {
                const int col = n0 + wn * 64 + nt * 8 + t * 2;
                float2 bv = *(const float2*)(bias + col);
                float2 o0 = { c[mt][nt][0] + bv.x, c[mt][nt][1] + bv.y };
                float2 o1 = { c[mt][nt][2] + bv.x, c[mt][nt][3] + bv.y };
                *(float2*)(C + (size_t)row * N + col)       = o0;
                *(float2*)(C + (size_t)(row + 8) * N + col) = o1;
            }
        }
    }
}

// ---------------------------------------------------------------------------
// Flash attention — bf16x3 m16n8k16, pre-split GMEM planes, cp.async double
// buffering, register-direct P fragments. BQ=128, 8 warps. (unchanged)
// ---------------------------------------------------------------------------
#define RSTR 144
#define OQH 0
#define OQL 18432
#define OKV0 36864
#define KVBUF 36864
#define ATTN_SMEM 110592

__global__ __launch_bounds__(256, 2) void attn_mma_kernel(
    float* __restrict__ attn_out)
{
    extern __shared__ char sm[];
    const uint32_t smb = (uint32_t)__cvta_generic_to_shared(sm);

    const int tid  = threadIdx.x;
    const int lane = tid & 31;
    const int wm   = tid >> 5;
    const int g    = lane >> 2;
    const int t    = lane & 3;
    const int q0   = blockIdx.x * 128;
    const int h    = blockIdx.y;
    const int b    = blockIdx.z;

    const size_t hb = (size_t)(b * NHEADS + h) * SEQ;
    const int prow = wm * 16;

    const uint32_t aRow = (uint32_t)(prow + (lane & 15)) * RSTR + (lane >> 4) * 16;
    const uint32_t qA = smb + OQH + aRow;
    const uint32_t kLane = (uint32_t)((((lane >> 4) & 1) * 8) + (lane & 7)) * RSTR
                         + ((lane >> 3) & 1) * 16;
    const uint32_t vLane = (uint32_t)((((lane >> 3) & 1) * 8) + (lane & 7)) * RSTR
                         + ((lane >> 4) & 1) * 16;

    const int cr = tid >> 3;
    const int ccol = (tid & 7) * 16;
    const int csrc = (tid & 7) * 8;

    #pragma unroll
    for (int it = 0; it < 4; it++) {
        int r = cr + it * 32;
        CP16(smb + OQH + r * RSTR + ccol, g_Qh + (hb + q0 + r) * HSIZE + csrc);
        CP16(smb + OQL + r * RSTR + ccol, g_Ql + (hb + q0 + r) * HSIZE + csrc);
    }
    {
        const uint32_t kvb = smb + OKV0;
        #pragma unroll
        for (int it = 0; it < 2; it++) {
            int r = cr + it * 32;
            size_t src = (hb + r) * HSIZE + csrc;
            uint32_t doff = r * RSTR + ccol;
            CP16(kvb + doff,          g_Kh + src);
            CP16(kvb + 9216 + doff,   g_Kl + src);
            CP16(kvb + 18432 + doff,  g_Vh + src);
            CP16(kvb + 27648 + doff,  g_Vl + src);
        }
    }
    CP_COMMIT();

    float oc[8][4];
    #pragma unroll
    for (int nt = 0; nt < 8; nt++)
        #pragma unroll
        for (int i = 0; i < 4; i++) oc[nt][i] = 0.f;
    float mstat[2] = { -1e30f, -1e30f };
    float lstat[2] = { 0.f, 0.f };

    const int NT = SEQ / 64;
    for (int tile = 0; tile < NT; tile++) {
        const int buf = tile & 1;
        if (tile + 1 < NT) {
            const uint32_t kvb = smb + OKV0 + (buf ^ 1) * KVBUF;
            const int kv1 = (tile + 1) * 64;
            #pragma unroll
            for (int it = 0; it < 2; it++) {
                int r = cr + it * 32;
                size_t src = (hb + kv1 + r) * HSIZE + csrc;
                uint32_t doff = r * RSTR + ccol;
                CP16(kvb + doff,          g_Kh + src);
                CP16(kvb + 9216 + doff,   g_Kl + src);
                CP16(kvb + 18432 + doff,  g_Vh + src);
                CP16(kvb + 27648 + doff,  g_Vl + src);
            }
            CP_COMMIT();
            CP_WAIT1();
        } else {
            CP_WAIT0();
        }
        __syncthreads();

        const uint32_t kvb = smb + OKV0 + buf * KVBUF;
        const uint32_t kA = kvb + kLane;
        const uint32_t vA = kvb + 18432 + vLane;

        float sc[8][4];
        #pragma unroll
        for (int nt = 0; nt < 8; nt++)
            #pragma unroll
            for (int i = 0; i < 4; i++) sc[nt][i] = 0.f;

        #pragma unroll
        for (int ks = 0; ks < 4; ks++) {
            uint32_t ah[4], al[4];
            LDMX4(ah, qA + ks * 32);
            LDMX4(al, qA + OQL + ks * 32);
            #pragma unroll
            for (int p = 0; p < 4; p++) {
                uint32_t bh[4], bl[4];
                LDMX4(bh, kA + p * 2304 + ks * 32);
                LDMX4(bl, kA + 9216 + p * 2304 + ks * 32);
                MMA_BF16(sc[2*p],   ah, bh);
                MMA_BF16(sc[2*p],   al, bh);
                MMA_BF16(sc[2*p],   ah, bl);
                MMA_BF16(sc[2*p+1], ah, bh + 2);
                MMA_BF16(sc[2*p+1], al, bh + 2);
                MMA_BF16(sc[2*p+1], ah, bl + 2);
            }
        }

        #pragma unroll
        for (int hf = 0; hf < 2; hf++) {
            const int i0 = hf * 2;
            float rm = -1e30f;
            #pragma unroll
            for (int nt = 0; nt < 8; nt++)
                rm = fmaxf(rm, fmaxf(sc[nt][i0], sc[nt][i0 + 1]));
            rm = fmaxf(rm, __shfl_xor_sync(0xffffffffu, rm, 1));
            rm = fmaxf(rm, __shfl_xor_sync(0xffffffffu, rm, 2));
            float nm   = fmaxf(mstat[hf], rm);
            float corr = __expf(mstat[hf] - nm);
            float rs = 0.f;
            #pragma unroll
            for (int nt = 0; nt < 8; nt++) {
                float p0 = __expf(sc[nt][i0]     - nm);
                float p1 = __expf(sc[nt][i0 + 1] - nm);
                sc[nt][i0] = p0; sc[nt][i0 + 1] = p1;
                rs += p0 + p1;
            }
            rs += __shfl_xor_sync(0xffffffffu, rs, 1);
            rs += __shfl_xor_sync(0xffffffffu, rs, 2);
            lstat[hf] = lstat[hf] * corr + rs;
            mstat[hf] = nm;
            #pragma unroll
            for (int nt = 0; nt < 8; nt++) {
                oc[nt][i0]     *= corr;
                oc[nt][i0 + 1] *= corr;
            }
        }

        #pragma unroll
        for (int ks = 0; ks < 4; ks++) {
            uint2 u0 = split2(sc[2*ks][0],   sc[2*ks][1]);
            uint2 u1 = split2(sc[2*ks][2],   sc[2*ks][3]);
            uint2 u2 = split2(sc[2*ks+1][0], sc[2*ks+1][1]);
            uint2 u3 = split2(sc[2*ks+1][2], sc[2*ks+1][3]);
            uint32_t ah[4] = { u0.x, u1.x, u2.x, u3.x };
            uint32_t al[4] = { u0.y, u1.y, u2.y, u3.y };
            #pragma unroll
            for (int p = 0; p < 4; p++) {
                uint32_t bh[4], bl[4];
                LDMX4T(bh, vA + ks * 2304 + p * 32);
                LDMX4T(bl, vA + 9216 + ks * 2304 + p * 32);
                MMA_BF16(oc[2*p],   ah, bh);
                MMA_BF16(oc[2*p],   al, bh);
                MMA_BF16(oc[2*p],   ah, bl);
                MMA_BF16(oc[2*p+1], ah, bh + 2);
                MMA_BF16(oc[2*p+1], al, bh + 2);
                MMA_BF16(oc[2*p+1], ah, bl + 2);
            }
        }
        __syncthreads();
    }

    const float inv0 = 1.0f / lstat[0];
    const float inv1 = 1.0f / lstat[1];
    const size_t r0 = (size_t)(b * SEQ + q0 + prow + g);
    const int col0 = h * HSIZE;
    #pragma unroll
    for (int nt = 0; nt < 8; nt++) {
        const int colw = col0 + nt * 8 + 2 * t;
        float2 o0 = { __uint_as_float(f2tf32(oc[nt][0] * inv0)),
                      __uint_as_float(f2tf32(oc[nt][1] * inv0)) };
        float2 o1 = { __uint_as_float(f2tf32(oc[nt][2] * inv1)),
                      __uint_as_float(f2tf32(oc[nt][3] * inv1)) };
        *(float2*)(attn_out + r0 * HIDDEN + colw)       = o0;
        *(float2*)(attn_out + (r0 + 8) * HIDDEN + colw) = o1;
    }
}

// ---------------------------------------------------------------------------
// Launch
// ---------------------------------------------------------------------------
extern "C" void kernel_launch(void* const* d_in, const int* in_sizes, int n_in,
                              void* d_out, int out_size)
{
    const float* x    = (const float*)d_in[0];
    const float* Wqkv = (const float*)d_in[1];
    const float* bqkv = (const float*)d_in[2];
    const float* Wo   = (const float*)d_in[3];
    const float* bo   = (const float*)d_in[4];
    float* out = (float*)d_out;

    float *attn_p = nullptr, *xr_p = nullptr, *wqkvT_p = nullptr, *woT_p = nullptr;
    cudaGetSymbolAddress((void**)&attn_p,  g_attn);
    cudaGetSymbolAddress((void**)&xr_p,    g_xr);
    cudaGetSymbolAddress((void**)&wqkvT_p, g_wqkvT);
    cudaGetSymbolAddress((void**)&woT_p,   g_woT);

    cudaFuncSetAttribute(attn_mma_kernel,
                         cudaFuncAttributeMaxDynamicSharedMemorySize, ATTN_SMEM);
    cudaFuncSetAttribute(gemm_tf32_mma,
                         cudaFuncAttributeMaxDynamicSharedMemorySize, GEMM_SMEM);

    // 0) Pre-round x; transpose+round weights
    round_kernel<<<(BS * HIDDEN / 4) / 256, 256>>>(x, xr_p);
    transpose_kernel<<<dim3(QKVW / 32, HIDDEN / 32), dim3(32, 8)>>>(
        Wqkv, wqkvT_p, HIDDEN, QKVW);
    transpose_kernel<<<dim3(HIDDEN / 32, HIDDEN / 32), dim3(32, 8)>>>(
        Wo, woT_p, HIDDEN, HIDDEN);

    // 1) QKV projection, fused with bf16 hi/lo plane conversion (mode 1)
    gemm_tf32_mma<<<dim3(QKVW / 128, BS / 128), 256, GEMM_SMEM>>>(
        xr_p, wqkvT_p, bqkv, nullptr, QKVW, 1);

    // 2) Attention
    attn_mma_kernel<<<dim3(SEQ / 128, NHEADS, BATCH), 256, ATTN_SMEM>>>(attn_p);

    // 3) Output projection (mode 0)
    gemm_tf32_mma<<<dim3(HIDDEN / 128, BS / 128), 256, GEMM_SMEM>>>(
        attn_p, woT_p, bo, out, HIDDEN, 0);
}

// round 16
// speedup vs baseline: 3.7180x; 1.0644x over previous
#include <cuda_runtime.h>
#include <cuda_bf16.h>
#include <cstdint>
#include <math.h>

// Problem constants
#define HIDDEN  1024
#define NHEADS  16
#define HSIZE   64
#define BATCH   2
#define SEQ     2048
#define BS      (BATCH * SEQ)      // 4096 rows
#define QKVW    (3 * HIDDEN)       // 3072
#define GK      1024               // GEMM K (both projections)

// Scratch (allocation-free rule: __device__ globals)
__device__ float g_attn [ (size_t)BS * HIDDEN ];     // [4096][1024] (tf32-rounded)
__device__ float g_xr   [ (size_t)BS * HIDDEN ];     // x, tf32-rounded
__device__ float g_wqkvT[ (size_t)QKVW * HIDDEN ];   // Wqkv^T (tf32-rounded)
__device__ float g_woT  [ (size_t)HIDDEN * HIDDEN ]; // Wo^T   (tf32-rounded)
// Pre-split bf16 planes, per-head layout: ((b*16+h)*SEQ+s)*64+d
__device__ __nv_bfloat16 g_Qh[(size_t)BS * HIDDEN];
__device__ __nv_bfloat16 g_Ql[(size_t)BS * HIDDEN];
__device__ __nv_bfloat16 g_Kh[(size_t)BS * HIDDEN];
__device__ __nv_bfloat16 g_Kl[(size_t)BS * HIDDEN];
__device__ __nv_bfloat16 g_Vh[(size_t)BS * HIDDEN];
__device__ __nv_bfloat16 g_Vl[(size_t)BS * HIDDEN];

__device__ __forceinline__ uint32_t f2tf32(float x) {
    uint32_t u;
    asm("cvt.rna.tf32.f32 %0, %1;" : "=r"(u) : "f"(x));
    return u;
}

#define MMA_TF32(c, a, b) \
    asm volatile("mma.sync.aligned.m16n8k8.row.col.f32.tf32.tf32.f32 " \
        "{%0,%1,%2,%3}, {%4,%5,%6,%7}, {%8,%9}, {%0,%1,%2,%3};" \
        : "+f"((c)[0]), "+f"((c)[1]), "+f"((c)[2]), "+f"((c)[3]) \
        : "r"((a)[0]), "r"((a)[1]), "r"((a)[2]), "r"((a)[3]), \
          "r"((b)[0]), "r"((b)[1]))

#define MMA_BF16(c, a, b) \
    asm volatile("mma.sync.aligned.m16n8k16.row.col.f32.bf16.bf16.f32 " \
        "{%0,%1,%2,%3}, {%4,%5,%6,%7}, {%8,%9}, {%0,%1,%2,%3};" \
        : "+f"((c)[0]), "+f"((c)[1]), "+f"((c)[2]), "+f"((c)[3]) \
        : "r"((a)[0]), "r"((a)[1]), "r"((a)[2]), "r"((a)[3]), \
          "r"((b)[0]), "r"((b)[1]))

#define LDMX4(r, a) \
    asm volatile("ldmatrix.sync.aligned.m8n8.x4.shared.b16 {%0,%1,%2,%3}, [%4];" \
        : "=r"((r)[0]), "=r"((r)[1]), "=r"((r)[2]), "=r"((r)[3]) : "r"(a))

#define LDMX4T(r, a) \
    asm volatile("ldmatrix.sync.aligned.m8n8.x4.trans.shared.b16 {%0,%1,%2,%3}, [%4];" \
        : "=r"((r)[0]), "=r"((r)[1]), "=r"((r)[2]), "=r"((r)[3]) : "r"(a))

#define CP16(dst, src) \
    asm volatile("cp.async.cg.shared.global [%0], [%1], 16;" \
        :: "r"(dst), "l"(src))
#define CP_COMMIT() asm volatile("cp.async.commit_group;")
#define CP_WAIT1()  asm volatile("cp.async.wait_group 1;")
#define CP_WAIT0()  asm volatile("cp.async.wait_group 0;")

// Split two floats into {hi bf16x2, lo bf16x2}
__device__ __forceinline__ uint2 split2(float x0, float x1) {
    __nv_bfloat162 h = __floats2bfloat162_rn(x0, x1);
    float h0 = __bfloat162float(h.x);
    float h1 = __bfloat162float(h.y);
    __nv_bfloat162 l = __floats2bfloat162_rn(x0 - h0, x1 - h1);
    uint2 r;
    r.x = *reinterpret_cast<uint32_t*>(&h);
    r.y = *reinterpret_cast<uint32_t*>(&l);
    return r;
}

// ---------------------------------------------------------------------------
// Round: out = tf32(in)
// ---------------------------------------------------------------------------
__global__ __launch_bounds__(256) void round_kernel(
    const float* __restrict__ in, float* __restrict__ out)
{
    int i = (blockIdx.x * 256 + threadIdx.x) * 4;
    float4 v = *(const float4*)(in + i);
    float4 o;
    o.x = __uint_as_float(f2tf32(v.x));
    o.y = __uint_as_float(f2tf32(v.y));
    o.z = __uint_as_float(f2tf32(v.z));
    o.w = __uint_as_float(f2tf32(v.w));
    *(float4*)(out + i) = o;
}

// ---------------------------------------------------------------------------
// Transpose + tf32 round: out[C][R] = tf32(in[R][C])
// ---------------------------------------------------------------------------
__global__ __launch_bounds__(256) void transpose_kernel(
    const float* __restrict__ in, float* __restrict__ out, int R, int C)
{
    __shared__ float t[32][33];
    int x  = blockIdx.x * 32 + threadIdx.x;
    int y0 = blockIdx.y * 32;
    #pragma unroll
    for (int i = threadIdx.y; i < 32; i += 8)
        t[i][threadIdx.x] = in[(size_t)(y0 + i) * C + x];
    __syncthreads();
    int ox  = y0 + threadIdx.x;
    int oy0 = blockIdx.x * 32;
    #pragma unroll
    for (int i = threadIdx.y; i < 32; i += 8)
        out[(size_t)(oy0 + i) * R + ox] =
            __uint_as_float(f2tf32(t[threadIdx.x][i]));
}

// ---------------------------------------------------------------------------
// tf32 GEMM v5: K-chunk 32, 3-stage cp.async pipeline (fewer barriers, more
// HMMA per sync). C = A * BT^T + bias.
// mode 0: f32 C+bias. mode 1: QKV epilogue -> bf16 hi/lo head planes
// (Q additionally pre-scaled by 0.125*log2e for exp2-softmax).
// CTA 128x128, 8 warps (4m x 2n), warp tile 32x64.
// SMEM rows: 36 floats (144 B) -> ldmatrix banks conflict-free.
// ---------------------------------------------------------------------------
#define GROW 144
#define ABUF 18432                    // one stage of one operand: 128*144
#define OB   55296                    // B base (A[3] first)
#define GEMM_SMEM 110592

__global__ __launch_bounds__(256, 2) void gemm_tf32_mma(
    const float* __restrict__ A, const float* __restrict__ BT,
    const float* __restrict__ bias, float* __restrict__ C, int N, int mode)
{
    extern __shared__ float smem_f[];
    const uint32_t smb = (uint32_t)__cvta_generic_to_shared(smem_f);

    const int tid  = threadIdx.x;
    const int lane = tid & 31;
    const int w    = tid >> 5;
    const int wm   = w & 3;
    const int wn   = w >> 2;
    const int n0   = blockIdx.x * 128;
    const int m0   = blockIdx.y * 128;
    const int g    = lane >> 2;
    const int t    = lane & 3;

    float c[2][8][4];
    #pragma unroll
    for (int mt = 0; mt < 2; mt++)
        #pragma unroll
        for (int nt = 0; nt < 8; nt++)
            #pragma unroll
            for (int i = 0; i < 4; i++) c[mt][nt][i] = 0.f;

    // cp.async coords: per operand per chunk: 128 rows x 128B = 1024 x 16B,
    // 4 per thread: r = tid>>3 + it*32, col = (tid&7)*16
    const int cra = tid >> 3;          // base row
    const int cca = (tid & 7) * 16;    // byte col within 128B of K-data

    const uint32_t aA = smb + (uint32_t)(wm * 32 + (lane & 15)) * GROW
                      + (lane >> 4) * 16;
    const uint32_t bB = smb + OB
                      + (uint32_t)(wn * 64 + ((lane >> 4) & 1) * 8 + (lane & 7)) * GROW
                      + ((lane >> 3) & 1) * 16;

    const int NCHUNK = GK / 32;   // 32

    // Prologue: issue chunks 0,1 into stages 0,1
    #pragma unroll
    for (int s = 0; s < 2; s++) {
        const uint32_t db = s * ABUF;
        const int k0 = s * 32;
        #pragma unroll
        for (int it = 0; it < 4; it++) {
            int r = cra + it * 32;
            CP16(smb + db + r * GROW + cca,
                 A  + (size_t)(m0 + r) * GK + k0 + (cca >> 2));
            CP16(smb + OB + db + r * GROW + cca,
                 BT + (size_t)(n0 + r) * GK + k0 + (cca >> 2));
        }
        CP_COMMIT();
    }

    int st = 0, ist = 2;   // compute stage, issue stage = (chunk+2)%3
    for (int chunk = 0; chunk < NCHUNK; chunk++) {
        const uint32_t ab = st * ABUF;

        if (chunk + 1 < NCHUNK) { CP_WAIT1(); }
        else                    { CP_WAIT0(); }
        __syncthreads();   // retires reads of stage ist from chunk-1

        if (chunk + 2 < NCHUNK) {
            const int k0 = (chunk + 2) * 32;
            const uint32_t db = ist * ABUF;
            #pragma unroll
            for (int it = 0; it < 4; it++) {
                int r = cra + it * 32;
                CP16(smb + db + r * GROW + cca,
                     A  + (size_t)(m0 + r) * GK + k0 + (cca >> 2));
                CP16(smb + OB + db + r * GROW + cca,
                     BT + (size_t)(n0 + r) * GK + k0 + (cca >> 2));
            }
            CP_COMMIT();
        }

        #pragma unroll
        for (int ks = 0; ks < 4; ks++) {          // 4 x k8 per 32-chunk
            uint32_t af[2][4], bf[8][4];
            #pragma unroll
            for (int mt = 0; mt < 2; mt++)
                LDMX4(af[mt], aA + ab + mt * 16 * GROW + ks * 32);
            #pragma unroll
            for (int p = 0; p < 4; p++)
                LDMX4(bf[2 * p], bB + ab + p * 16 * GROW + ks * 32);
            #pragma unroll
            for (int mt = 0; mt < 2; mt++)
                #pragma unroll
                for (int p = 0; p < 4; p++) {
                    MMA_TF32(c[mt][2 * p],     af[mt], &bf[2 * p][0]);
                    MMA_TF32(c[mt][2 * p + 1], af[mt], &bf[2 * p][2]);
                }
        }
        st  = (st  == 2) ? 0 : st  + 1;
        ist = (ist == 2) ? 0 : ist + 1;
    }

    if (mode == 1) {
        // QKV epilogue: bias + Q-scale(0.125*log2e) + bf16 hi/lo split
        const int sec = n0 >> 10;          // 0=q, 1=k, 2=v (uniform per CTA)
        __nv_bfloat16* ph = (sec == 0) ? g_Qh : (sec == 1) ? g_Kh : g_Vh;
        __nv_bfloat16* pl = (sec == 0) ? g_Ql : (sec == 1) ? g_Kl : g_Vl;
        const float qs = (sec == 0) ? 0.125f * 1.4426950408889634f : 1.0f;
        #pragma unroll
        for (int mt = 0; mt < 2; mt++) {
            const int row = m0 + wm * 32 + mt * 16 + g;
            const int bb = row >> 11, ss = row & 2047;
            #pragma unroll
            for (int nt = 0; nt < 8; nt++) {
                const int colg = n0 + wn * 64 + nt * 8 + 2 * t;
                float2 bv = *(const float2*)(bias + colg);
                const int gc = colg & 1023;
                const int hh = gc >> 6, d = gc & 63;
                const size_t dst0 =
                    ((size_t)(bb * NHEADS + hh) * SEQ + ss) * HSIZE + d;
                const size_t dst1 = dst0 + 8 * HSIZE;   // row + 8
                uint2 s0 = split2((c[mt][nt][0] + bv.x) * qs,
                                  (c[mt][nt][1] + bv.y) * qs);
                uint2 s1 = split2((c[mt][nt][2] + bv.x) * qs,
                                  (c[mt][nt][3] + bv.y) * qs);
                *(uint32_t*)(ph + dst0) = s0.x;
                *(uint32_t*)(pl + dst0) = s0.y;
                *(uint32_t*)(ph + dst1) = s1.x;
                *(uint32_t*)(pl + dst1) = s1.y;
            }
        }
    } else {
        #pragma unroll
        for (int mt = 0; mt < 2; mt++) {
            const int row = m0 + wm * 32 + mt * 16 + g;
            #pragma unroll
            for (int nt = 0; nt < 8; nt++) {
                const int col = n0 + wn * 64 + nt * 8 + t * 2;
                float2 bv = *(const float2*)(bias + col);
                float2 o0 = { c[mt][nt][0] + bv.x, c[mt][nt][1] + bv.y };
                float2 o1 = { c[mt][nt][2] + bv.x, c[mt][nt][3] + bv.y };
                *(float2*)(C + (size_t)row * N + col)       = o0;
                *(float2*)(C + (size_t)(row + 8) * N + col) = o1;
            }
        }
    }
}

// ---------------------------------------------------------------------------
// Flash attention — bf16x3 m16n8k16, pre-split GMEM planes (Q in log2-scaled
// units), cp.async double buffering, register-direct P fragments, exp2
// softmax. BQ=128, 8 warps.
// ---------------------------------------------------------------------------
#define RSTR 144
#define OQH 0
#define OQL 18432
#define OKV0 36864
#define KVBUF 36864
#define ATTN_SMEM 110592

__global__ __launch_bounds__(256, 2) void attn_mma_kernel(
    float* __restrict__ attn_out)
{
    extern __shared__ char sm[];
    const uint32_t smb = (uint32_t)__cvta_generic_to_shared(sm);

    const int tid  = threadIdx.x;
    const int lane = tid & 31;
    const int wm   = tid >> 5;
    const int g    = lane >> 2;
    const int t    = lane & 3;
    const int q0   = blockIdx.x * 128;
    const int h    = blockIdx.y;
    const int b    = blockIdx.z;

    const size_t hb = (size_t)(b * NHEADS + h) * SEQ;
    const int prow = wm * 16;

    const uint32_t aRow = (uint32_t)(prow + (lane & 15)) * RSTR + (lane >> 4) * 16;
    const uint32_t qA = smb + OQH + aRow;
    const uint32_t kLane = (uint32_t)((((lane >> 4) & 1) * 8) + (lane & 7)) * RSTR
                         + ((lane >> 3) & 1) * 16;
    const uint32_t vLane = (uint32_t)((((lane >> 3) & 1) * 8) + (lane & 7)) * RSTR
                         + ((lane >> 4) & 1) * 16;

    const int cr = tid >> 3;
    const int ccol = (tid & 7) * 16;
    const int csrc = (tid & 7) * 8;

    #pragma unroll
    for (int it = 0; it < 4; it++) {
        int r = cr + it * 32;
        CP16(smb + OQH + r * RSTR + ccol, g_Qh + (hb + q0 + r) * HSIZE + csrc);
        CP16(smb + OQL + r * RSTR + ccol, g_Ql + (hb + q0 + r) * HSIZE + csrc);
    }
    {
        const uint32_t kvb = smb + OKV0;
        #pragma unroll
        for (int it = 0; it < 2; it++) {
            int r = cr + it * 32;
            size_t src = (hb + r) * HSIZE + csrc;
            uint32_t doff = r * RSTR + ccol;
            CP16(kvb + doff,          g_Kh + src);
            CP16(kvb + 9216 + doff,   g_Kl + src);
            CP16(kvb + 18432 + doff,  g_Vh + src);
            CP16(kvb + 27648 + doff,  g_Vl + src);
        }
    }
    CP_COMMIT();

    float oc[8][4];
    #pragma unroll
    for (int nt = 0; nt < 8; nt++)
        #pragma unroll
        for (int i = 0; i < 4; i++) oc[nt][i] = 0.f;
    float mstat[2] = { -1e30f, -1e30f };
    float lstat[2] = { 0.f, 0.f };

    const int NT = SEQ / 64;
    for (int tile = 0; tile < NT; tile++) {
        const int buf = tile & 1;
        if (tile + 1 < NT) {
            const uint32_t kvb = smb + OKV0 + (buf ^ 1) * KVBUF;
            const int kv1 = (tile + 1) * 64;
            #pragma unroll
            for (int it = 0; it < 2; it++) {
                int r = cr + it * 32;
                size_t src = (hb + kv1 + r) * HSIZE + csrc;
                uint32_t doff = r * RSTR + ccol;
                CP16(kvb + doff,          g_Kh + src);
                CP16(kvb + 9216 + doff,   g_Kl + src);
                CP16(kvb + 18432 + doff,  g_Vh + src);
                CP16(kvb + 27648 + doff,  g_Vl + src);
            }
            CP_COMMIT();
            CP_WAIT1();
        } else {
            CP_WAIT0();
        }
        __syncthreads();

        const uint32_t kvb = smb + OKV0 + buf * KVBUF;
        const uint32_t kA = kvb + kLane;
        const uint32_t vA = kvb + 18432 + vLane;

        float sc[8][4];
        #pragma unroll
        for (int nt = 0; nt < 8; nt++)
            #pragma unroll
            for (int i = 0; i < 4; i++) sc[nt][i] = 0.f;

        #pragma unroll
        for (int ks = 0; ks < 4; ks++) {
            uint32_t ah[4], al[4];
            LDMX4(ah, qA + ks * 32);
            LDMX4(al, qA + OQL + ks * 32);
            #pragma unroll
            for (int p = 0; p < 4; p++) {
                uint32_t bh[4], bl[4];
                LDMX4(bh, kA + p * 2304 + ks * 32);
                LDMX4(bl, kA + 9216 + p * 2304 + ks * 32);
                MMA_BF16(sc[2*p],   ah, bh);
                MMA_BF16(sc[2*p],   al, bh);
                MMA_BF16(sc[2*p],   ah, bl);
                MMA_BF16(sc[2*p+1], ah, bh + 2);
                MMA_BF16(sc[2*p+1], al, bh + 2);
                MMA_BF16(sc[2*p+1], ah, bl + 2);
            }
        }

        // online softmax in log2 domain (Q pre-scaled by 0.125*log2e)
        #pragma unroll
        for (int hf = 0; hf < 2; hf++) {
            const int i0 = hf * 2;
            float rm = -1e30f;
            #pragma unroll
            for (int nt = 0; nt < 8; nt++)
                rm = fmaxf(rm, fmaxf(sc[nt][i0], sc[nt][i0 + 1]));
            rm = fmaxf(rm, __shfl_xor_sync(0xffffffffu, rm, 1));
            rm = fmaxf(rm, __shfl_xor_sync(0xffffffffu, rm, 2));
            float nm   = fmaxf(mstat[hf], rm);
            float corr = exp2f(mstat[hf] - nm);
            float rs = 0.f;
            #pragma unroll
            for (int nt = 0; nt < 8; nt++) {
                float p0 = exp2f(sc[nt][i0]     - nm);
                float p1 = exp2f(sc[nt][i0 + 1] - nm);
                sc[nt][i0] = p0; sc[nt][i0 + 1] = p1;
                rs += p0 + p1;
            }
            rs += __shfl_xor_sync(0xffffffffu, rs, 1);
            rs += __shfl_xor_sync(0xffffffffu, rs, 2);
            lstat[hf] = lstat[hf] * corr + rs;
            mstat[hf] = nm;
            #pragma unroll
            for (int nt = 0; nt < 8; nt++) {
                oc[nt][i0]     *= corr;
                oc[nt][i0 + 1] *= corr;
            }
        }

        #pragma unroll
        for (int ks = 0; ks < 4; ks++) {
            uint2 u0 = split2(sc[2*ks][0],   sc[2*ks][1]);
            uint2 u1 = split2(sc[2*ks][2],   sc[2*ks][3]);
            uint2 u2 = split2(sc[2*ks+1][0], sc[2*ks+1][1]);
            uint2 u3 = split2(sc[2*ks+1][2], sc[2*ks+1][3]);
            uint32_t ah[4] = { u0.x, u1.x, u2.x, u3.x };
            uint32_t al[4] = { u0.y, u1.y, u2.y, u3.y };
            #pragma unroll
            for (int p = 0; p < 4; p++) {
                uint32_t bh[4], bl[4];
                LDMX4T(bh, vA + ks * 2304 + p * 32);
                LDMX4T(bl, vA + 9216 + ks * 2304 + p * 32);
                MMA_BF16(oc[2*p],   ah, bh);
                MMA_BF16(oc[2*p],   al, bh);
                MMA_BF16(oc[2*p],   ah, bl);
                MMA_BF16(oc[2*p+1], ah, bh + 2);
                MMA_BF16(oc[2*p+1], al, bh + 2);
                MMA_BF16(oc[2*p+1], ah, bl + 2);
            }
        }
        __syncthreads();
    }

    const float inv0 = 1.0f / lstat[0];
    const float inv1 = 1.0f / lstat[1];
    const size_t r0 = (size_t)(b * SEQ + q0 + prow + g);
    const int col0 = h * HSIZE;
    #pragma unroll
    for (int nt = 0; nt < 8; nt++) {
        const int colw = col0 + nt * 8 + 2 * t;
        float2 o0 = { __uint_as_float(f2tf32(oc[nt][0] * inv0)),
                      __uint_as_float(f2tf32(oc[nt][1] * inv0)) };
        float2 o1 = { __uint_as_float(f2tf32(oc[nt][2] * inv1)),
                      __uint_as_float(f2tf32(oc[nt][3] * inv1)) };
        *(float2*)(attn_out + r0 * HIDDEN + colw)       = o0;
        *(float2*)(attn_out + (r0 + 8) * HIDDEN + colw) = o1;
    }
}

// ---------------------------------------------------------------------------
// Launch
// ---------------------------------------------------------------------------
extern "C" void kernel_launch(void* const* d_in, const int* in_sizes, int n_in,
                              void* d_out, int out_size)
{
    const float* x    = (const float*)d_in[0];
    const float* Wqkv = (const float*)d_in[1];
    const float* bqkv = (const float*)d_in[2];
    const float* Wo   = (const float*)d_in[3];
    const float* bo   = (const float*)d_in[4];
    float* out = (float*)d_out;

    float *attn_p = nullptr, *xr_p = nullptr, *wqkvT_p = nullptr, *woT_p = nullptr;
    cudaGetSymbolAddress((void**)&attn_p,  g_attn);
    cudaGetSymbolAddress((void**)&xr_p,    g_xr);
    cudaGetSymbolAddress((void**)&wqkvT_p, g_wqkvT);
    cudaGetSymbolAddress((void**)&woT_p,   g_woT);

    cudaFuncSetAttribute(attn_mma_kernel,
                         cudaFuncAttributeMaxDynamicSharedMemorySize, ATTN_SMEM);
    cudaFuncSetAttribute(gemm_tf32_mma,
                         cudaFuncAttributeMaxDynamicSharedMemorySize, GEMM_SMEM);

    // 0) Pre-round x; transpose+round weights
    round_kernel<<<(BS * HIDDEN / 4) / 256, 256>>>(x, xr_p);
    transpose_kernel<<<dim3(QKVW / 32, HIDDEN / 32), dim3(32, 8)>>>(
        Wqkv, wqkvT_p, HIDDEN, QKVW);
    transpose_kernel<<<dim3(HIDDEN / 32, HIDDEN / 32), dim3(32, 8)>>>(
        Wo, woT_p, HIDDEN, HIDDEN);

    // 1) QKV projection, fused with bf16 hi/lo plane conversion (mode 1)
    gemm_tf32_mma<<<dim3(QKVW / 128, BS / 128), 256, GEMM_SMEM>>>(
        xr_p, wqkvT_p, bqkv, nullptr, QKVW, 1);

    // 2) Attention
    attn_mma_kernel<<<dim3(SEQ / 128, NHEADS, BATCH), 256, ATTN_SMEM>>>(attn_p);

    // 3) Output projection (mode 0)
    gemm_tf32_mma<<<dim3(HIDDEN / 128, BS / 128), 256, GEMM_SMEM>>>(
        attn_p, woT_p, bo, out, HIDDEN, 0);
}